// round 1
// baseline (speedup 1.0000x reference)
#include <cuda_runtime.h>
#include <math.h>

#define NN 3000
#define NFEATD 512
#define AA 2
#define HHD 4
#define O1D 64
#define O2D 32
#define HO1D 256
#define HO2D 128
#define FUSD 64
#define NCLSD 8
#define WPR 94            // ceil(3000/32) words per adjacency row
#define NTILES 94         // ceil(3000/32) m-tiles
#define ALPHAF 0.2f

// ---------------- scratch (static device allocations) ----------------
__device__ float g_Wh1[AA*NN*HO1D];
__device__ float g_gat1[AA*NN*HO1D];
__device__ float g_Wh2[AA*NN*HO2D];
__device__ float g_gat2[AA*NN*HO2D];
__device__ float g_f1[AA*HHD*NN], g_f2[AA*HHD*NN];
__device__ float g_ea[AA*HHD*NN], g_eb[AA*HHD*NN];
__device__ float g_E1[AA*HHD*NN], g_E2[AA*HHD*NN];
__device__ unsigned g_bits[AA*WPR*NN];   // layout [a][mt][n] for coalesced reads
__device__ float g_h1p[NN*AA*FUSD];
__device__ float g_out1[NN*FUSD];
__device__ float g_h2p[NN*AA*NCLSD];
__device__ float g_logits[NN*NCLSD];
__device__ float g_wint1T[HO1D*FUSD];
__device__ float g_wfus1T[AA*FUSD*FUSD];
__device__ float g_wint2T[HO2D*NCLSD];
__device__ float g_wfus2T[AA*NCLSD*NCLSD];

// ---------------- generic small transpose ----------------
__global__ void transpose_kernel(const float* __restrict__ src, float* __restrict__ dst,
                                 int R, int C) {
    int t = blockIdx.x * blockDim.x + threadIdx.x;
    if (t < R * C) {
        int r = t / C, c = t % C;
        dst[c * R + r] = src[t];
    }
}

// ---------------- adjacency -> bitmask (transposed layout) ----------------
__global__ void bitmask_kernel(const int* __restrict__ adj) {
    int gw = (blockIdx.x * blockDim.x + threadIdx.x) >> 5;
    int lane = threadIdx.x & 31;
    if (gw >= AA * WPR * 94) return;
    int a = gw / (WPR * 94);
    int rem = gw % (WPR * 94);
    int mt = rem / 94;
    int ng = rem % 94;
    int n = ng * 32 + lane;
    if (n >= NN) return;
    const int* row = adj + (size_t)(a * NN + n) * NN + mt * 32;
    int mmax = NN - mt * 32; if (mmax > 32) mmax = 32;
    unsigned word = 0u;
    for (int j = 0; j < mmax; j++)
        if (row[j] > 0) word |= (1u << j);
    g_bits[(size_t)(a * WPR + mt) * NN + n] = word;
}

// ---------------- per-node attention factor precompute ----------------
__global__ void fprep_kernel(const float* __restrict__ Wh, const float* __restrict__ avec,
                             float* __restrict__ f1o, float* __restrict__ f2o,
                             float* __restrict__ eao, float* __restrict__ ebo,
                             float* __restrict__ E1o, float* __restrict__ E2o,
                             int O, int HO) {
    int t = blockIdx.x * blockDim.x + threadIdx.x;
    if (t >= AA * HHD * NN) return;
    int ah = t / NN, n = t % NN;
    int a = ah / HHD, h = ah % HHD;
    const float* wr = Wh + (size_t)(a * NN + n) * HO + h * O;
    const float* av = avec + ah * 2 * O;
    float f1 = 0.f, f2 = 0.f;
    for (int o = 0; o < O; o++) {
        float w = wr[o];
        f1 += w * av[o];
        f2 += w * av[O + o];
    }
    f1o[t] = f1; f2o[t] = f2;
    eao[t] = expf(f1);          ebo[t] = expf(ALPHAF * f1);
    E1o[t] = expf(f2);          E2o[t] = expf(ALPHAF * f2);
}

// ---------------- generic tiled SGEMM with batch-z, bias, elu ----------------
// C[m,c] = sum_k A[m,k]*B[k,c] (+bias[c]) (elu if act==1)
__global__ void sgemm_kernel(const float* __restrict__ A, const float* __restrict__ B,
                             float* __restrict__ C, const float* __restrict__ bias,
                             int M, int K, int Nc, int lda, int ldb, int ldc,
                             int Hz, long long sAa, long long sAh,
                             long long sBa, long long sBh,
                             long long sCa, long long sCh, int act) {
    int z = blockIdx.z;
    int za = z / Hz, zh = z % Hz;
    A += za * sAa + zh * sAh;
    B += za * sBa + zh * sBh;
    C += za * sCa + zh * sCh;
    __shared__ float As[16][65];
    __shared__ __align__(16) float Bs[16][64];
    int tid = threadIdx.x;
    int tx = tid & 15, ty = tid >> 4;
    int m0 = blockIdx.x * 64, n0 = blockIdx.y * 64;
    float acc[4][4] = {};
    for (int k0 = 0; k0 < K; k0 += 16) {
        __syncthreads();
#pragma unroll
        for (int i = 0; i < 4; i++) {
            int e = tid + i * 256;
            int k = e & 15, m = e >> 4;
            As[k][m] = (m0 + m < M) ? A[(size_t)(m0 + m) * lda + k0 + k] : 0.f;
        }
#pragma unroll
        for (int i = 0; i < 4; i++) {
            int e = tid + i * 256;
            int n = e & 63, k = e >> 6;
            Bs[k][n] = (n0 + n < Nc) ? B[(size_t)(k0 + k) * ldb + n0 + n] : 0.f;
        }
        __syncthreads();
#pragma unroll
        for (int k = 0; k < 16; k++) {
            float4 bv = *reinterpret_cast<const float4*>(&Bs[k][tx * 4]);
            float b4[4] = {bv.x, bv.y, bv.z, bv.w};
#pragma unroll
            for (int i = 0; i < 4; i++) {
                float av = As[k][ty * 4 + i];
#pragma unroll
                for (int j = 0; j < 4; j++) acc[i][j] += av * b4[j];
            }
        }
    }
#pragma unroll
    for (int i = 0; i < 4; i++) {
        int r = m0 + ty * 4 + i;
        if (r >= M) continue;
#pragma unroll
        for (int j = 0; j < 4; j++) {
            int c = n0 + tx * 4 + j;
            if (c >= Nc) continue;
            float v = acc[i][j];
            if (bias) v += bias[c];
            if (act == 1) v = v > 0.f ? v : (expf(v) - 1.f);
            C[(size_t)r * ldc + c] = v;
        }
    }
}

// ---------------- fused masked-softmax attention aggregate ----------------
// For one (a,h): out[n,:] = elu( (sum_m w(n,m)*Wh[m,:]) / (sum_m w(n,m)) )
// w(n,m) = adjbit(n,m) * ( f1[n]+f2[m] > 0 ? ea[n]*E1[m] : eb[n]*E2[m] )
template <int O>
__global__ void att_kernel(const float* __restrict__ Wh,
                           const float* __restrict__ f1v, const float* __restrict__ f2v,
                           const float* __restrict__ eav, const float* __restrict__ ebv,
                           const float* __restrict__ E1v, const float* __restrict__ E2v,
                           const unsigned* __restrict__ bits, float* __restrict__ outp) {
    constexpr int HO = HHD * O;
    constexpr int VO = O / 16;
    int z = blockIdx.y;
    int a = z >> 2, h = z & 3;
    int n0 = blockIdx.x * 64;
    const float* whb = Wh + (size_t)a * NN * HO + h * O;
    const float* f1b = f1v + (size_t)z * NN;
    const float* f2b = f2v + (size_t)z * NN;
    const float* eab = eav + (size_t)z * NN;
    const float* ebb = ebv + (size_t)z * NN;
    const float* E1b = E1v + (size_t)z * NN;
    const float* E2b = E2v + (size_t)z * NN;
    const unsigned* bb = bits + (size_t)a * WPR * NN;

    int tid = threadIdx.x;
    int nr = tid >> 2, q = tid & 3;
    int grow = n0 + nr;
    float f1n = 0.f, ean = 0.f, ebn = 0.f;
    if (grow < NN) { f1n = f1b[grow]; ean = eab[grow]; ebn = ebb[grow]; }

    __shared__ __align__(16) float Whs[32][O];
    __shared__ float ws[64][33];
    __shared__ float Zp[256];
    __shared__ float Zr[64];

    int ty = tid >> 4, tx = tid & 15;
    float acc[4][VO];
#pragma unroll
    for (int i = 0; i < 4; i++)
#pragma unroll
        for (int j = 0; j < VO; j++) acc[i][j] = 0.f;
    float zacc = 0.f;

    for (int mt = 0; mt < NTILES; mt++) {
        __syncthreads();
#pragma unroll
        for (int i = 0; i < (32 * O) / 256; i++) {
            int e = tid + i * 256;
            int lm = e / O, o = e % O;
            int m = mt * 32 + lm;
            Whs[lm][o] = (m < NN) ? whb[(size_t)m * HO + o] : 0.f;
        }
        unsigned word = (grow < NN) ? bb[(size_t)mt * NN + grow] : 0u;
#pragma unroll
        for (int j = 0; j < 8; j++) {
            int ml = q * 8 + j;
            float wv = 0.f;
            if ((word >> ml) & 1u) {
                int m = mt * 32 + ml;
                float s = f1n + f2b[m];
                wv = (s > 0.f) ? ean * E1b[m] : ebn * E2b[m];
            }
            ws[nr][ml] = wv;
            zacc += wv;
        }
        __syncthreads();
#pragma unroll
        for (int k = 0; k < 32; k++) {
            float b4[VO];
            if constexpr (VO == 4) {
                float4 bv = *reinterpret_cast<const float4*>(&Whs[k][tx * 4]);
                b4[0] = bv.x; b4[1] = bv.y; b4[2] = bv.z; b4[3] = bv.w;
            } else {
                float2 bv = *reinterpret_cast<const float2*>(&Whs[k][tx * 2]);
                b4[0] = bv.x; b4[1] = bv.y;
            }
#pragma unroll
            for (int i = 0; i < 4; i++) {
                float av = ws[ty * 4 + i][k];
#pragma unroll
                for (int j = 0; j < VO; j++) acc[i][j] += av * b4[j];
            }
        }
    }

    Zp[tid] = zacc;
    __syncthreads();
    if (tid < 64) {
        float s = Zp[tid * 4] + Zp[tid * 4 + 1] + Zp[tid * 4 + 2] + Zp[tid * 4 + 3];
        Zr[tid] = (s > 0.f) ? 1.f / s : 0.f;
    }
    __syncthreads();
#pragma unroll
    for (int i = 0; i < 4; i++) {
        int r = ty * 4 + i;
        int gr = n0 + r;
        if (gr >= NN) continue;
        float inv = Zr[r];
#pragma unroll
        for (int j = 0; j < VO; j++) {
            float v = acc[i][j] * inv;
            v = v > 0.f ? v : (expf(v) - 1.f);
            outp[(size_t)(a * NN + gr) * HO + h * O + tx * VO + j] = v;
        }
    }
}

// ---------------- log_softmax + L1 scalar ----------------
__global__ void lsm_kernel(float* __restrict__ out, int out_size) {
    int n = blockIdx.x * blockDim.x + threadIdx.x;
    if (n >= NN) return;
    float v[NCLSD];
    float mx = -1e30f;
#pragma unroll
    for (int c = 0; c < NCLSD; c++) { v[c] = g_logits[n * NCLSD + c]; mx = fmaxf(mx, v[c]); }
    float s = 0.f;
#pragma unroll
    for (int c = 0; c < NCLSD; c++) s += expf(v[c] - mx);
    float l = logf(s) + mx;
#pragma unroll
    for (int c = 0; c < NCLSD; c++) {
        int idx = n * NCLSD + c;
        if (idx < out_size) out[idx] = v[c] - l;
    }
}

__global__ void l1_kernel(const float* __restrict__ wfus1, const float* __restrict__ wfus2,
                          float* __restrict__ out, int out_size) {
    __shared__ float red[256];
    int tid = threadIdx.x;
    float s1 = 0.f, s2 = 0.f;
    for (int i = tid; i < FUSD * AA * FUSD; i += 256) s1 += fabsf(wfus1[i]);
    for (int i = tid; i < NCLSD * AA * NCLSD; i += 256) s2 += fabsf(wfus2[i]);
    red[tid] = s1 / (float)(FUSD * AA * FUSD) + s2 / (float)(NCLSD * AA * NCLSD);
    __syncthreads();
    for (int o = 128; o > 0; o >>= 1) {
        if (tid < o) red[tid] += red[tid + o];
        __syncthreads();
    }
    if (tid == 0 && out_size > NN * NCLSD) out[NN * NCLSD] = red[0];
}

// ---------------- host launcher ----------------
extern "C" void kernel_launch(void* const* d_in, const int* in_sizes, int n_in,
                              void* d_out, int out_size) {
    const float* x     = (const float*)d_in[0];
    const int*   adj   = (const int*)d_in[1];
    const float* W1    = (const float*)d_in[2];
    const float* a1    = (const float*)d_in[3];
    const float* W2    = (const float*)d_in[4];
    const float* a2    = (const float*)d_in[5];
    const float* wint1 = (const float*)d_in[6];
    const float* bint1 = (const float*)d_in[7];
    const float* wfus1 = (const float*)d_in[8];
    const float* bfus1 = (const float*)d_in[9];
    const float* wint2 = (const float*)d_in[10];
    const float* bint2 = (const float*)d_in[11];
    const float* wfus2 = (const float*)d_in[12];
    const float* bfus2 = (const float*)d_in[13];
    float* out = (float*)d_out;

    float *pWh1, *pgat1, *pWh2, *pgat2;
    float *pf1, *pf2, *pea, *peb, *pE1, *pE2;
    float *ph1p, *pout1, *ph2p, *plogits;
    float *pwint1T, *pwfus1T, *pwint2T, *pwfus2T;
    unsigned* pbits;
    cudaGetSymbolAddress((void**)&pWh1, g_Wh1);
    cudaGetSymbolAddress((void**)&pgat1, g_gat1);
    cudaGetSymbolAddress((void**)&pWh2, g_Wh2);
    cudaGetSymbolAddress((void**)&pgat2, g_gat2);
    cudaGetSymbolAddress((void**)&pf1, g_f1);
    cudaGetSymbolAddress((void**)&pf2, g_f2);
    cudaGetSymbolAddress((void**)&pea, g_ea);
    cudaGetSymbolAddress((void**)&peb, g_eb);
    cudaGetSymbolAddress((void**)&pE1, g_E1);
    cudaGetSymbolAddress((void**)&pE2, g_E2);
    cudaGetSymbolAddress((void**)&pbits, g_bits);
    cudaGetSymbolAddress((void**)&ph1p, g_h1p);
    cudaGetSymbolAddress((void**)&pout1, g_out1);
    cudaGetSymbolAddress((void**)&ph2p, g_h2p);
    cudaGetSymbolAddress((void**)&plogits, g_logits);
    cudaGetSymbolAddress((void**)&pwint1T, g_wint1T);
    cudaGetSymbolAddress((void**)&pwfus1T, g_wfus1T);
    cudaGetSymbolAddress((void**)&pwint2T, g_wint2T);
    cudaGetSymbolAddress((void**)&pwfus2T, g_wfus2T);

    // weight transposes (tiny)
    transpose_kernel<<<(FUSD * HO1D + 255) / 256, 256>>>(wint1, pwint1T, FUSD, HO1D);
    transpose_kernel<<<(FUSD * AA * FUSD + 255) / 256, 256>>>(wfus1, pwfus1T, FUSD, AA * FUSD);
    transpose_kernel<<<(NCLSD * HO2D + 255) / 256, 256>>>(wint2, pwint2T, NCLSD, HO2D);
    transpose_kernel<<<(NCLSD * AA * NCLSD + 255) / 256, 256>>>(wfus2, pwfus2T, NCLSD, AA * NCLSD);

    // adjacency bitmask
    {
        int warps = AA * WPR * 94;
        bitmask_kernel<<<(warps * 32 + 255) / 256, 256>>>(adj);
    }

    int nblk = (NN + 63) / 64;

    // stage 1: Wh1 = x @ W1  -> [A][N][H*64]
    sgemm_kernel<<<dim3(nblk, 1, AA * HHD), 256>>>(
        x, W1, pWh1, nullptr, NN, NFEATD, O1D, NFEATD, O1D, HO1D,
        HHD, 0, 0, (long long)HHD * NFEATD * O1D, (long long)NFEATD * O1D,
        (long long)NN * HO1D, O1D, 0);

    fprep_kernel<<<(AA * HHD * NN + 255) / 256, 256>>>(pWh1, a1, pf1, pf2, pea, peb, pE1, pE2, O1D, HO1D);

    att_kernel<O1D><<<dim3(nblk, AA * HHD), 256>>>(pWh1, pf1, pf2, pea, peb, pE1, pE2, pbits, pgat1);

    // interproj1: elu(gat1 @ wint1T + bint1) -> h1p[n][a*64+g]
    sgemm_kernel<<<dim3(nblk, 1, AA), 256>>>(
        pgat1, pwint1T, ph1p, bint1, NN, HO1D, FUSD, HO1D, FUSD, AA * FUSD,
        1, (long long)NN * HO1D, 0, 0, 0, FUSD, 0, 1);

    // fusion1: out1 = h1p @ wfus1T + bfus1
    sgemm_kernel<<<dim3(nblk, 1, 1), 256>>>(
        ph1p, pwfus1T, pout1, bfus1, NN, AA * FUSD, FUSD, AA * FUSD, FUSD, FUSD,
        1, 0, 0, 0, 0, 0, 0, 0);

    // stage 2: Wh2 = out1 @ W2 -> [A][N][H*32]
    sgemm_kernel<<<dim3(nblk, 1, AA * HHD), 256>>>(
        pout1, W2, pWh2, nullptr, NN, FUSD, O2D, FUSD, O2D, HO2D,
        HHD, 0, 0, (long long)HHD * FUSD * O2D, (long long)FUSD * O2D,
        (long long)NN * HO2D, O2D, 0);

    fprep_kernel<<<(AA * HHD * NN + 255) / 256, 256>>>(pWh2, a2, pf1, pf2, pea, peb, pE1, pE2, O2D, HO2D);

    att_kernel<O2D><<<dim3(nblk, AA * HHD), 256>>>(pWh2, pf1, pf2, pea, peb, pE1, pE2, pbits, pgat2);

    // interproj2: elu(gat2 @ wint2T + bint2) -> h2p[n][a*8+g]
    sgemm_kernel<<<dim3(nblk, 1, AA), 256>>>(
        pgat2, pwint2T, ph2p, bint2, NN, HO2D, NCLSD, HO2D, NCLSD, AA * NCLSD,
        1, (long long)NN * HO2D, 0, 0, 0, NCLSD, 0, 1);

    // fusion2: logits = h2p @ wfus2T + bfus2
    sgemm_kernel<<<dim3(nblk, 1, 1), 256>>>(
        ph2p, pwfus2T, plogits, bfus2, NN, AA * NCLSD, NCLSD, AA * NCLSD, NCLSD, NCLSD,
        1, 0, 0, 0, 0, 0, 0, 0);

    lsm_kernel<<<(NN + 255) / 256, 256>>>(out, out_size);
    l1_kernel<<<1, 256>>>(wfus1, wfus2, out, out_size);
}

// round 3
// speedup vs baseline: 1.4786x; 1.4786x over previous
#include <cuda_runtime.h>
#include <math.h>
#include <stdint.h>

#define NN 3000
#define NFEATD 512
#define AA 2
#define HHD 4
#define O1D 64
#define O2D 32
#define HO1D 256
#define HO2D 128
#define FUSD 64
#define NCLSD 8
#define WPR 94            // ceil(3000/32) words per adjacency row
#define NTILES 94         // ceil(3000/32) m-tiles
#define ALPHAF 0.2f

// ---------------- scratch (static device allocations) ----------------
__device__ float g_Wh1[AA*NN*HO1D];
__device__ float g_gat1[AA*NN*HO1D];
__device__ float g_Wh2[AA*NN*HO2D];
__device__ float g_gat2[AA*NN*HO2D];
__device__ float g_f1[AA*HHD*NN], g_f2[AA*HHD*NN];
__device__ float g_ea[AA*HHD*NN], g_eb[AA*HHD*NN];
__device__ float g_E1[AA*HHD*NN], g_E2[AA*HHD*NN];
__device__ unsigned g_bits[AA*WPR*NN];   // layout [a][mt][n]
__device__ float g_h1p[NN*AA*FUSD];
__device__ float g_out1[NN*FUSD];
__device__ float g_h2p[NN*AA*NCLSD];
__device__ float g_logits[NN*NCLSD];
__device__ float g_wint1T[HO1D*FUSD];
__device__ float g_wfus1T[AA*FUSD*FUSD];
__device__ float g_wint2T[HO2D*NCLSD];
__device__ float g_wfus2T[AA*NCLSD*NCLSD];

// ---------------- tf32 mma helper ----------------
__device__ __forceinline__ void mma_tf32(float* c, uint32_t a0, uint32_t a1,
                                         uint32_t a2, uint32_t a3,
                                         uint32_t b0, uint32_t b1) {
    asm volatile(
        "mma.sync.aligned.m16n8k8.row.col.f32.tf32.tf32.f32 "
        "{%0,%1,%2,%3}, {%4,%5,%6,%7}, {%8,%9}, {%0,%1,%2,%3};\n"
        : "+f"(c[0]), "+f"(c[1]), "+f"(c[2]), "+f"(c[3])
        : "r"(a0), "r"(a1), "r"(a2), "r"(a3), "r"(b0), "r"(b1));
}

__device__ __forceinline__ float cvt_tf32(float v) {
    uint32_t r;
    asm("cvt.rna.tf32.f32 %0, %1;" : "=r"(r) : "f"(v));
    return __uint_as_float(r);
}

// ---------------- generic small transpose ----------------
__global__ void transpose_kernel(const float* __restrict__ src, float* __restrict__ dst,
                                 int R, int C) {
    int t = blockIdx.x * blockDim.x + threadIdx.x;
    if (t < R * C) {
        int r = t / C, c = t % C;
        dst[c * R + r] = src[t];
    }
}

// ---------------- adjacency -> bitmask via ballot (coalesced) ----------------
__global__ void bitmask_kernel(const int* __restrict__ adj) {
    int gw = (blockIdx.x * blockDim.x + threadIdx.x) >> 5;
    int lane = threadIdx.x & 31;
    if (gw >= AA * NN * WPR) return;
    int a = gw / (NN * WPR);
    int rem = gw % (NN * WPR);
    int n = rem / WPR;
    int mt = rem % WPR;
    int m = mt * 32 + lane;
    int v = 0;
    if (m < NN) v = adj[(size_t)(a * NN + n) * NN + m] > 0;
    unsigned word = __ballot_sync(0xffffffffu, v);
    if (lane == 0) g_bits[(size_t)(a * WPR + mt) * NN + n] = word;
}

// ---------------- per-node attention factor precompute ----------------
__global__ void fprep_kernel(const float* __restrict__ Wh, const float* __restrict__ avec,
                             float* __restrict__ f1o, float* __restrict__ f2o,
                             float* __restrict__ eao, float* __restrict__ ebo,
                             float* __restrict__ E1o, float* __restrict__ E2o,
                             int O, int HO) {
    int t = blockIdx.x * blockDim.x + threadIdx.x;
    if (t >= AA * HHD * NN) return;
    int ah = t / NN, n = t % NN;
    int a = ah / HHD, h = ah % HHD;
    const float* wr = Wh + (size_t)(a * NN + n) * HO + h * O;
    const float* av = avec + ah * 2 * O;
    float f1 = 0.f, f2 = 0.f;
    for (int o = 0; o < O; o++) {
        float w = wr[o];
        f1 += w * av[o];
        f2 += w * av[O + o];
    }
    f1o[t] = f1; f2o[t] = f2;
    eao[t] = expf(f1);          ebo[t] = expf(ALPHAF * f1);
    E1o[t] = expf(f2);          E2o[t] = expf(ALPHAF * f2);
}

// ---------------- generic tf32 MMA GEMM (batched, bias, elu) ----------------
// C[r, col] = sum_k A[r,k] * B[k,col]; A row-major, B row-major [K][O].
// Block: 64 rows x O cols, 256 threads, 8 warps = 4 rowgroups x 2 colgroups.
template <int O>
__global__ void gemm_mma_kernel(const float* __restrict__ A, const float* __restrict__ B,
                                float* __restrict__ C, const float* __restrict__ bias,
                                int M, int K, int lda, int ldb, int ldc,
                                int Hz, long long sAa, long long sAh,
                                long long sBa, long long sBh,
                                long long sCa, int cOffH, int act) {
    constexpr int BS = O + 8;
    constexpr int NT = O / 16;
    int z = blockIdx.y;
    int za = z / Hz, zh = z - za * Hz;
    A += za * sAa + zh * sAh;
    B += za * sBa + zh * sBh;
    C += za * sCa + (long long)zh * cOffH;

    __shared__ float As[64][36];
    __shared__ float Bs[32][BS];

    int tid = threadIdx.x, w = tid >> 5, lane = tid & 31;
    int rg = w >> 1, cg = w & 1;
    int g = lane >> 2, t4 = lane & 3;
    int m0 = blockIdx.x * 64;

    float acc[NT][4];
#pragma unroll
    for (int i = 0; i < NT; i++)
#pragma unroll
        for (int j = 0; j < 4; j++) acc[i][j] = 0.f;

    for (int k0 = 0; k0 < K; k0 += 32) {
        // load A tile 64x32
#pragma unroll
        for (int i = 0; i < 8; i++) {
            int e = tid + i * 256;
            int r = e >> 5, k = e & 31;
            int m = m0 + r;
            float v = (m < M) ? A[(size_t)m * lda + k0 + k] : 0.f;
            As[r][k] = cvt_tf32(v);
        }
        // load B tile 32xO
#pragma unroll
        for (int i = 0; i < (32 * O) / 256; i++) {
            int e = tid + i * 256;
            int k, c;
            if (O == 64) { k = e >> 6; c = e & 63; } else { k = e >> 5; c = e & 31; }
            Bs[k][c] = cvt_tf32(B[(size_t)(k0 + k) * ldb + c]);
        }
        __syncthreads();
#pragma unroll
        for (int kk = 0; kk < 4; kk++) {
            int kb = kk * 8;
            int ar = rg * 16 + g;
            uint32_t a0 = __float_as_uint(As[ar][kb + t4]);
            uint32_t a1 = __float_as_uint(As[ar + 8][kb + t4]);
            uint32_t a2 = __float_as_uint(As[ar][kb + t4 + 4]);
            uint32_t a3 = __float_as_uint(As[ar + 8][kb + t4 + 4]);
#pragma unroll
            for (int nt = 0; nt < NT; nt++) {
                int col = cg * (O / 2) + nt * 8 + g;
                uint32_t b0 = __float_as_uint(Bs[kb + t4][col]);
                uint32_t b1 = __float_as_uint(Bs[kb + t4 + 4][col]);
                mma_tf32(acc[nt], a0, a1, a2, a3, b0, b1);
            }
        }
        __syncthreads();
    }
    // epilogue
#pragma unroll
    for (int half = 0; half < 2; half++) {
        int r = rg * 16 + g + half * 8;
        int gr = m0 + r;
        if (gr < M) {
#pragma unroll
            for (int nt = 0; nt < NT; nt++) {
                int col = cg * (O / 2) + nt * 8 + 2 * t4;
                float v0 = acc[nt][half * 2 + 0];
                float v1 = acc[nt][half * 2 + 1];
                if (bias) { v0 += bias[col]; v1 += bias[col + 1]; }
                if (act == 1) {
                    v0 = v0 > 0.f ? v0 : (expf(v0) - 1.f);
                    v1 = v1 > 0.f ? v1 : (expf(v1) - 1.f);
                }
                *(float2*)&C[(size_t)gr * ldc + col] = make_float2(v0, v1);
            }
        }
    }
}

// ---------------- fused masked-softmax attention aggregate (tf32 MMA) ----------------
// out[n,:] = elu( (sum_m w(n,m)*Wh[m,:]) / (sum_m w(n,m)) )
// w(n,m) = adjbit(n,m) * ( f1[n]+f2[m] > 0 ? ea[n]*E1[m] : eb[n]*E2[m] )
template <int O>
__global__ void att_mma_kernel(const float* __restrict__ Wh,
                               const float* __restrict__ f1v, const float* __restrict__ f2v,
                               const float* __restrict__ eav, const float* __restrict__ ebv,
                               const float* __restrict__ E1v, const float* __restrict__ E2v,
                               const unsigned* __restrict__ bits, float* __restrict__ outp) {
    constexpr int HO = HHD * O;
    constexpr int BS = O + 8;
    constexpr int NT = O / 16;
    int z = blockIdx.y;
    int a = z >> 2, h = z & 3;
    int n0 = blockIdx.x * 64;
    const float* whb = Wh + (size_t)a * NN * HO + h * O;
    const float* f2b = f2v + (size_t)z * NN;
    const float* E1b = E1v + (size_t)z * NN;
    const float* E2b = E2v + (size_t)z * NN;
    const unsigned* bb = bits + (size_t)a * WPR * NN;

    __shared__ float Whs[32][BS];
    __shared__ float ws[64][36];
    __shared__ float f1s[64], eas[64], ebs[64];
    __shared__ float Zr[64];

    int tid = threadIdx.x, w = tid >> 5, lane = tid & 31;
    int rg = w >> 1, cg = w & 1;
    int g = lane >> 2, t4 = lane & 3;

    if (tid < 64) {
        int gr = n0 + tid;
        float f1 = 0.f, ea = 0.f, eb = 0.f;
        if (gr < NN) {
            f1 = f1v[(size_t)z * NN + gr];
            ea = eav[(size_t)z * NN + gr];
            eb = ebv[(size_t)z * NN + gr];
        }
        f1s[tid] = f1; eas[tid] = ea; ebs[tid] = eb;
    }

    float acc[NT][4];
#pragma unroll
    for (int i = 0; i < NT; i++)
#pragma unroll
        for (int j = 0; j < 4; j++) acc[i][j] = 0.f;
    float zp[8];
#pragma unroll
    for (int i = 0; i < 8; i++) zp[i] = 0.f;

    __syncthreads();

    for (int mt = 0; mt < NTILES; mt++) {
        // load Wh tile 32xO
#pragma unroll
        for (int i = 0; i < (32 * O) / 256; i++) {
            int e = tid + i * 256;
            int lm, o;
            if (O == 64) { lm = e >> 6; o = e & 63; } else { lm = e >> 5; o = e & 31; }
            int m = mt * 32 + lm;
            float v = (m < NN) ? whb[(size_t)m * HO + o] : 0.f;
            Whs[lm][o] = cvt_tf32(v);
        }
        // build weight tile: warp w builds rows w*8..w*8+7, lane = m-within-tile
#pragma unroll
        for (int rr = 0; rr < 8; rr++) {
            int r = w * 8 + rr;
            int gr = n0 + r;
            unsigned word = (gr < NN) ? bb[(size_t)mt * NN + gr] : 0u;
            float wv = 0.f;
            if ((word >> lane) & 1u) {
                int m = mt * 32 + lane;   // bits beyond NN are zero, so m < NN here
                float s = f1s[r] + f2b[m];
                wv = (s > 0.f) ? eas[r] * E1b[m] : ebs[r] * E2b[m];
            }
            float wt = cvt_tf32(wv);
            ws[r][lane] = wt;
            zp[rr] += wt;
        }
        __syncthreads();
#pragma unroll
        for (int kk = 0; kk < 4; kk++) {
            int kb = kk * 8;
            int ar = rg * 16 + g;
            uint32_t a0 = __float_as_uint(ws[ar][kb + t4]);
            uint32_t a1 = __float_as_uint(ws[ar + 8][kb + t4]);
            uint32_t a2 = __float_as_uint(ws[ar][kb + t4 + 4]);
            uint32_t a3 = __float_as_uint(ws[ar + 8][kb + t4 + 4]);
#pragma unroll
            for (int nt = 0; nt < NT; nt++) {
                int col = cg * (O / 2) + nt * 8 + g;
                uint32_t b0 = __float_as_uint(Whs[kb + t4][col]);
                uint32_t b1 = __float_as_uint(Whs[kb + t4 + 4][col]);
                mma_tf32(acc[nt], a0, a1, a2, a3, b0, b1);
            }
        }
        __syncthreads();
    }

    // per-row Z reduce (lane-striped partials)
#pragma unroll
    for (int rr = 0; rr < 8; rr++) {
        float s = zp[rr];
        s += __shfl_xor_sync(0xffffffffu, s, 16);
        s += __shfl_xor_sync(0xffffffffu, s, 8);
        s += __shfl_xor_sync(0xffffffffu, s, 4);
        s += __shfl_xor_sync(0xffffffffu, s, 2);
        s += __shfl_xor_sync(0xffffffffu, s, 1);
        if (lane == 0) Zr[w * 8 + rr] = (s > 0.f) ? 1.f / s : 0.f;
    }
    __syncthreads();

    // epilogue: normalize + elu + store
#pragma unroll
    for (int half = 0; half < 2; half++) {
        int r = rg * 16 + g + half * 8;
        int gr = n0 + r;
        if (gr < NN) {
            float inv = Zr[r];
#pragma unroll
            for (int nt = 0; nt < NT; nt++) {
                int col = cg * (O / 2) + nt * 8 + 2 * t4;
                float v0 = acc[nt][half * 2 + 0] * inv;
                float v1 = acc[nt][half * 2 + 1] * inv;
                v0 = v0 > 0.f ? v0 : (expf(v0) - 1.f);
                v1 = v1 > 0.f ? v1 : (expf(v1) - 1.f);
                *(float2*)&outp[(size_t)(a * NN + gr) * HO + h * O + col] =
                    make_float2(v0, v1);
            }
        }
    }
}

// ---------------- SIMT SGEMM kept for tiny tail layers ----------------
__global__ void sgemm_kernel(const float* __restrict__ A, const float* __restrict__ B,
                             float* __restrict__ C, const float* __restrict__ bias,
                             int M, int K, int Nc, int lda, int ldb, int ldc,
                             int Hz, long long sAa, long long sAh,
                             long long sBa, long long sBh,
                             long long sCa, long long sCh, int act) {
    int z = blockIdx.z;
    int za = z / Hz, zh = z % Hz;
    A += za * sAa + zh * sAh;
    B += za * sBa + zh * sBh;
    C += za * sCa + zh * sCh;
    __shared__ float As[16][65];
    __shared__ __align__(16) float Bs[16][64];
    int tid = threadIdx.x;
    int tx = tid & 15, ty = tid >> 4;
    int m0 = blockIdx.x * 64, n0 = blockIdx.y * 64;
    float acc[4][4] = {};
    for (int k0 = 0; k0 < K; k0 += 16) {
        __syncthreads();
#pragma unroll
        for (int i = 0; i < 4; i++) {
            int e = tid + i * 256;
            int k = e & 15, m = e >> 4;
            As[k][m] = (m0 + m < M) ? A[(size_t)(m0 + m) * lda + k0 + k] : 0.f;
        }
#pragma unroll
        for (int i = 0; i < 4; i++) {
            int e = tid + i * 256;
            int n = e & 63, k = e >> 6;
            Bs[k][n] = (n0 + n < Nc) ? B[(size_t)(k0 + k) * ldb + n0 + n] : 0.f;
        }
        __syncthreads();
#pragma unroll
        for (int k = 0; k < 16; k++) {
            float4 bv = *reinterpret_cast<const float4*>(&Bs[k][tx * 4]);
            float b4[4] = {bv.x, bv.y, bv.z, bv.w};
#pragma unroll
            for (int i = 0; i < 4; i++) {
                float av = As[k][ty * 4 + i];
#pragma unroll
                for (int j = 0; j < 4; j++) acc[i][j] += av * b4[j];
            }
        }
    }
#pragma unroll
    for (int i = 0; i < 4; i++) {
        int r = m0 + ty * 4 + i;
        if (r >= M) continue;
#pragma unroll
        for (int j = 0; j < 4; j++) {
            int c = n0 + tx * 4 + j;
            if (c >= Nc) continue;
            float v = acc[i][j];
            if (bias) v += bias[c];
            if (act == 1) v = v > 0.f ? v : (expf(v) - 1.f);
            C[(size_t)r * ldc + c] = v;
        }
    }
}

// ---------------- log_softmax + L1 scalar ----------------
__global__ void lsm_kernel(float* __restrict__ out, int out_size) {
    int n = blockIdx.x * blockDim.x + threadIdx.x;
    if (n >= NN) return;
    float v[NCLSD];
    float mx = -1e30f;
#pragma unroll
    for (int c = 0; c < NCLSD; c++) { v[c] = g_logits[n * NCLSD + c]; mx = fmaxf(mx, v[c]); }
    float s = 0.f;
#pragma unroll
    for (int c = 0; c < NCLSD; c++) s += expf(v[c] - mx);
    float l = logf(s) + mx;
#pragma unroll
    for (int c = 0; c < NCLSD; c++) {
        int idx = n * NCLSD + c;
        if (idx < out_size) out[idx] = v[c] - l;
    }
}

__global__ void l1_kernel(const float* __restrict__ wfus1, const float* __restrict__ wfus2,
                          float* __restrict__ out, int out_size) {
    __shared__ float red[256];
    int tid = threadIdx.x;
    float s1 = 0.f, s2 = 0.f;
    for (int i = tid; i < FUSD * AA * FUSD; i += 256) s1 += fabsf(wfus1[i]);
    for (int i = tid; i < NCLSD * AA * NCLSD; i += 256) s2 += fabsf(wfus2[i]);
    red[tid] = s1 / (float)(FUSD * AA * FUSD) + s2 / (float)(NCLSD * AA * NCLSD);
    __syncthreads();
    for (int o = 128; o > 0; o >>= 1) {
        if (tid < o) red[tid] += red[tid + o];
        __syncthreads();
    }
    if (tid == 0 && out_size > NN * NCLSD) out[NN * NCLSD] = red[0];
}

// ---------------- host launcher ----------------
extern "C" void kernel_launch(void* const* d_in, const int* in_sizes, int n_in,
                              void* d_out, int out_size) {
    const float* x     = (const float*)d_in[0];
    const int*   adj   = (const int*)d_in[1];
    const float* W1    = (const float*)d_in[2];
    const float* a1    = (const float*)d_in[3];
    const float* W2    = (const float*)d_in[4];
    const float* a2    = (const float*)d_in[5];
    const float* wint1 = (const float*)d_in[6];
    const float* bint1 = (const float*)d_in[7];
    const float* wfus1 = (const float*)d_in[8];
    const float* bfus1 = (const float*)d_in[9];
    const float* wint2 = (const float*)d_in[10];
    const float* bint2 = (const float*)d_in[11];
    const float* wfus2 = (const float*)d_in[12];
    const float* bfus2 = (const float*)d_in[13];
    float* out = (float*)d_out;

    float *pWh1, *pgat1, *pWh2, *pgat2;
    float *pf1, *pf2, *pea, *peb, *pE1, *pE2;
    float *ph1p, *pout1, *ph2p, *plogits;
    float *pwint1T, *pwfus1T, *pwint2T, *pwfus2T;
    unsigned* pbits;
    cudaGetSymbolAddress((void**)&pWh1, g_Wh1);
    cudaGetSymbolAddress((void**)&pgat1, g_gat1);
    cudaGetSymbolAddress((void**)&pWh2, g_Wh2);
    cudaGetSymbolAddress((void**)&pgat2, g_gat2);
    cudaGetSymbolAddress((void**)&pf1, g_f1);
    cudaGetSymbolAddress((void**)&pf2, g_f2);
    cudaGetSymbolAddress((void**)&pea, g_ea);
    cudaGetSymbolAddress((void**)&peb, g_eb);
    cudaGetSymbolAddress((void**)&pE1, g_E1);
    cudaGetSymbolAddress((void**)&pE2, g_E2);
    cudaGetSymbolAddress((void**)&pbits, g_bits);
    cudaGetSymbolAddress((void**)&ph1p, g_h1p);
    cudaGetSymbolAddress((void**)&pout1, g_out1);
    cudaGetSymbolAddress((void**)&ph2p, g_h2p);
    cudaGetSymbolAddress((void**)&plogits, g_logits);
    cudaGetSymbolAddress((void**)&pwint1T, g_wint1T);
    cudaGetSymbolAddress((void**)&pwfus1T, g_wfus1T);
    cudaGetSymbolAddress((void**)&pwint2T, g_wint2T);
    cudaGetSymbolAddress((void**)&pwfus2T, g_wfus2T);

    // weight transposes (tiny)
    transpose_kernel<<<(FUSD * HO1D + 255) / 256, 256>>>(wint1, pwint1T, FUSD, HO1D);
    transpose_kernel<<<(FUSD * AA * FUSD + 255) / 256, 256>>>(wfus1, pwfus1T, FUSD, AA * FUSD);
    transpose_kernel<<<(NCLSD * HO2D + 255) / 256, 256>>>(wint2, pwint2T, NCLSD, HO2D);
    transpose_kernel<<<(NCLSD * AA * NCLSD + 255) / 256, 256>>>(wfus2, pwfus2T, NCLSD, AA * NCLSD);

    // adjacency bitmask (ballot, coalesced)
    {
        long long warps = (long long)AA * NN * WPR;
        int blocks = (int)((warps * 32 + 255) / 256);
        bitmask_kernel<<<blocks, 256>>>(adj);
    }

    int nblk = (NN + 63) / 64;   // 47

    // stage 1: Wh1 = x @ W1  -> [A][N][H*64]
    gemm_mma_kernel<O1D><<<dim3(nblk, AA * HHD), 256>>>(
        x, W1, pWh1, nullptr, NN, NFEATD, NFEATD, O1D, HO1D,
        HHD, 0, 0, (long long)HHD * NFEATD * O1D, (long long)NFEATD * O1D,
        (long long)NN * HO1D, O1D, 0);

    fprep_kernel<<<(AA * HHD * NN + 255) / 256, 256>>>(pWh1, a1, pf1, pf2, pea, peb, pE1, pE2, O1D, HO1D);

    att_mma_kernel<O1D><<<dim3(nblk, AA * HHD), 256>>>(pWh1, pf1, pf2, pea, peb, pE1, pE2, pbits, pgat1);

    // interproj1: elu(gat1 @ wint1T + bint1) -> h1p[n][a*64+g]
    gemm_mma_kernel<FUSD><<<dim3(nblk, AA), 256>>>(
        pgat1, pwint1T, ph1p, bint1, NN, HO1D, HO1D, FUSD, AA * FUSD,
        1, (long long)NN * HO1D, 0, 0, 0, FUSD, 0, 1);

    // fusion1: out1 = h1p @ wfus1T + bfus1
    gemm_mma_kernel<FUSD><<<dim3(nblk, 1), 256>>>(
        ph1p, pwfus1T, pout1, bfus1, NN, AA * FUSD, AA * FUSD, FUSD, FUSD,
        1, 0, 0, 0, 0, 0, 0, 0);

    // stage 2: Wh2 = out1 @ W2 -> [A][N][H*32]
    gemm_mma_kernel<O2D><<<dim3(nblk, AA * HHD), 256>>>(
        pout1, W2, pWh2, nullptr, NN, FUSD, FUSD, O2D, HO2D,
        HHD, 0, 0, (long long)HHD * FUSD * O2D, (long long)FUSD * O2D,
        (long long)NN * HO2D, O2D, 0);

    fprep_kernel<<<(AA * HHD * NN + 255) / 256, 256>>>(pWh2, a2, pf1, pf2, pea, peb, pE1, pE2, O2D, HO2D);

    att_mma_kernel<O2D><<<dim3(nblk, AA * HHD), 256>>>(pWh2, pf1, pf2, pea, peb, pE1, pE2, pbits, pgat2);

    // interproj2: elu(gat2 @ wint2T + bint2) -> h2p[n][a*8+g]  (tiny, SIMT)
    sgemm_kernel<<<dim3(nblk, 1, AA), 256>>>(
        pgat2, pwint2T, ph2p, bint2, NN, HO2D, NCLSD, HO2D, NCLSD, AA * NCLSD,
        1, (long long)NN * HO2D, 0, 0, 0, NCLSD, 0, 1);

    // fusion2: logits = h2p @ wfus2T + bfus2  (tiny, SIMT)
    sgemm_kernel<<<dim3(nblk, 1, 1), 256>>>(
        ph2p, pwfus2T, plogits, bfus2, NN, AA * NCLSD, NCLSD,
        AA * NCLSD, NCLSD, NCLSD,
        1, 0, 0, 0, 0, 0, 0, 0);

    lsm_kernel<<<(NN + 255) / 256, 256>>>(out, out_size);
    l1_kernel<<<1, 256>>>(wfus1, wfus2, out, out_size);
}

// round 4
// speedup vs baseline: 1.7395x; 1.1765x over previous
#include <cuda_runtime.h>
#include <math.h>
#include <stdint.h>

#define NN 3000
#define NFEATD 512
#define AA 2
#define HHD 4
#define O1D 64
#define O2D 32
#define HO1D 256
#define HO2D 128
#define FUSD 64
#define NCLSD 8
#define WPR 94            // ceil(3000/32) words per adjacency row
#define NTILES 94         // ceil(3000/32) m-tiles
#define ALPHAF 0.2f

// ---------------- scratch (static device allocations) ----------------
__device__ float g_Wh1[AA*NN*HO1D];
__device__ float g_gat1[AA*NN*HO1D];
__device__ float g_Wh2[AA*NN*HO2D];
__device__ float g_gat2[AA*NN*HO2D];
__device__ float g_f1[AA*HHD*NN], g_f2[AA*HHD*NN];
__device__ float g_ea[AA*HHD*NN], g_eb[AA*HHD*NN];
__device__ float g_E1[AA*HHD*NN], g_E2[AA*HHD*NN];
__device__ unsigned g_bits[AA*WPR*NN];   // layout [a][mt][n]
__device__ float g_h1p[NN*AA*FUSD];
__device__ float g_out1[NN*FUSD];
__device__ float g_h2p[NN*AA*NCLSD];
__device__ float g_logits[NN*NCLSD];
__device__ float g_wint1T[HO1D*FUSD];
__device__ float g_wfus1T[AA*FUSD*FUSD];
__device__ float g_wint2T[HO2D*NCLSD];
__device__ float g_wfus2T[AA*NCLSD*NCLSD];

// ---------------- tf32 mma helper ----------------
__device__ __forceinline__ void mma_tf32(float* c, uint32_t a0, uint32_t a1,
                                         uint32_t a2, uint32_t a3,
                                         uint32_t b0, uint32_t b1) {
    asm volatile(
        "mma.sync.aligned.m16n8k8.row.col.f32.tf32.tf32.f32 "
        "{%0,%1,%2,%3}, {%4,%5,%6,%7}, {%8,%9}, {%0,%1,%2,%3};\n"
        : "+f"(c[0]), "+f"(c[1]), "+f"(c[2]), "+f"(c[3])
        : "r"(a0), "r"(a1), "r"(a2), "r"(a3), "r"(b0), "r"(b1));
}

__device__ __forceinline__ float cvt_tf32(float v) {
    uint32_t r;
    asm("cvt.rna.tf32.f32 %0, %1;" : "=r"(r) : "f"(v));
    return __uint_as_float(r);
}

// ---------------- merged weight transposes (1 launch) ----------------
__global__ void transpose_all_kernel(const float* __restrict__ wint1,
                                     const float* __restrict__ wfus1,
                                     const float* __restrict__ wint2,
                                     const float* __restrict__ wfus2) {
    const int S1 = FUSD * HO1D;            // 16384
    const int S2 = FUSD * AA * FUSD;       // 8192
    const int S3 = NCLSD * HO2D;           // 1024
    const int S4 = NCLSD * AA * NCLSD;     // 128
    int t = blockIdx.x * blockDim.x + threadIdx.x;
    if (t < S1) {
        int r = t / HO1D, c = t % HO1D;
        g_wint1T[c * FUSD + r] = wint1[t];
    } else if (t < S1 + S2) {
        int e = t - S1;
        int r = e / (AA * FUSD), c = e % (AA * FUSD);
        g_wfus1T[c * FUSD + r] = wfus1[e];
    } else if (t < S1 + S2 + S3) {
        int e = t - S1 - S2;
        int r = e / HO2D, c = e % HO2D;
        g_wint2T[c * NCLSD + r] = wint2[e];
    } else if (t < S1 + S2 + S3 + S4) {
        int e = t - S1 - S2 - S3;
        int r = e / (AA * NCLSD), c = e % (AA * NCLSD);
        g_wfus2T[c * NCLSD + r] = wfus2[e];
    }
}

// ---------------- adjacency -> bitmask via ballot (coalesced) ----------------
__global__ void bitmask_kernel(const int* __restrict__ adj) {
    int gw = (blockIdx.x * blockDim.x + threadIdx.x) >> 5;
    int lane = threadIdx.x & 31;
    if (gw >= AA * NN * WPR) return;
    int a = gw / (NN * WPR);
    int rem = gw % (NN * WPR);
    int n = rem / WPR;
    int mt = rem % WPR;
    int m = mt * 32 + lane;
    int v = 0;
    if (m < NN) v = adj[(size_t)(a * NN + n) * NN + m] > 0;
    unsigned word = __ballot_sync(0xffffffffu, v);
    if (lane == 0) g_bits[(size_t)(a * WPR + mt) * NN + n] = word;
}

// ---------------- per-node attention factor precompute ----------------
__global__ void fprep_kernel(const float* __restrict__ Wh, const float* __restrict__ avec,
                             float* __restrict__ f1o, float* __restrict__ f2o,
                             float* __restrict__ eao, float* __restrict__ ebo,
                             float* __restrict__ E1o, float* __restrict__ E2o,
                             int O, int HO) {
    int t = blockIdx.x * blockDim.x + threadIdx.x;
    if (t >= AA * HHD * NN) return;
    int ah = t / NN, n = t % NN;
    int a = ah / HHD, h = ah % HHD;
    const float* wr = Wh + (size_t)(a * NN + n) * HO + h * O;
    const float* av = avec + ah * 2 * O;
    float f1 = 0.f, f2 = 0.f;
    for (int o = 0; o < O; o++) {
        float w = wr[o];
        f1 += w * av[o];
        f2 += w * av[O + o];
    }
    f1o[t] = f1; f2o[t] = f2;
    eao[t] = expf(f1);          ebo[t] = expf(ALPHAF * f1);
    E1o[t] = expf(f2);          E2o[t] = expf(ALPHAF * f2);
}

// ---------------- generic tf32 MMA GEMM (batched, bias, elu) ----------------
template <int O>
__global__ void gemm_mma_kernel(const float* __restrict__ A, const float* __restrict__ B,
                                float* __restrict__ C, const float* __restrict__ bias,
                                int M, int K, int lda, int ldb, int ldc,
                                int Hz, long long sAa, long long sAh,
                                long long sBa, long long sBh,
                                long long sCa, int cOffH, int act) {
    constexpr int BS = O + 8;
    constexpr int NT = O / 16;
    int z = blockIdx.y;
    int za = z / Hz, zh = z - za * Hz;
    A += za * sAa + zh * sAh;
    B += za * sBa + zh * sBh;
    C += za * sCa + (long long)zh * cOffH;

    __shared__ float As[64][36];
    __shared__ float Bs[32][BS];

    int tid = threadIdx.x, w = tid >> 5, lane = tid & 31;
    int rg = w >> 1, cg = w & 1;
    int g = lane >> 2, t4 = lane & 3;
    int m0 = blockIdx.x * 64;

    float acc[NT][4];
#pragma unroll
    for (int i = 0; i < NT; i++)
#pragma unroll
        for (int j = 0; j < 4; j++) acc[i][j] = 0.f;

    for (int k0 = 0; k0 < K; k0 += 32) {
#pragma unroll
        for (int i = 0; i < 8; i++) {
            int e = tid + i * 256;
            int r = e >> 5, k = e & 31;
            int m = m0 + r;
            float v = (m < M) ? A[(size_t)m * lda + k0 + k] : 0.f;
            As[r][k] = cvt_tf32(v);
        }
#pragma unroll
        for (int i = 0; i < (32 * O) / 256; i++) {
            int e = tid + i * 256;
            int k, c;
            if (O == 64) { k = e >> 6; c = e & 63; } else { k = e >> 5; c = e & 31; }
            Bs[k][c] = cvt_tf32(B[(size_t)(k0 + k) * ldb + c]);
        }
        __syncthreads();
#pragma unroll
        for (int kk = 0; kk < 4; kk++) {
            int kb = kk * 8;
            int ar = rg * 16 + g;
            uint32_t a0 = __float_as_uint(As[ar][kb + t4]);
            uint32_t a1 = __float_as_uint(As[ar + 8][kb + t4]);
            uint32_t a2 = __float_as_uint(As[ar][kb + t4 + 4]);
            uint32_t a3 = __float_as_uint(As[ar + 8][kb + t4 + 4]);
#pragma unroll
            for (int nt = 0; nt < NT; nt++) {
                int col = cg * (O / 2) + nt * 8 + g;
                uint32_t b0 = __float_as_uint(Bs[kb + t4][col]);
                uint32_t b1 = __float_as_uint(Bs[kb + t4 + 4][col]);
                mma_tf32(acc[nt], a0, a1, a2, a3, b0, b1);
            }
        }
        __syncthreads();
    }
#pragma unroll
    for (int half = 0; half < 2; half++) {
        int r = rg * 16 + g + half * 8;
        int gr = m0 + r;
        if (gr < M) {
#pragma unroll
            for (int nt = 0; nt < NT; nt++) {
                int col = cg * (O / 2) + nt * 8 + 2 * t4;
                float v0 = acc[nt][half * 2 + 0];
                float v1 = acc[nt][half * 2 + 1];
                if (bias) { v0 += bias[col]; v1 += bias[col + 1]; }
                if (act == 1) {
                    v0 = v0 > 0.f ? v0 : (expf(v0) - 1.f);
                    v1 = v1 > 0.f ? v1 : (expf(v1) - 1.f);
                }
                *(float2*)&C[(size_t)gr * ldc + col] = make_float2(v0, v1);
            }
        }
    }
}

// ---------------- fused masked-softmax attention aggregate (tf32 MMA, 2-stage pipeline) ----------------
// out[n,:] = elu( (sum_m w(n,m)*Wh[m,:]) / (sum_m w(n,m)) )
// w(n,m) = adjbit(n,m) * ( f1[n]+f2[m] > 0 ? ea[n]*E1[m] : eb[n]*E2[m] )
template <int O>
__global__ void att_mma_kernel(const float* __restrict__ Wh,
                               const float* __restrict__ f1v, const float* __restrict__ f2v,
                               const float* __restrict__ eav, const float* __restrict__ ebv,
                               const float* __restrict__ E1v, const float* __restrict__ E2v,
                               const unsigned* __restrict__ bits, float* __restrict__ outp) {
    constexpr int HO = HHD * O;
    constexpr int BS = O + 8;
    constexpr int NT = O / 16;
    int z = blockIdx.y;
    int a = z >> 2, h = z & 3;
    int n0 = blockIdx.x * 64;
    const float* whb = Wh + (size_t)a * NN * HO + h * O;
    const float* f2b = f2v + (size_t)z * NN;
    const float* E1b = E1v + (size_t)z * NN;
    const float* E2b = E2v + (size_t)z * NN;
    const unsigned* bb = bits + (size_t)a * WPR * NN;

    __shared__ float Whs[2][32][BS];
    __shared__ float ws[2][64][36];
    __shared__ float f1s[64], eas[64], ebs[64];
    __shared__ float Zr[64];

    int tid = threadIdx.x, w = tid >> 5, lane = tid & 31;
    int rg = w >> 1, cg = w & 1;
    int g = lane >> 2, t4 = lane & 3;

    if (tid < 64) {
        int gr = n0 + tid;
        float f1 = 0.f, ea = 0.f, eb = 0.f;
        if (gr < NN) {
            f1 = f1v[(size_t)z * NN + gr];
            ea = eav[(size_t)z * NN + gr];
            eb = ebv[(size_t)z * NN + gr];
        }
        f1s[tid] = f1; eas[tid] = ea; ebs[tid] = eb;
    }

    float acc[NT][4];
#pragma unroll
    for (int i = 0; i < NT; i++)
#pragma unroll
        for (int j = 0; j < 4; j++) acc[i][j] = 0.f;
    float zp[8];
#pragma unroll
    for (int i = 0; i < 8; i++) zp[i] = 0.f;

    __syncthreads();   // f1s/eas/ebs visible before any build

    // ---- tile builder: load Wh tile + construct weight tile into buffer buf ----
    auto build_tile = [&](int mt, int buf) {
        // Wh tile 32 x O
#pragma unroll
        for (int i = 0; i < (32 * O) / 256; i++) {
            int e = tid + i * 256;
            int lm, o;
            if (O == 64) { lm = e >> 6; o = e & 63; } else { lm = e >> 5; o = e & 31; }
            int m = mt * 32 + lm;
            float v = (m < NN) ? whb[(size_t)m * HO + o] : 0.f;
            Whs[buf][lm][o] = cvt_tf32(v);
        }
        // per-tile m-side factors (one coalesced load per warp)
        int m = mt * 32 + lane;
        float f2m = 0.f, E1m = 0.f, E2m = 0.f;
        if (m < NN) { f2m = f2b[m]; E1m = E1b[m]; E2m = E2b[m]; }
        // warp w builds rows w*8..w*8+7, lane = m-within-tile
#pragma unroll
        for (int rr = 0; rr < 8; rr++) {
            int r = w * 8 + rr;
            int gr = n0 + r;
            unsigned word = (gr < NN) ? bb[(size_t)mt * NN + gr] : 0u;
            float wv = 0.f;
            if ((word >> lane) & 1u) {
                float s = f1s[r] + f2m;
                wv = (s > 0.f) ? eas[r] * E1m : ebs[r] * E2m;
            }
            wv = cvt_tf32(wv);
            ws[buf][r][lane] = wv;
            zp[rr] += wv;
        }
    };

    build_tile(0, 0);
    __syncthreads();

    for (int mt = 0; mt < NTILES; mt++) {
        int cur = mt & 1;
        if (mt + 1 < NTILES) build_tile(mt + 1, cur ^ 1);
        // MMA on current buffer
#pragma unroll
        for (int kk = 0; kk < 4; kk++) {
            int kb = kk * 8;
            int ar = rg * 16 + g;
            uint32_t a0 = __float_as_uint(ws[cur][ar][kb + t4]);
            uint32_t a1 = __float_as_uint(ws[cur][ar + 8][kb + t4]);
            uint32_t a2 = __float_as_uint(ws[cur][ar][kb + t4 + 4]);
            uint32_t a3 = __float_as_uint(ws[cur][ar + 8][kb + t4 + 4]);
#pragma unroll
            for (int nt = 0; nt < NT; nt++) {
                int col = cg * (O / 2) + nt * 8 + g;
                uint32_t b0 = __float_as_uint(Whs[cur][kb + t4][col]);
                uint32_t b1 = __float_as_uint(Whs[cur][kb + t4 + 4][col]);
                mma_tf32(acc[nt], a0, a1, a2, a3, b0, b1);
            }
        }
        __syncthreads();
    }

    // per-row Z reduce (lane-striped partials)
#pragma unroll
    for (int rr = 0; rr < 8; rr++) {
        float s = zp[rr];
        s += __shfl_xor_sync(0xffffffffu, s, 16);
        s += __shfl_xor_sync(0xffffffffu, s, 8);
        s += __shfl_xor_sync(0xffffffffu, s, 4);
        s += __shfl_xor_sync(0xffffffffu, s, 2);
        s += __shfl_xor_sync(0xffffffffu, s, 1);
        if (lane == 0) Zr[w * 8 + rr] = (s > 0.f) ? 1.f / s : 0.f;
    }
    __syncthreads();

    // epilogue: normalize + elu + store
#pragma unroll
    for (int half = 0; half < 2; half++) {
        int r = rg * 16 + g + half * 8;
        int gr = n0 + r;
        if (gr < NN) {
            float inv = Zr[r];
#pragma unroll
            for (int nt = 0; nt < NT; nt++) {
                int col = cg * (O / 2) + nt * 8 + 2 * t4;
                float v0 = acc[nt][half * 2 + 0] * inv;
                float v1 = acc[nt][half * 2 + 1] * inv;
                v0 = v0 > 0.f ? v0 : (expf(v0) - 1.f);
                v1 = v1 > 0.f ? v1 : (expf(v1) - 1.f);
                *(float2*)&outp[(size_t)(a * NN + gr) * HO + h * O + col] =
                    make_float2(v0, v1);
            }
        }
    }
}

// ---------------- SIMT SGEMM kept for tiny tail layers ----------------
__global__ void sgemm_kernel(const float* __restrict__ A, const float* __restrict__ B,
                             float* __restrict__ C, const float* __restrict__ bias,
                             int M, int K, int Nc, int lda, int ldb, int ldc,
                             int Hz, long long sAa, long long sAh,
                             long long sBa, long long sBh,
                             long long sCa, long long sCh, int act) {
    int z = blockIdx.z;
    int za = z / Hz, zh = z % Hz;
    A += za * sAa + zh * sAh;
    B += za * sBa + zh * sBh;
    C += za * sCa + zh * sCh;
    __shared__ float As[16][65];
    __shared__ __align__(16) float Bs[16][64];
    int tid = threadIdx.x;
    int tx = tid & 15, ty = tid >> 4;
    int m0 = blockIdx.x * 64, n0 = blockIdx.y * 64;
    float acc[4][4] = {};
    for (int k0 = 0; k0 < K; k0 += 16) {
        __syncthreads();
#pragma unroll
        for (int i = 0; i < 4; i++) {
            int e = tid + i * 256;
            int k = e & 15, m = e >> 4;
            As[k][m] = (m0 + m < M) ? A[(size_t)(m0 + m) * lda + k0 + k] : 0.f;
        }
#pragma unroll
        for (int i = 0; i < 4; i++) {
            int e = tid + i * 256;
            int n = e & 63, k = e >> 6;
            Bs[k][n] = (n0 + n < Nc) ? B[(size_t)(k0 + k) * ldb + n0 + n] : 0.f;
        }
        __syncthreads();
#pragma unroll
        for (int k = 0; k < 16; k++) {
            float4 bv = *reinterpret_cast<const float4*>(&Bs[k][tx * 4]);
            float b4[4] = {bv.x, bv.y, bv.z, bv.w};
#pragma unroll
            for (int i = 0; i < 4; i++) {
                float av = As[k][ty * 4 + i];
#pragma unroll
                for (int j = 0; j < 4; j++) acc[i][j] += av * b4[j];
            }
        }
    }
#pragma unroll
    for (int i = 0; i < 4; i++) {
        int r = m0 + ty * 4 + i;
        if (r >= M) continue;
#pragma unroll
        for (int j = 0; j < 4; j++) {
            int c = n0 + tx * 4 + j;
            if (c >= Nc) continue;
            float v = acc[i][j];
            if (bias) v += bias[c];
            if (act == 1) v = v > 0.f ? v : (expf(v) - 1.f);
            C[(size_t)r * ldc + c] = v;
        }
    }
}

// ---------------- log_softmax + L1 scalar ----------------
__global__ void lsm_kernel(float* __restrict__ out, int out_size) {
    int n = blockIdx.x * blockDim.x + threadIdx.x;
    if (n >= NN) return;
    float v[NCLSD];
    float mx = -1e30f;
#pragma unroll
    for (int c = 0; c < NCLSD; c++) { v[c] = g_logits[n * NCLSD + c]; mx = fmaxf(mx, v[c]); }
    float s = 0.f;
#pragma unroll
    for (int c = 0; c < NCLSD; c++) s += expf(v[c] - mx);
    float l = logf(s) + mx;
#pragma unroll
    for (int c = 0; c < NCLSD; c++) {
        int idx = n * NCLSD + c;
        if (idx < out_size) out[idx] = v[c] - l;
    }
}

__global__ void l1_kernel(const float* __restrict__ wfus1, const float* __restrict__ wfus2,
                          float* __restrict__ out, int out_size) {
    __shared__ float red[256];
    int tid = threadIdx.x;
    float s1 = 0.f, s2 = 0.f;
    for (int i = tid; i < FUSD * AA * FUSD; i += 256) s1 += fabsf(wfus1[i]);
    for (int i = tid; i < NCLSD * AA * NCLSD; i += 256) s2 += fabsf(wfus2[i]);
    red[tid] = s1 / (float)(FUSD * AA * FUSD) + s2 / (float)(NCLSD * AA * NCLSD);
    __syncthreads();
    for (int o = 128; o > 0; o >>= 1) {
        if (tid < o) red[tid] += red[tid + o];
        __syncthreads();
    }
    if (tid == 0 && out_size > NN * NCLSD) out[NN * NCLSD] = red[0];
}

// ---------------- host launcher ----------------
extern "C" void kernel_launch(void* const* d_in, const int* in_sizes, int n_in,
                              void* d_out, int out_size) {
    const float* x     = (const float*)d_in[0];
    const int*   adj   = (const int*)d_in[1];
    const float* W1    = (const float*)d_in[2];
    const float* a1    = (const float*)d_in[3];
    const float* W2    = (const float*)d_in[4];
    const float* a2    = (const float*)d_in[5];
    const float* wint1 = (const float*)d_in[6];
    const float* bint1 = (const float*)d_in[7];
    const float* wfus1 = (const float*)d_in[8];
    const float* bfus1 = (const float*)d_in[9];
    const float* wint2 = (const float*)d_in[10];
    const float* bint2 = (const float*)d_in[11];
    const float* wfus2 = (const float*)d_in[12];
    const float* bfus2 = (const float*)d_in[13];
    float* out = (float*)d_out;

    float *pWh1, *pgat1, *pWh2, *pgat2;
    float *pf1, *pf2, *pea, *peb, *pE1, *pE2;
    float *ph1p, *pout1, *ph2p, *plogits;
    float *pwint1T, *pwfus1T, *pwint2T, *pwfus2T;
    unsigned* pbits;
    cudaGetSymbolAddress((void**)&pWh1, g_Wh1);
    cudaGetSymbolAddress((void**)&pgat1, g_gat1);
    cudaGetSymbolAddress((void**)&pWh2, g_Wh2);
    cudaGetSymbolAddress((void**)&pgat2, g_gat2);
    cudaGetSymbolAddress((void**)&pf1, g_f1);
    cudaGetSymbolAddress((void**)&pf2, g_f2);
    cudaGetSymbolAddress((void**)&pea, g_ea);
    cudaGetSymbolAddress((void**)&peb, g_eb);
    cudaGetSymbolAddress((void**)&pE1, g_E1);
    cudaGetSymbolAddress((void**)&pE2, g_E2);
    cudaGetSymbolAddress((void**)&pbits, g_bits);
    cudaGetSymbolAddress((void**)&ph1p, g_h1p);
    cudaGetSymbolAddress((void**)&pout1, g_out1);
    cudaGetSymbolAddress((void**)&ph2p, g_h2p);
    cudaGetSymbolAddress((void**)&plogits, g_logits);
    cudaGetSymbolAddress((void**)&pwint1T, g_wint1T);
    cudaGetSymbolAddress((void**)&pwfus1T, g_wfus1T);
    cudaGetSymbolAddress((void**)&pwint2T, g_wint2T);
    cudaGetSymbolAddress((void**)&pwfus2T, g_wfus2T);

    int nblk = (NN + 63) / 64;   // 47

    // launch 0: stage 1 Wh1 = x @ W1  -> [A][N][H*64]
    gemm_mma_kernel<O1D><<<dim3(nblk, AA * HHD), 256>>>(
        x, W1, pWh1, nullptr, NN, NFEATD, NFEATD, O1D, HO1D,
        HHD, 0, 0, (long long)HHD * NFEATD * O1D, (long long)NFEATD * O1D,
        (long long)NN * HO1D, O1D, 0);

    // launch 1: attention factors for stage 1
    fprep_kernel<<<(AA * HHD * NN + 255) / 256, 256>>>(pWh1, a1, pf1, pf2, pea, peb, pE1, pE2, O1D, HO1D);

    // launch 2: adjacency bitmask (ballot, coalesced)
    {
        long long warps = (long long)AA * NN * WPR;
        int blocks = (int)((warps * 32 + 255) / 256);
        bitmask_kernel<<<blocks, 256>>>(adj);
    }

    // launch 3: att1 (positioned here so ncu's fixed-index capture lands on it)
    att_mma_kernel<O1D><<<dim3(nblk, AA * HHD), 256>>>(pWh1, pf1, pf2, pea, peb, pE1, pE2, pbits, pgat1);

    // launch 4: all weight transposes
    {
        int total = FUSD * HO1D + FUSD * AA * FUSD + NCLSD * HO2D + NCLSD * AA * NCLSD;
        transpose_all_kernel<<<(total + 255) / 256, 256>>>(wint1, wfus1, wint2, wfus2);
    }

    // interproj1: elu(gat1 @ wint1T + bint1) -> h1p[n][a*64+g]
    gemm_mma_kernel<FUSD><<<dim3(nblk, AA), 256>>>(
        pgat1, pwint1T, ph1p, bint1, NN, HO1D, HO1D, FUSD, AA * FUSD,
        1, (long long)NN * HO1D, 0, 0, 0, FUSD, 0, 1);

    // fusion1: out1 = h1p @ wfus1T + bfus1
    gemm_mma_kernel<FUSD><<<dim3(nblk, 1), 256>>>(
        ph1p, pwfus1T, pout1, bfus1, NN, AA * FUSD, AA * FUSD, FUSD, FUSD,
        1, 0, 0, 0, 0, 0, 0, 0);

    // stage 2: Wh2 = out1 @ W2 -> [A][N][H*32]
    gemm_mma_kernel<O2D><<<dim3(nblk, AA * HHD), 256>>>(
        pout1, W2, pWh2, nullptr, NN, FUSD, FUSD, O2D, HO2D,
        HHD, 0, 0, (long long)HHD * FUSD * O2D, (long long)FUSD * O2D,
        (long long)NN * HO2D, O2D, 0);

    fprep_kernel<<<(AA * HHD * NN + 255) / 256, 256>>>(pWh2, a2, pf1, pf2, pea, peb, pE1, pE2, O2D, HO2D);

    att_mma_kernel<O2D><<<dim3(nblk, AA * HHD), 256>>>(pWh2, pf1, pf2, pea, peb, pE1, pE2, pbits, pgat2);

    // interproj2: elu(gat2 @ wint2T + bint2) -> h2p[n][a*8+g]  (tiny, SIMT)
    sgemm_kernel<<<dim3(nblk, 1, AA), 256>>>(
        pgat2, pwint2T, ph2p, bint2, NN, HO2D, NCLSD, HO2D, NCLSD, AA * NCLSD,
        1, (long long)NN * HO2D, 0, 0, 0, NCLSD, 0, 1);

    // fusion2: logits = h2p @ wfus2T + bfus2  (tiny, SIMT)
    sgemm_kernel<<<dim3(nblk, 1, 1), 256>>>(
        ph2p, pwfus2T, plogits, bfus2, NN, AA * NCLSD, NCLSD,
        AA * NCLSD, NCLSD, NCLSD,
        1, 0, 0, 0, 0, 0, 0, 0);

    lsm_kernel<<<(NN + 255) / 256, 256>>>(out, out_size);
    l1_kernel<<<1, 256>>>(wfus1, wfus2, out, out_size);
}

// round 6
// speedup vs baseline: 1.8661x; 1.0728x over previous
#include <cuda_runtime.h>
#include <math.h>
#include <stdint.h>

#define NN 3000
#define NFEATD 512
#define AA 2
#define HHD 4
#define O1D 64
#define O2D 32
#define HO1D 256
#define HO2D 128
#define LDW1 512          // flattened Wh1/gat1 row width = AA*HHD*O1D
#define LDW2 256          // flattened Wh2/gat2 row width
#define FUSD 64
#define NCLSD 8
#define WPR 94
#define NTILES 94
#define ALPHAF 0.2f

// ---------------- scratch ----------------
__device__ float g_Wh1[NN*LDW1];        // [n][a*256+h*64+o]
__device__ float g_gat1[NN*LDW1];
__device__ float g_Wh2[NN*LDW2];        // [n][a*128+h*32+o]
__device__ float g_gat2[NN*LDW2];
__device__ float g_f1[AA*HHD*NN], g_ea[AA*HHD*NN], g_eb[AA*HHD*NN];
__device__ float4 g_mfac4[AA*HHD*NN];   // (f2, exp(f2), exp(a*f2), 0)
__device__ unsigned g_bits[AA*WPR*NN];  // [a][mt][n]
__device__ float g_h1p[NN*AA*FUSD];
__device__ float g_out1[NN*FUSD];
__device__ float g_h2p[NN*AA*NCLSD];
__device__ float g_logits[NN*NCLSD];
__device__ float g_wint1T[HO1D*FUSD];
__device__ float g_wfus1T[AA*FUSD*FUSD];
__device__ float g_wint2T[HO2D*NCLSD];
__device__ float g_wfus2T[AA*NCLSD*NCLSD];

// ---------------- tf32 mma helpers ----------------
__device__ __forceinline__ void mma_tf32(float* c, uint32_t a0, uint32_t a1,
                                         uint32_t a2, uint32_t a3,
                                         uint32_t b0, uint32_t b1) {
    asm volatile(
        "mma.sync.aligned.m16n8k8.row.col.f32.tf32.tf32.f32 "
        "{%0,%1,%2,%3}, {%4,%5,%6,%7}, {%8,%9}, {%0,%1,%2,%3};\n"
        : "+f"(c[0]), "+f"(c[1]), "+f"(c[2]), "+f"(c[3])
        : "r"(a0), "r"(a1), "r"(a2), "r"(a3), "r"(b0), "r"(b1));
}
__device__ __forceinline__ float cvt_tf32(float v) {
    uint32_t r;
    asm("cvt.rna.tf32.f32 %0, %1;" : "=r"(r) : "f"(v));
    return __uint_as_float(r);
}

// ---------------- merged weight transposes ----------------
__global__ void transpose_all_kernel(const float* __restrict__ wint1,
                                     const float* __restrict__ wfus1,
                                     const float* __restrict__ wint2,
                                     const float* __restrict__ wfus2) {
    const int S1 = FUSD * HO1D;
    const int S2 = FUSD * AA * FUSD;
    const int S3 = NCLSD * HO2D;
    const int S4 = NCLSD * AA * NCLSD;
    int t = blockIdx.x * blockDim.x + threadIdx.x;
    if (t < S1) {
        int r = t / HO1D, c = t % HO1D;
        g_wint1T[c * FUSD + r] = wint1[t];
    } else if (t < S1 + S2) {
        int e = t - S1;
        int r = e / (AA * FUSD), c = e % (AA * FUSD);
        g_wfus1T[c * FUSD + r] = wfus1[e];
    } else if (t < S1 + S2 + S3) {
        int e = t - S1 - S2;
        int r = e / HO2D, c = e % HO2D;
        g_wint2T[c * NCLSD + r] = wint2[e];
    } else if (t < S1 + S2 + S3 + S4) {
        int e = t - S1 - S2 - S3;
        int r = e / (AA * NCLSD), c = e % (AA * NCLSD);
        g_wfus2T[c * NCLSD + r] = wfus2[e];
    }
}

// ---------------- adjacency -> bitmask via ballot ----------------
__global__ void bitmask_kernel(const int* __restrict__ adj) {
    int gw = (blockIdx.x * blockDim.x + threadIdx.x) >> 5;
    int lane = threadIdx.x & 31;
    if (gw >= AA * NN * WPR) return;
    int a = gw / (NN * WPR);
    int rem = gw % (NN * WPR);
    int n = rem / WPR;
    int mt = rem % WPR;
    int m = mt * 32 + lane;
    int v = 0;
    if (m < NN) v = adj[(size_t)(a * NN + n) * NN + m] > 0;
    unsigned word = __ballot_sync(0xffffffffu, v);
    if (lane == 0) g_bits[(size_t)(a * WPR + mt) * NN + n] = word;
}

// ---------------- attention factor precompute (flattened Wh) ----------------
__global__ void fprep_kernel(const float* __restrict__ Wh, const float* __restrict__ avec,
                             int O, int ldw) {
    int t = blockIdx.x * blockDim.x + threadIdx.x;
    if (t >= AA * HHD * NN) return;
    int ah = t / NN, n = t % NN;
    int a = ah / HHD, h = ah % HHD;
    const float* wr = Wh + (size_t)n * ldw + (a * HHD + h) * O;
    const float* av = avec + ah * 2 * O;
    float f1 = 0.f, f2 = 0.f;
    for (int o = 0; o < O; o++) {
        float w = wr[o];
        f1 += w * av[o];
        f2 += w * av[O + o];
    }
    g_f1[t] = f1;
    g_ea[t] = expf(f1);
    g_eb[t] = expf(ALPHAF * f1);
    g_mfac4[t] = make_float4(f2, expf(f2), expf(ALPHAF * f2), 0.f);
}

// ---------------- generic tf32 MMA GEMM (batched, bias, elu) ----------------
template <int O>
__global__ void gemm_mma_kernel(const float* __restrict__ A, const float* __restrict__ B,
                                float* __restrict__ C, const float* __restrict__ bias,
                                int M, int K, int lda, int ldb, int ldc,
                                int Hz, long long sAa, long long sAh,
                                long long sBa, long long sBh,
                                long long sCa, int cOffH, int act) {
    constexpr int BS = O + 8;
    constexpr int NT = O / 16;
    int z = blockIdx.y;
    int za = z / Hz, zh = z - za * Hz;
    A += za * sAa + zh * sAh;
    B += za * sBa + zh * sBh;
    C += za * sCa + (long long)zh * cOffH;

    __shared__ float As[64][36];
    __shared__ float Bs[32][BS];

    int tid = threadIdx.x, w = tid >> 5, lane = tid & 31;
    int rg = w >> 1, cg = w & 1;
    int g = lane >> 2, t4 = lane & 3;
    int m0 = blockIdx.x * 64;

    float acc[NT][4];
#pragma unroll
    for (int i = 0; i < NT; i++)
#pragma unroll
        for (int j = 0; j < 4; j++) acc[i][j] = 0.f;

    for (int k0 = 0; k0 < K; k0 += 32) {
#pragma unroll
        for (int i = 0; i < 8; i++) {
            int e = tid + i * 256;
            int r = e >> 5, k = e & 31;
            int m = m0 + r;
            float v = (m < M) ? A[(size_t)m * lda + k0 + k] : 0.f;
            As[r][k] = cvt_tf32(v);
        }
#pragma unroll
        for (int i = 0; i < (32 * O) / 256; i++) {
            int e = tid + i * 256;
            int k, c;
            if (O == 64) { k = e >> 6; c = e & 63; } else { k = e >> 5; c = e & 31; }
            Bs[k][c] = cvt_tf32(B[(size_t)(k0 + k) * ldb + c]);
        }
        __syncthreads();
#pragma unroll
        for (int kk = 0; kk < 4; kk++) {
            int kb = kk * 8;
            int ar = rg * 16 + g;
            uint32_t a0 = __float_as_uint(As[ar][kb + t4]);
            uint32_t a1 = __float_as_uint(As[ar + 8][kb + t4]);
            uint32_t a2 = __float_as_uint(As[ar][kb + t4 + 4]);
            uint32_t a3 = __float_as_uint(As[ar + 8][kb + t4 + 4]);
#pragma unroll
            for (int nt = 0; nt < NT; nt++) {
                int col = cg * (O / 2) + nt * 8 + g;
                uint32_t b0 = __float_as_uint(Bs[kb + t4][col]);
                uint32_t b1 = __float_as_uint(Bs[kb + t4 + 4][col]);
                mma_tf32(acc[nt], a0, a1, a2, a3, b0, b1);
            }
        }
        __syncthreads();
    }
#pragma unroll
    for (int half = 0; half < 2; half++) {
        int r = rg * 16 + g + half * 8;
        int gr = m0 + r;
        if (gr < M) {
#pragma unroll
            for (int nt = 0; nt < NT; nt++) {
                int col = cg * (O / 2) + nt * 8 + 2 * t4;
                float v0 = acc[nt][half * 2 + 0];
                float v1 = acc[nt][half * 2 + 1];
                if (bias) { v0 += bias[col]; v1 += bias[col + 1]; }
                if (act == 1) {
                    v0 = v0 > 0.f ? v0 : (expf(v0) - 1.f);
                    v1 = v1 > 0.f ? v1 : (expf(v1) - 1.f);
                }
                *(float2*)&C[(size_t)gr * ldc + col] = make_float2(v0, v1);
            }
        }
    }
}

// ---------------- attention weight (register A-fragment) ----------------
__device__ __forceinline__ float attw(unsigned word, int mb, float f1n, float ean,
                                      float ebn, const float4 q) {
    float wv = 0.f;
    if ((word >> mb) & 1u) {
        float s = f1n + q.x;
        wv = (s > 0.f) ? ean * q.y : ebn * q.z;
    }
    return cvt_tf32(wv);
}

// ---------------- fused masked-softmax attention aggregate ----------------
// M-tile 128, register-built A-fragments, double-buffered Wh/mfac/bit staging.
// out[n,:] = elu( (sum_m w(n,m)*Wh[m,:]) / (sum_m w(n,m)) )
template <int O>
__global__ void att_mma_kernel(const float* __restrict__ Wh,
                               const float* __restrict__ f1v, const float* __restrict__ eav,
                               const float* __restrict__ ebv,
                               const float4* __restrict__ mfac,
                               const unsigned* __restrict__ bits,
                               float* __restrict__ outp) {
    constexpr int LDW = AA * HHD * O;
    constexpr int BS = O + 8;
    constexpr int NT = O / 8;     // n8 subtiles per warp (warp covers full O)
    int z = blockIdx.y;
    int a = z >> 2, h = z & 3;
    int n0 = blockIdx.x * 128;
    const float* whb = Wh + (a * HHD + h) * O;     // + m*LDW
    const float4* mfb = mfac + (size_t)z * NN;
    const unsigned* bb = bits + (size_t)a * WPR * NN;

    __shared__ float Whs[2][32][BS];
    __shared__ float4 mfs[2][32];
    __shared__ unsigned wds[2][128];

    int tid = threadIdx.x, w = tid >> 5, lane = tid & 31;
    int g = lane >> 2, t4 = lane & 3;
    int r0 = w * 16 + g, r1 = r0 + 8;
    int gr0 = n0 + r0, gr1 = n0 + r1;

    // n-side factors: fixed per thread for whole kernel
    float f10 = 0.f, ea0 = 0.f, eb0 = 0.f, f11 = 0.f, ea1 = 0.f, eb1 = 0.f;
    if (gr0 < NN) { f10 = f1v[(size_t)z*NN+gr0]; ea0 = eav[(size_t)z*NN+gr0]; eb0 = ebv[(size_t)z*NN+gr0]; }
    if (gr1 < NN) { f11 = f1v[(size_t)z*NN+gr1]; ea1 = eav[(size_t)z*NN+gr1]; eb1 = ebv[(size_t)z*NN+gr1]; }

    float acc[NT][4];
#pragma unroll
    for (int i = 0; i < NT; i++)
#pragma unroll
        for (int j = 0; j < 4; j++) acc[i][j] = 0.f;
    float zp0 = 0.f, zp1 = 0.f;

    auto build = [&](int mt, int buf) {
        // Wh tile 32 x O (flattened layout, row stride LDW)
#pragma unroll
        for (int i = 0; i < (32 * O) / 256; i++) {
            int e = tid + i * 256;
            int lm, o;
            if (O == 64) { lm = e >> 6; o = e & 63; } else { lm = e >> 5; o = e & 31; }
            int m = mt * 32 + lm;
            float v = (m < NN) ? whb[(size_t)m * LDW + o] : 0.f;
            Whs[buf][lm][o] = cvt_tf32(v);
        }
        if (tid < 32) {
            int m = mt * 32 + tid;
            mfs[buf][tid] = (m < NN) ? mfb[m] : make_float4(0.f, 0.f, 0.f, 0.f);
        }
        if (tid < 128) {
            int rr = n0 + tid;
            wds[buf][tid] = (rr < NN) ? bb[(size_t)mt * NN + rr] : 0u;
        }
    };

    build(0, 0);
    __syncthreads();

    for (int mt = 0; mt < NTILES; mt++) {
        int cur = mt & 1;
        if (mt + 1 < NTILES) build(mt + 1, cur ^ 1);
        unsigned w0 = wds[cur][r0], w1 = wds[cur][r1];
#pragma unroll
        for (int kk = 0; kk < 4; kk++) {
            int kb = kk * 8;
            float4 q0 = mfs[cur][kb + t4];
            float4 q1 = mfs[cur][kb + t4 + 4];
            float av0 = attw(w0, kb + t4, f10, ea0, eb0, q0);
            float av1 = attw(w1, kb + t4, f11, ea1, eb1, q0);
            float av2 = attw(w0, kb + t4 + 4, f10, ea0, eb0, q1);
            float av3 = attw(w1, kb + t4 + 4, f11, ea1, eb1, q1);
            zp0 += av0 + av2;
            zp1 += av1 + av3;
            uint32_t a0 = __float_as_uint(av0), a1 = __float_as_uint(av1);
            uint32_t a2 = __float_as_uint(av2), a3 = __float_as_uint(av3);
#pragma unroll
            for (int nt = 0; nt < NT; nt++) {
                int col = nt * 8 + g;
                uint32_t b0 = __float_as_uint(Whs[cur][kb + t4][col]);
                uint32_t b1 = __float_as_uint(Whs[cur][kb + t4 + 4][col]);
                mma_tf32(acc[nt], a0, a1, a2, a3, b0, b1);
            }
        }
        __syncthreads();
    }

    // Z reduce over quad (t4) via butterfly; all lanes get full sum
#pragma unroll
    for (int d = 1; d < 4; d <<= 1) {
        zp0 += __shfl_xor_sync(0xffffffffu, zp0, d);
        zp1 += __shfl_xor_sync(0xffffffffu, zp1, d);
    }
    float inv0 = (zp0 > 0.f) ? 1.f / zp0 : 0.f;
    float inv1 = (zp1 > 0.f) ? 1.f / zp1 : 0.f;

    // epilogue: normalize + elu + store (flattened layout)
#pragma unroll
    for (int nt = 0; nt < NT; nt++) {
        int col = nt * 8 + 2 * t4;
        if (gr0 < NN) {
            float v0 = acc[nt][0] * inv0;
            float v1 = acc[nt][1] * inv0;
            v0 = v0 > 0.f ? v0 : (expf(v0) - 1.f);
            v1 = v1 > 0.f ? v1 : (expf(v1) - 1.f);
            *(float2*)&outp[(size_t)gr0 * LDW + (a * HHD + h) * O + col] = make_float2(v0, v1);
        }
        if (gr1 < NN) {
            float v2 = acc[nt][2] * inv1;
            float v3 = acc[nt][3] * inv1;
            v2 = v2 > 0.f ? v2 : (expf(v2) - 1.f);
            v3 = v3 > 0.f ? v3 : (expf(v3) - 1.f);
            *(float2*)&outp[(size_t)gr1 * LDW + (a * HHD + h) * O + col] = make_float2(v2, v3);
        }
    }
}

// ---------------- SIMT SGEMM for tiny tail layers ----------------
__global__ void sgemm_kernel(const float* __restrict__ A, const float* __restrict__ B,
                             float* __restrict__ C, const float* __restrict__ bias,
                             int M, int K, int Nc, int lda, int ldb, int ldc,
                             int Hz, long long sAa, long long sAh,
                             long long sBa, long long sBh,
                             long long sCa, long long sCh, int act) {
    int z = blockIdx.z;
    int za = z / Hz, zh = z % Hz;
    A += za * sAa + zh * sAh;
    B += za * sBa + zh * sBh;
    C += za * sCa + zh * sCh;
    __shared__ float As[16][65];
    __shared__ __align__(16) float Bs[16][64];
    int tid = threadIdx.x;
    int tx = tid & 15, ty = tid >> 4;
    int m0 = blockIdx.x * 64, n0 = blockIdx.y * 64;
    float acc[4][4] = {};
    for (int k0 = 0; k0 < K; k0 += 16) {
        __syncthreads();
#pragma unroll
        for (int i = 0; i < 4; i++) {
            int e = tid + i * 256;
            int k = e & 15, m = e >> 4;
            As[k][m] = (m0 + m < M) ? A[(size_t)(m0 + m) * lda + k0 + k] : 0.f;
        }
#pragma unroll
        for (int i = 0; i < 4; i++) {
            int e = tid + i * 256;
            int n = e & 63, k = e >> 6;
            Bs[k][n] = (n0 + n < Nc) ? B[(size_t)(k0 + k) * ldb + n0 + n] : 0.f;
        }
        __syncthreads();
#pragma unroll
        for (int k = 0; k < 16; k++) {
            float4 bv = *reinterpret_cast<const float4*>(&Bs[k][tx * 4]);
            float b4[4] = {bv.x, bv.y, bv.z, bv.w};
#pragma unroll
            for (int i = 0; i < 4; i++) {
                float av = As[k][ty * 4 + i];
#pragma unroll
                for (int j = 0; j < 4; j++) acc[i][j] += av * b4[j];
            }
        }
    }
#pragma unroll
    for (int i = 0; i < 4; i++) {
        int r = m0 + ty * 4 + i;
        if (r >= M) continue;
#pragma unroll
        for (int j = 0; j < 4; j++) {
            int c = n0 + tx * 4 + j;
            if (c >= Nc) continue;
            float v = acc[i][j];
            if (bias) v += bias[c];
            if (act == 1) v = v > 0.f ? v : (expf(v) - 1.f);
            C[(size_t)r * ldc + c] = v;
        }
    }
}

// ---------------- log_softmax + L1 scalar ----------------
__global__ void lsm_kernel(float* __restrict__ out, int out_size) {
    int n = blockIdx.x * blockDim.x + threadIdx.x;
    if (n >= NN) return;
    float v[NCLSD];
    float mx = -1e30f;
#pragma unroll
    for (int c = 0; c < NCLSD; c++) { v[c] = g_logits[n * NCLSD + c]; mx = fmaxf(mx, v[c]); }
    float s = 0.f;
#pragma unroll
    for (int c = 0; c < NCLSD; c++) s += expf(v[c] - mx);
    float l = logf(s) + mx;
#pragma unroll
    for (int c = 0; c < NCLSD; c++) {
        int idx = n * NCLSD + c;
        if (idx < out_size) out[idx] = v[c] - l;
    }
}

__global__ void l1_kernel(const float* __restrict__ wfus1, const float* __restrict__ wfus2,
                          float* __restrict__ out, int out_size) {
    __shared__ float red[256];
    int tid = threadIdx.x;
    float s1 = 0.f, s2 = 0.f;
    for (int i = tid; i < FUSD * AA * FUSD; i += 256) s1 += fabsf(wfus1[i]);
    for (int i = tid; i < NCLSD * AA * NCLSD; i += 256) s2 += fabsf(wfus2[i]);
    red[tid] = s1 / (float)(FUSD * AA * FUSD) + s2 / (float)(NCLSD * AA * NCLSD);
    __syncthreads();
    for (int o = 128; o > 0; o >>= 1) {
        if (tid < o) red[tid] += red[tid + o];
        __syncthreads();
    }
    if (tid == 0 && out_size > NN * NCLSD) out[NN * NCLSD] = red[0];
}

// ---------------- host launcher ----------------
extern "C" void kernel_launch(void* const* d_in, const int* in_sizes, int n_in,
                              void* d_out, int out_size) {
    const float* x     = (const float*)d_in[0];
    const int*   adj   = (const int*)d_in[1];
    const float* W1    = (const float*)d_in[2];
    const float* a1    = (const float*)d_in[3];
    const float* W2    = (const float*)d_in[4];
    const float* a2    = (const float*)d_in[5];
    const float* wint1 = (const float*)d_in[6];
    const float* bint1 = (const float*)d_in[7];
    const float* wfus1 = (const float*)d_in[8];
    const float* bfus1 = (const float*)d_in[9];
    const float* wint2 = (const float*)d_in[10];
    const float* bint2 = (const float*)d_in[11];
    const float* wfus2 = (const float*)d_in[12];
    const float* bfus2 = (const float*)d_in[13];
    float* out = (float*)d_out;

    float *pWh1, *pgat1, *pWh2, *pgat2;
    float *pf1, *pea, *peb;
    float4* pmfac;
    float *ph1p, *pout1, *ph2p, *plogits;
    float *pwint1T, *pwfus1T, *pwint2T, *pwfus2T;
    unsigned* pbits;
    cudaGetSymbolAddress((void**)&pWh1, g_Wh1);
    cudaGetSymbolAddress((void**)&pgat1, g_gat1);
    cudaGetSymbolAddress((void**)&pWh2, g_Wh2);
    cudaGetSymbolAddress((void**)&pgat2, g_gat2);
    cudaGetSymbolAddress((void**)&pf1, g_f1);
    cudaGetSymbolAddress((void**)&pea, g_ea);
    cudaGetSymbolAddress((void**)&peb, g_eb);
    cudaGetSymbolAddress((void**)&pmfac, g_mfac4);
    cudaGetSymbolAddress((void**)&pbits, g_bits);
    cudaGetSymbolAddress((void**)&ph1p, g_h1p);
    cudaGetSymbolAddress((void**)&pout1, g_out1);
    cudaGetSymbolAddress((void**)&ph2p, g_h2p);
    cudaGetSymbolAddress((void**)&plogits, g_logits);
    cudaGetSymbolAddress((void**)&pwint1T, g_wint1T);
    cudaGetSymbolAddress((void**)&pwfus1T, g_wfus1T);
    cudaGetSymbolAddress((void**)&pwint2T, g_wint2T);
    cudaGetSymbolAddress((void**)&pwfus2T, g_wfus2T);

    int nblk64 = (NN + 63) / 64;     // 47
    int nblk128 = (NN + 127) / 128;  // 24

    // launch 0: stage 1 Wh1 = x @ W1 -> flattened [n][a*256+h*64+o]
    gemm_mma_kernel<O1D><<<dim3(nblk64, AA * HHD), 256>>>(
        x, W1, pWh1, nullptr, NN, NFEATD, NFEATD, O1D, LDW1,
        HHD, 0, 0, (long long)HHD * NFEATD * O1D, (long long)NFEATD * O1D,
        HO1D, O1D, 0);

    // launch 1: attention factors for stage 1
    fprep_kernel<<<(AA * HHD * NN + 255) / 256, 256>>>(pWh1, a1, O1D, LDW1);

    // launch 2: adjacency bitmask
    {
        long long warps = (long long)AA * NN * WPR;
        int blocks = (int)((warps * 32 + 255) / 256);
        bitmask_kernel<<<blocks, 256>>>(adj);
    }

    // launch 3: att1 (keep at this index for ncu capture)
    att_mma_kernel<O1D><<<dim3(nblk128, AA * HHD), 256>>>(
        pWh1, pf1, pea, peb, pmfac, pbits, pgat1);

    // launch 4: all weight transposes
    {
        int total = FUSD * HO1D + FUSD * AA * FUSD + NCLSD * HO2D + NCLSD * AA * NCLSD;
        transpose_all_kernel<<<(total + 255) / 256, 256>>>(wint1, wfus1, wint2, wfus2);
    }

    // interproj1: elu(gat1[:, a*256:(a+1)*256] @ wint1T + bint1) -> h1p[n][a*64+g]
    gemm_mma_kernel<FUSD><<<dim3(nblk64, AA), 256>>>(
        pgat1, pwint1T, ph1p, bint1, NN, HO1D, LDW1, FUSD, AA * FUSD,
        1, HO1D, 0, 0, 0, FUSD, 0, 1);

    // fusion1: out1 = h1p @ wfus1T + bfus1
    gemm_mma_kernel<FUSD><<<dim3(nblk64, 1), 256>>>(
        ph1p, pwfus1T, pout1, bfus1, NN, AA * FUSD, AA * FUSD, FUSD, FUSD,
        1, 0, 0, 0, 0, 0, 0, 0);

    // stage 2: Wh2 = out1 @ W2 -> flattened [n][a*128+h*32+o]
    gemm_mma_kernel<O2D><<<dim3(nblk64, AA * HHD), 256>>>(
        pout1, W2, pWh2, nullptr, NN, FUSD, FUSD, O2D, LDW2,
        HHD, 0, 0, (long long)HHD * FUSD * O2D, (long long)FUSD * O2D,
        HO2D, O2D, 0);

    fprep_kernel<<<(AA * HHD * NN + 255) / 256, 256>>>(pWh2, a2, O2D, LDW2);

    att_mma_kernel<O2D><<<dim3(nblk128, AA * HHD), 256>>>(
        pWh2, pf1, pea, peb, pmfac, pbits, pgat2);

    // interproj2: elu(gat2[:, a*128:(a+1)*128] @ wint2T + bint2) -> h2p[n][a*8+c]
    sgemm_kernel<<<dim3(nblk64, 1, AA), 256>>>(
        pgat2, pwint2T, ph2p, bint2, NN, HO2D, NCLSD, LDW2, NCLSD, AA * NCLSD,
        1, HO2D, 0, 0, 0, NCLSD, 0, 1);

    // fusion2: logits = h2p @ wfus2T + bfus2
    sgemm_kernel<<<dim3(nblk64, 1, 1), 256>>>(
        ph2p, pwfus2T, plogits, bfus2, NN, AA * NCLSD, NCLSD,
        AA * NCLSD, NCLSD, NCLSD,
        1, 0, 0, 0, 0, 0, 0, 0);

    lsm_kernel<<<(NN + 255) / 256, 256>>>(out, out_size);
    l1_kernel<<<1, 256>>>(wfus1, wfus2, out, out_size);
}

// round 7
// speedup vs baseline: 1.9749x; 1.0583x over previous
#include <cuda_runtime.h>
#include <math.h>
#include <stdint.h>

#define NN 3000
#define NFEATD 512
#define AA 2
#define HHD 4
#define O1D 64
#define O2D 32
#define HO1D 256
#define HO2D 128
#define LDW1 512          // flattened Wh1/gat1 row width = AA*HHD*O1D
#define LDW2 256          // flattened Wh2/gat2 row width
#define FUSD 64
#define NCLSD 8
#define WPR 94
#define NTILES 94
#define ALPHAF 0.2f

// ---------------- scratch ----------------
__device__ float g_Wh1[NN*LDW1];        // [n][a*256+h*64+o]
__device__ float g_gat1[NN*LDW1];
__device__ float g_Wh2[NN*LDW2];        // [n][a*128+h*32+o]
__device__ float g_gat2[NN*LDW2];
__device__ float g_f1[AA*HHD*NN], g_ea[AA*HHD*NN], g_eb[AA*HHD*NN];
__device__ float4 g_mfac4[AA*HHD*NN];   // (f2, exp(f2), exp(a*f2), 0)
__device__ unsigned g_bits[AA*WPR*NN];  // [a][mt][n]
__device__ float g_h1p[NN*AA*FUSD];
__device__ float g_out1[NN*FUSD];
__device__ float g_h2p[NN*AA*NCLSD];
__device__ float g_logits[NN*NCLSD];
__device__ float g_wint1T[HO1D*FUSD];
__device__ float g_wfus1T[AA*FUSD*FUSD];
__device__ float g_wint2T[HO2D*NCLSD];
__device__ float g_wfus2T[AA*NCLSD*NCLSD];

// ---------------- tf32 mma helpers ----------------
__device__ __forceinline__ void mma_tf32(float* c, uint32_t a0, uint32_t a1,
                                         uint32_t a2, uint32_t a3,
                                         uint32_t b0, uint32_t b1) {
    asm volatile(
        "mma.sync.aligned.m16n8k8.row.col.f32.tf32.tf32.f32 "
        "{%0,%1,%2,%3}, {%4,%5,%6,%7}, {%8,%9}, {%0,%1,%2,%3};\n"
        : "+f"(c[0]), "+f"(c[1]), "+f"(c[2]), "+f"(c[3])
        : "r"(a0), "r"(a1), "r"(a2), "r"(a3), "r"(b0), "r"(b1));
}
__device__ __forceinline__ float cvt_tf32(float v) {
    uint32_t r;
    asm("cvt.rna.tf32.f32 %0, %1;" : "=r"(r) : "f"(v));
    return __uint_as_float(r);
}

// ---------------- merged weight transposes ----------------
__global__ void transpose_all_kernel(const float* __restrict__ wint1,
                                     const float* __restrict__ wfus1,
                                     const float* __restrict__ wint2,
                                     const float* __restrict__ wfus2) {
    const int S1 = FUSD * HO1D;
    const int S2 = FUSD * AA * FUSD;
    const int S3 = NCLSD * HO2D;
    const int S4 = NCLSD * AA * NCLSD;
    int t = blockIdx.x * blockDim.x + threadIdx.x;
    if (t < S1) {
        int r = t / HO1D, c = t % HO1D;
        g_wint1T[c * FUSD + r] = wint1[t];
    } else if (t < S1 + S2) {
        int e = t - S1;
        int r = e / (AA * FUSD), c = e % (AA * FUSD);
        g_wfus1T[c * FUSD + r] = wfus1[e];
    } else if (t < S1 + S2 + S3) {
        int e = t - S1 - S2;
        int r = e / HO2D, c = e % HO2D;
        g_wint2T[c * NCLSD + r] = wint2[e];
    } else if (t < S1 + S2 + S3 + S4) {
        int e = t - S1 - S2 - S3;
        int r = e / (AA * NCLSD), c = e % (AA * NCLSD);
        g_wfus2T[c * NCLSD + r] = wfus2[e];
    }
}

// ---------------- adjacency -> bitmask via ballot ----------------
__global__ void bitmask_kernel(const int* __restrict__ adj) {
    int gw = (blockIdx.x * blockDim.x + threadIdx.x) >> 5;
    int lane = threadIdx.x & 31;
    if (gw >= AA * NN * WPR) return;
    int a = gw / (NN * WPR);
    int rem = gw % (NN * WPR);
    int n = rem / WPR;
    int mt = rem % WPR;
    int m = mt * 32 + lane;
    int v = 0;
    if (m < NN) v = adj[(size_t)(a * NN + n) * NN + m] > 0;
    unsigned word = __ballot_sync(0xffffffffu, v);
    if (lane == 0) g_bits[(size_t)(a * WPR + mt) * NN + n] = word;
}

// ---------------- attention factor precompute (flattened Wh) ----------------
__global__ void fprep_kernel(const float* __restrict__ Wh, const float* __restrict__ avec,
                             int O, int ldw) {
    int t = blockIdx.x * blockDim.x + threadIdx.x;
    if (t >= AA * HHD * NN) return;
    int ah = t / NN, n = t % NN;
    int a = ah / HHD, h = ah % HHD;
    const float* wr = Wh + (size_t)n * ldw + (a * HHD + h) * O;
    const float* av = avec + ah * 2 * O;
    float f1 = 0.f, f2 = 0.f;
    for (int o = 0; o < O; o++) {
        float w = wr[o];
        f1 += w * av[o];
        f2 += w * av[O + o];
    }
    g_f1[t] = f1;
    g_ea[t] = expf(f1);
    g_eb[t] = expf(ALPHAF * f1);
    g_mfac4[t] = make_float4(f2, expf(f2), expf(ALPHAF * f2), 0.f);
}

// ---------------- generic tf32 MMA GEMM (batched, bias, elu) ----------------
template <int O>
__global__ void gemm_mma_kernel(const float* __restrict__ A, const float* __restrict__ B,
                                float* __restrict__ C, const float* __restrict__ bias,
                                int M, int K, int lda, int ldb, int ldc,
                                int Hz, long long sAa, long long sAh,
                                long long sBa, long long sBh,
                                long long sCa, int cOffH, int act) {
    constexpr int BS = O + 8;
    constexpr int NT = O / 16;
    int z = blockIdx.y;
    int za = z / Hz, zh = z - za * Hz;
    A += za * sAa + zh * sAh;
    B += za * sBa + zh * sBh;
    C += za * sCa + (long long)zh * cOffH;

    __shared__ float As[64][36];
    __shared__ float Bs[32][BS];

    int tid = threadIdx.x, w = tid >> 5, lane = tid & 31;
    int rg = w >> 1, cg = w & 1;
    int g = lane >> 2, t4 = lane & 3;
    int m0 = blockIdx.x * 64;

    float acc[NT][4];
#pragma unroll
    for (int i = 0; i < NT; i++)
#pragma unroll
        for (int j = 0; j < 4; j++) acc[i][j] = 0.f;

    for (int k0 = 0; k0 < K; k0 += 32) {
#pragma unroll
        for (int i = 0; i < 8; i++) {
            int e = tid + i * 256;
            int r = e >> 5, k = e & 31;
            int m = m0 + r;
            float v = (m < M) ? A[(size_t)m * lda + k0 + k] : 0.f;
            As[r][k] = cvt_tf32(v);
        }
#pragma unroll
        for (int i = 0; i < (32 * O) / 256; i++) {
            int e = tid + i * 256;
            int k, c;
            if (O == 64) { k = e >> 6; c = e & 63; } else { k = e >> 5; c = e & 31; }
            Bs[k][c] = cvt_tf32(B[(size_t)(k0 + k) * ldb + c]);
        }
        __syncthreads();
#pragma unroll
        for (int kk = 0; kk < 4; kk++) {
            int kb = kk * 8;
            int ar = rg * 16 + g;
            uint32_t a0 = __float_as_uint(As[ar][kb + t4]);
            uint32_t a1 = __float_as_uint(As[ar + 8][kb + t4]);
            uint32_t a2 = __float_as_uint(As[ar][kb + t4 + 4]);
            uint32_t a3 = __float_as_uint(As[ar + 8][kb + t4 + 4]);
#pragma unroll
            for (int nt = 0; nt < NT; nt++) {
                int col = cg * (O / 2) + nt * 8 + g;
                uint32_t b0 = __float_as_uint(Bs[kb + t4][col]);
                uint32_t b1 = __float_as_uint(Bs[kb + t4 + 4][col]);
                mma_tf32(acc[nt], a0, a1, a2, a3, b0, b1);
            }
        }
        __syncthreads();
    }
#pragma unroll
    for (int half = 0; half < 2; half++) {
        int r = rg * 16 + g + half * 8;
        int gr = m0 + r;
        if (gr < M) {
#pragma unroll
            for (int nt = 0; nt < NT; nt++) {
                int col = cg * (O / 2) + nt * 8 + 2 * t4;
                float v0 = acc[nt][half * 2 + 0];
                float v1 = acc[nt][half * 2 + 1];
                if (bias) { v0 += bias[col]; v1 += bias[col + 1]; }
                if (act == 1) {
                    v0 = v0 > 0.f ? v0 : (expf(v0) - 1.f);
                    v1 = v1 > 0.f ? v1 : (expf(v1) - 1.f);
                }
                *(float2*)&C[(size_t)gr * ldc + col] = make_float2(v0, v1);
            }
        }
    }
}

// ---------------- attention weight (register A-fragment) ----------------
__device__ __forceinline__ float attw(unsigned word, int mb, float f1n, float ean,
                                      float ebn, const float4 q) {
    float wv = 0.f;
    if ((word >> mb) & 1u) {
        float s = f1n + q.x;
        wv = (s > 0.f) ? ean * q.y : ebn * q.z;
    }
    return cvt_tf32(wv);
}

// ---------------- fused masked-softmax attention aggregate ----------------
// 64-row tiles, 8 warps = 4 rowgroups x 2 colgroups; register-built A fragments
// (duplicated across colgroups — ALU is cheap); double-buffered staging.
// out[n,:] = elu( (sum_m w(n,m)*Wh[m,:]) / (sum_m w(n,m)) )
template <int O>
__global__ void att_mma_kernel(const float* __restrict__ Wh,
                               const float* __restrict__ f1v, const float* __restrict__ eav,
                               const float* __restrict__ ebv,
                               const float4* __restrict__ mfac,
                               const unsigned* __restrict__ bits,
                               float* __restrict__ outp) {
    constexpr int LDW = AA * HHD * O;
    constexpr int BS = O + 8;
    constexpr int NT = O / 16;    // n8 subtiles per warp (warp covers O/2 cols)
    int z = blockIdx.y;
    int a = z >> 2, h = z & 3;
    int n0 = blockIdx.x * 64;
    const float* whb = Wh + (a * HHD + h) * O;     // + m*LDW
    const float4* mfb = mfac + (size_t)z * NN;
    const unsigned* bb = bits + (size_t)a * WPR * NN;

    __shared__ float Whs[2][32][BS];
    __shared__ float4 mfs[2][32];
    __shared__ unsigned wds[2][64];

    int tid = threadIdx.x, w = tid >> 5, lane = tid & 31;
    int rg = w >> 1, cg = w & 1;
    int g = lane >> 2, t4 = lane & 3;
    int r0 = rg * 16 + g, r1 = r0 + 8;
    int gr0 = n0 + r0, gr1 = n0 + r1;

    // n-side factors: fixed per thread for whole kernel
    float f10 = 0.f, ea0 = 0.f, eb0 = 0.f, f11 = 0.f, ea1 = 0.f, eb1 = 0.f;
    if (gr0 < NN) { f10 = f1v[(size_t)z*NN+gr0]; ea0 = eav[(size_t)z*NN+gr0]; eb0 = ebv[(size_t)z*NN+gr0]; }
    if (gr1 < NN) { f11 = f1v[(size_t)z*NN+gr1]; ea1 = eav[(size_t)z*NN+gr1]; eb1 = ebv[(size_t)z*NN+gr1]; }

    float acc[NT][4];
#pragma unroll
    for (int i = 0; i < NT; i++)
#pragma unroll
        for (int j = 0; j < 4; j++) acc[i][j] = 0.f;
    float zp0 = 0.f, zp1 = 0.f;

    auto build = [&](int mt, int buf) {
        // Wh tile 32 x O (flattened layout, row stride LDW)
#pragma unroll
        for (int i = 0; i < (32 * O) / 256; i++) {
            int e = tid + i * 256;
            int lm, o;
            if (O == 64) { lm = e >> 6; o = e & 63; } else { lm = e >> 5; o = e & 31; }
            int m = mt * 32 + lm;
            float v = (m < NN) ? whb[(size_t)m * LDW + o] : 0.f;
            Whs[buf][lm][o] = cvt_tf32(v);
        }
        if (tid < 32) {
            int m = mt * 32 + tid;
            mfs[buf][tid] = (m < NN) ? mfb[m] : make_float4(0.f, 0.f, 0.f, 0.f);
        } else if (tid >= 64 && tid < 128) {
            int rr = n0 + tid - 64;
            wds[buf][tid - 64] = (rr < NN) ? bb[(size_t)mt * NN + rr] : 0u;
        }
    };

    build(0, 0);
    __syncthreads();

    for (int mt = 0; mt < NTILES; mt++) {
        int cur = mt & 1;
        if (mt + 1 < NTILES) build(mt + 1, cur ^ 1);
        unsigned w0 = wds[cur][r0], w1 = wds[cur][r1];
#pragma unroll
        for (int kk = 0; kk < 4; kk++) {
            int kb = kk * 8;
            float4 q0 = mfs[cur][kb + t4];
            float4 q1 = mfs[cur][kb + t4 + 4];
            float av0 = attw(w0, kb + t4, f10, ea0, eb0, q0);
            float av1 = attw(w1, kb + t4, f11, ea1, eb1, q0);
            float av2 = attw(w0, kb + t4 + 4, f10, ea0, eb0, q1);
            float av3 = attw(w1, kb + t4 + 4, f11, ea1, eb1, q1);
            zp0 += av0 + av2;
            zp1 += av1 + av3;
            uint32_t a0 = __float_as_uint(av0), a1 = __float_as_uint(av1);
            uint32_t a2 = __float_as_uint(av2), a3 = __float_as_uint(av3);
#pragma unroll
            for (int nt = 0; nt < NT; nt++) {
                int col = cg * (O / 2) + nt * 8 + g;
                uint32_t b0 = __float_as_uint(Whs[cur][kb + t4][col]);
                uint32_t b1 = __float_as_uint(Whs[cur][kb + t4 + 4][col]);
                mma_tf32(acc[nt], a0, a1, a2, a3, b0, b1);
            }
        }
        __syncthreads();
    }

    // Z reduce over quad (t4) via butterfly; all lanes get full sum
#pragma unroll
    for (int d = 1; d < 4; d <<= 1) {
        zp0 += __shfl_xor_sync(0xffffffffu, zp0, d);
        zp1 += __shfl_xor_sync(0xffffffffu, zp1, d);
    }
    float inv0 = (zp0 > 0.f) ? 1.f / zp0 : 0.f;
    float inv1 = (zp1 > 0.f) ? 1.f / zp1 : 0.f;

    // epilogue: normalize + elu + store (flattened layout)
#pragma unroll
    for (int nt = 0; nt < NT; nt++) {
        int col = cg * (O / 2) + nt * 8 + 2 * t4;
        if (gr0 < NN) {
            float v0 = acc[nt][0] * inv0;
            float v1 = acc[nt][1] * inv0;
            v0 = v0 > 0.f ? v0 : (expf(v0) - 1.f);
            v1 = v1 > 0.f ? v1 : (expf(v1) - 1.f);
            *(float2*)&outp[(size_t)gr0 * LDW + (a * HHD + h) * O + col] = make_float2(v0, v1);
        }
        if (gr1 < NN) {
            float v2 = acc[nt][2] * inv1;
            float v3 = acc[nt][3] * inv1;
            v2 = v2 > 0.f ? v2 : (expf(v2) - 1.f);
            v3 = v3 > 0.f ? v3 : (expf(v3) - 1.f);
            *(float2*)&outp[(size_t)gr1 * LDW + (a * HHD + h) * O + col] = make_float2(v2, v3);
        }
    }
}

// ---------------- SIMT SGEMM for tiny tail layers ----------------
__global__ void sgemm_kernel(const float* __restrict__ A, const float* __restrict__ B,
                             float* __restrict__ C, const float* __restrict__ bias,
                             int M, int K, int Nc, int lda, int ldb, int ldc,
                             int Hz, long long sAa, long long sAh,
                             long long sBa, long long sBh,
                             long long sCa, long long sCh, int act) {
    int z = blockIdx.z;
    int za = z / Hz, zh = z % Hz;
    A += za * sAa + zh * sAh;
    B += za * sBa + zh * sBh;
    C += za * sCa + zh * sCh;
    __shared__ float As[16][65];
    __shared__ __align__(16) float Bs[16][64];
    int tid = threadIdx.x;
    int tx = tid & 15, ty = tid >> 4;
    int m0 = blockIdx.x * 64, n0 = blockIdx.y * 64;
    float acc[4][4] = {};
    for (int k0 = 0; k0 < K; k0 += 16) {
        __syncthreads();
#pragma unroll
        for (int i = 0; i < 4; i++) {
            int e = tid + i * 256;
            int k = e & 15, m = e >> 4;
            As[k][m] = (m0 + m < M) ? A[(size_t)(m0 + m) * lda + k0 + k] : 0.f;
        }
#pragma unroll
        for (int i = 0; i < 4; i++) {
            int e = tid + i * 256;
            int n = e & 63, k = e >> 6;
            Bs[k][n] = (n0 + n < Nc) ? B[(size_t)(k0 + k) * ldb + n0 + n] : 0.f;
        }
        __syncthreads();
#pragma unroll
        for (int k = 0; k < 16; k++) {
            float4 bv = *reinterpret_cast<const float4*>(&Bs[k][tx * 4]);
            float b4[4] = {bv.x, bv.y, bv.z, bv.w};
#pragma unroll
            for (int i = 0; i < 4; i++) {
                float av = As[k][ty * 4 + i];
#pragma unroll
                for (int j = 0; j < 4; j++) acc[i][j] += av * b4[j];
            }
        }
    }
#pragma unroll
    for (int i = 0; i < 4; i++) {
        int r = m0 + ty * 4 + i;
        if (r >= M) continue;
#pragma unroll
        for (int j = 0; j < 4; j++) {
            int c = n0 + tx * 4 + j;
            if (c >= Nc) continue;
            float v = acc[i][j];
            if (bias) v += bias[c];
            if (act == 1) v = v > 0.f ? v : (expf(v) - 1.f);
            C[(size_t)r * ldc + c] = v;
        }
    }
}

// ---------------- log_softmax + L1 scalar ----------------
__global__ void lsm_kernel(float* __restrict__ out, int out_size) {
    int n = blockIdx.x * blockDim.x + threadIdx.x;
    if (n >= NN) return;
    float v[NCLSD];
    float mx = -1e30f;
#pragma unroll
    for (int c = 0; c < NCLSD; c++) { v[c] = g_logits[n * NCLSD + c]; mx = fmaxf(mx, v[c]); }
    float s = 0.f;
#pragma unroll
    for (int c = 0; c < NCLSD; c++) s += expf(v[c] - mx);
    float l = logf(s) + mx;
#pragma unroll
    for (int c = 0; c < NCLSD; c++) {
        int idx = n * NCLSD + c;
        if (idx < out_size) out[idx] = v[c] - l;
    }
}

__global__ void l1_kernel(const float* __restrict__ wfus1, const float* __restrict__ wfus2,
                          float* __restrict__ out, int out_size) {
    __shared__ float red[256];
    int tid = threadIdx.x;
    float s1 = 0.f, s2 = 0.f;
    for (int i = tid; i < FUSD * AA * FUSD; i += 256) s1 += fabsf(wfus1[i]);
    for (int i = tid; i < NCLSD * AA * NCLSD; i += 256) s2 += fabsf(wfus2[i]);
    red[tid] = s1 / (float)(FUSD * AA * FUSD) + s2 / (float)(NCLSD * AA * NCLSD);
    __syncthreads();
    for (int o = 128; o > 0; o >>= 1) {
        if (tid < o) red[tid] += red[tid + o];
        __syncthreads();
    }
    if (tid == 0 && out_size > NN * NCLSD) out[NN * NCLSD] = red[0];
}

// ---------------- host launcher ----------------
extern "C" void kernel_launch(void* const* d_in, const int* in_sizes, int n_in,
                              void* d_out, int out_size) {
    const float* x     = (const float*)d_in[0];
    const int*   adj   = (const int*)d_in[1];
    const float* W1    = (const float*)d_in[2];
    const float* a1    = (const float*)d_in[3];
    const float* W2    = (const float*)d_in[4];
    const float* a2    = (const float*)d_in[5];
    const float* wint1 = (const float*)d_in[6];
    const float* bint1 = (const float*)d_in[7];
    const float* wfus1 = (const float*)d_in[8];
    const float* bfus1 = (const float*)d_in[9];
    const float* wint2 = (const float*)d_in[10];
    const float* bint2 = (const float*)d_in[11];
    const float* wfus2 = (const float*)d_in[12];
    const float* bfus2 = (const float*)d_in[13];
    float* out = (float*)d_out;

    float *pWh1, *pgat1, *pWh2, *pgat2;
    float *pf1, *pea, *peb;
    float4* pmfac;
    float *ph1p, *pout1, *ph2p, *plogits;
    float *pwint1T, *pwfus1T, *pwint2T, *pwfus2T;
    unsigned* pbits;
    cudaGetSymbolAddress((void**)&pWh1, g_Wh1);
    cudaGetSymbolAddress((void**)&pgat1, g_gat1);
    cudaGetSymbolAddress((void**)&pWh2, g_Wh2);
    cudaGetSymbolAddress((void**)&pgat2, g_gat2);
    cudaGetSymbolAddress((void**)&pf1, g_f1);
    cudaGetSymbolAddress((void**)&pea, g_ea);
    cudaGetSymbolAddress((void**)&peb, g_eb);
    cudaGetSymbolAddress((void**)&pmfac, g_mfac4);
    cudaGetSymbolAddress((void**)&pbits, g_bits);
    cudaGetSymbolAddress((void**)&ph1p, g_h1p);
    cudaGetSymbolAddress((void**)&pout1, g_out1);
    cudaGetSymbolAddress((void**)&ph2p, g_h2p);
    cudaGetSymbolAddress((void**)&plogits, g_logits);
    cudaGetSymbolAddress((void**)&pwint1T, g_wint1T);
    cudaGetSymbolAddress((void**)&pwfus1T, g_wfus1T);
    cudaGetSymbolAddress((void**)&pwint2T, g_wint2T);
    cudaGetSymbolAddress((void**)&pwfus2T, g_wfus2T);

    int nblk64 = (NN + 63) / 64;     // 47

    // launch 0: stage 1 Wh1 = x @ W1 -> flattened [n][a*256+h*64+o]
    gemm_mma_kernel<O1D><<<dim3(nblk64, AA * HHD), 256>>>(
        x, W1, pWh1, nullptr, NN, NFEATD, NFEATD, O1D, LDW1,
        HHD, 0, 0, (long long)HHD * NFEATD * O1D, (long long)NFEATD * O1D,
        HO1D, O1D, 0);

    // launch 1: attention factors for stage 1
    fprep_kernel<<<(AA * HHD * NN + 255) / 256, 256>>>(pWh1, a1, O1D, LDW1);

    // launch 2: adjacency bitmask
    {
        long long warps = (long long)AA * NN * WPR;
        int blocks = (int)((warps * 32 + 255) / 256);
        bitmask_kernel<<<blocks, 256>>>(adj);
    }

    // launch 3: att1 (keep at this index for ncu capture)
    att_mma_kernel<O1D><<<dim3(nblk64, AA * HHD), 256>>>(
        pWh1, pf1, pea, peb, pmfac, pbits, pgat1);

    // launch 4: all weight transposes
    {
        int total = FUSD * HO1D + FUSD * AA * FUSD + NCLSD * HO2D + NCLSD * AA * NCLSD;
        transpose_all_kernel<<<(total + 255) / 256, 256>>>(wint1, wfus1, wint2, wfus2);
    }

    // interproj1: elu(gat1[:, a*256:(a+1)*256] @ wint1T + bint1) -> h1p[n][a*64+g]
    gemm_mma_kernel<FUSD><<<dim3(nblk64, AA), 256>>>(
        pgat1, pwint1T, ph1p, bint1, NN, HO1D, LDW1, FUSD, AA * FUSD,
        1, HO1D, 0, 0, 0, FUSD, 0, 1);

    // fusion1: out1 = h1p @ wfus1T + bfus1
    gemm_mma_kernel<FUSD><<<dim3(nblk64, 1), 256>>>(
        ph1p, pwfus1T, pout1, bfus1, NN, AA * FUSD, AA * FUSD, FUSD, FUSD,
        1, 0, 0, 0, 0, 0, 0, 0);

    // stage 2: Wh2 = out1 @ W2 -> flattened [n][a*128+h*32+o]
    gemm_mma_kernel<O2D><<<dim3(nblk64, AA * HHD), 256>>>(
        pout1, W2, pWh2, nullptr, NN, FUSD, FUSD, O2D, LDW2,
        HHD, 0, 0, (long long)HHD * FUSD * O2D, (long long)FUSD * O2D,
        HO2D, O2D, 0);

    fprep_kernel<<<(AA * HHD * NN + 255) / 256, 256>>>(pWh2, a2, O2D, LDW2);

    att_mma_kernel<O2D><<<dim3(nblk64, AA * HHD), 256>>>(
        pWh2, pf1, pea, peb, pmfac, pbits, pgat2);

    // interproj2: elu(gat2[:, a*128:(a+1)*128] @ wint2T + bint2) -> h2p[n][a*8+c]
    sgemm_kernel<<<dim3(nblk64, 1, AA), 256>>>(
        pgat2, pwint2T, ph2p, bint2, NN, HO2D, NCLSD, LDW2, NCLSD, AA * NCLSD,
        1, HO2D, 0, 0, 0, NCLSD, 0, 1);

    // fusion2: logits = h2p @ wfus2T + bfus2
    sgemm_kernel<<<dim3(nblk64, 1, 1), 256>>>(
        ph2p, pwfus2T, plogits, bfus2, NN, AA * NCLSD, NCLSD,
        AA * NCLSD, NCLSD, NCLSD,
        1, 0, 0, 0, 0, 0, 0, 0);

    lsm_kernel<<<(NN + 255) / 256, 256>>>(out, out_size);
    l1_kernel<<<1, 256>>>(wfus1, wfus2, out, out_size);
}

// round 8
// speedup vs baseline: 2.5939x; 1.3135x over previous
#include <cuda_runtime.h>
#include <math.h>
#include <stdint.h>

#define NN 3000
#define NFEATD 512
#define AA 2
#define HHD 4
#define O1D 64
#define O2D 32
#define HO1D 256
#define HO2D 128
#define LDW1 512          // flattened Wh1/gat1 row width = AA*HHD*O1D
#define LDW2 256          // flattened Wh2/gat2 row width
#define FUSD 64
#define NCLSD 8
#define WPR 94
#define NTILES 94
#define ALPHAF 0.2f

// ---------------- scratch ----------------
__device__ float g_Wh1[NN*LDW1];        // [n][a*256+h*64+o]
__device__ float g_gat1[NN*LDW1];
__device__ float g_Wh2[NN*LDW2];        // [n][a*128+h*32+o]
__device__ float g_gat2[NN*LDW2];
__device__ float g_f1[AA*HHD*NN], g_ea[AA*HHD*NN], g_eb[AA*HHD*NN];
__device__ float4 g_mfac4[AA*HHD*NN];   // (f2, exp(f2), exp(a*f2), 0)
__device__ unsigned g_bits[AA*WPR*NN];  // [a][mt][n]
__device__ float g_h1p[NN*AA*FUSD];
__device__ float g_out1[NN*FUSD];
__device__ float g_h2p[NN*AA*NCLSD];
__device__ float g_logits[NN*NCLSD];
__device__ float g_wint1T[HO1D*FUSD];
__device__ float g_wfus1T[AA*FUSD*FUSD];
__device__ float g_wint2T[HO2D*NCLSD];
__device__ float g_wfus2T[AA*NCLSD*NCLSD];

// ---------------- mma helpers ----------------
__device__ __forceinline__ void mma_tf32(float* c, uint32_t a0, uint32_t a1,
                                         uint32_t a2, uint32_t a3,
                                         uint32_t b0, uint32_t b1) {
    asm volatile(
        "mma.sync.aligned.m16n8k8.row.col.f32.tf32.tf32.f32 "
        "{%0,%1,%2,%3}, {%4,%5,%6,%7}, {%8,%9}, {%0,%1,%2,%3};\n"
        : "+f"(c[0]), "+f"(c[1]), "+f"(c[2]), "+f"(c[3])
        : "r"(a0), "r"(a1), "r"(a2), "r"(a3), "r"(b0), "r"(b1));
}
__device__ __forceinline__ void mma_bf16(float* c, uint32_t a0, uint32_t a1,
                                         uint32_t a2, uint32_t a3,
                                         uint32_t b0, uint32_t b1) {
    asm volatile(
        "mma.sync.aligned.m16n8k16.row.col.f32.bf16.bf16.f32 "
        "{%0,%1,%2,%3}, {%4,%5,%6,%7}, {%8,%9}, {%0,%1,%2,%3};\n"
        : "+f"(c[0]), "+f"(c[1]), "+f"(c[2]), "+f"(c[3])
        : "r"(a0), "r"(a1), "r"(a2), "r"(a3), "r"(b0), "r"(b1));
}
__device__ __forceinline__ float cvt_tf32(float v) {
    uint32_t r;
    asm("cvt.rna.tf32.f32 %0, %1;" : "=r"(r) : "f"(v));
    return __uint_as_float(r);
}
__device__ __forceinline__ uint32_t pack_bf16x2(float hi, float lo) {
    uint32_t r;
    asm("cvt.rn.bf16x2.f32 %0, %1, %2;" : "=r"(r) : "f"(hi), "f"(lo));
    return r;
}

// ---------------- merged weight transposes ----------------
__global__ void transpose_all_kernel(const float* __restrict__ wint1,
                                     const float* __restrict__ wfus1,
                                     const float* __restrict__ wint2,
                                     const float* __restrict__ wfus2) {
    const int S1 = FUSD * HO1D;
    const int S2 = FUSD * AA * FUSD;
    const int S3 = NCLSD * HO2D;
    const int S4 = NCLSD * AA * NCLSD;
    int t = blockIdx.x * blockDim.x + threadIdx.x;
    if (t < S1) {
        int r = t / HO1D, c = t % HO1D;
        g_wint1T[c * FUSD + r] = wint1[t];
    } else if (t < S1 + S2) {
        int e = t - S1;
        int r = e / (AA * FUSD), c = e % (AA * FUSD);
        g_wfus1T[c * FUSD + r] = wfus1[e];
    } else if (t < S1 + S2 + S3) {
        int e = t - S1 - S2;
        int r = e / HO2D, c = e % HO2D;
        g_wint2T[c * NCLSD + r] = wint2[e];
    } else if (t < S1 + S2 + S3 + S4) {
        int e = t - S1 - S2 - S3;
        int r = e / (AA * NCLSD), c = e % (AA * NCLSD);
        g_wfus2T[c * NCLSD + r] = wfus2[e];
    }
}

// ---------------- adjacency -> bitmask via ballot ----------------
__global__ void bitmask_kernel(const int* __restrict__ adj) {
    int gw = (blockIdx.x * blockDim.x + threadIdx.x) >> 5;
    int lane = threadIdx.x & 31;
    if (gw >= AA * NN * WPR) return;
    int a = gw / (NN * WPR);
    int rem = gw % (NN * WPR);
    int n = rem / WPR;
    int mt = rem % WPR;
    int m = mt * 32 + lane;
    int v = 0;
    if (m < NN) v = adj[(size_t)(a * NN + n) * NN + m] > 0;
    unsigned word = __ballot_sync(0xffffffffu, v);
    if (lane == 0) g_bits[(size_t)(a * WPR + mt) * NN + n] = word;
}

// ---------------- attention factor precompute (flattened Wh) ----------------
__global__ void fprep_kernel(const float* __restrict__ Wh, const float* __restrict__ avec,
                             int O, int ldw) {
    int t = blockIdx.x * blockDim.x + threadIdx.x;
    if (t >= AA * HHD * NN) return;
    int ah = t / NN, n = t % NN;
    int a = ah / HHD, h = ah % HHD;
    const float* wr = Wh + (size_t)n * ldw + (a * HHD + h) * O;
    const float* av = avec + ah * 2 * O;
    float f1 = 0.f, f2 = 0.f;
    for (int o = 0; o < O; o++) {
        float w = wr[o];
        f1 += w * av[o];
        f2 += w * av[O + o];
    }
    g_f1[t] = f1;
    g_ea[t] = expf(f1);
    g_eb[t] = expf(ALPHAF * f1);
    g_mfac4[t] = make_float4(f2, expf(f2), expf(ALPHAF * f2), 0.f);
}

// ---------------- generic tf32 MMA GEMM (batched, bias, elu) ----------------
template <int O>
__global__ void gemm_mma_kernel(const float* __restrict__ A, const float* __restrict__ B,
                                float* __restrict__ C, const float* __restrict__ bias,
                                int M, int K, int lda, int ldb, int ldc,
                                int Hz, long long sAa, long long sAh,
                                long long sBa, long long sBh,
                                long long sCa, int cOffH, int act) {
    constexpr int BS = O + 8;
    constexpr int NT = O / 16;
    int z = blockIdx.y;
    int za = z / Hz, zh = z - za * Hz;
    A += za * sAa + zh * sAh;
    B += za * sBa + zh * sBh;
    C += za * sCa + (long long)zh * cOffH;

    __shared__ float As[64][36];
    __shared__ float Bs[32][BS];

    int tid = threadIdx.x, w = tid >> 5, lane = tid & 31;
    int rg = w >> 1, cg = w & 1;
    int g = lane >> 2, t4 = lane & 3;
    int m0 = blockIdx.x * 64;

    float acc[NT][4];
#pragma unroll
    for (int i = 0; i < NT; i++)
#pragma unroll
        for (int j = 0; j < 4; j++) acc[i][j] = 0.f;

    for (int k0 = 0; k0 < K; k0 += 32) {
#pragma unroll
        for (int i = 0; i < 8; i++) {
            int e = tid + i * 256;
            int r = e >> 5, k = e & 31;
            int m = m0 + r;
            float v = (m < M) ? A[(size_t)m * lda + k0 + k] : 0.f;
            As[r][k] = cvt_tf32(v);
        }
#pragma unroll
        for (int i = 0; i < (32 * O) / 256; i++) {
            int e = tid + i * 256;
            int k, c;
            if (O == 64) { k = e >> 6; c = e & 63; } else { k = e >> 5; c = e & 31; }
            Bs[k][c] = cvt_tf32(B[(size_t)(k0 + k) * ldb + c]);
        }
        __syncthreads();
#pragma unroll
        for (int kk = 0; kk < 4; kk++) {
            int kb = kk * 8;
            int ar = rg * 16 + g;
            uint32_t a0 = __float_as_uint(As[ar][kb + t4]);
            uint32_t a1 = __float_as_uint(As[ar + 8][kb + t4]);
            uint32_t a2 = __float_as_uint(As[ar][kb + t4 + 4]);
            uint32_t a3 = __float_as_uint(As[ar + 8][kb + t4 + 4]);
#pragma unroll
            for (int nt = 0; nt < NT; nt++) {
                int col = cg * (O / 2) + nt * 8 + g;
                uint32_t b0 = __float_as_uint(Bs[kb + t4][col]);
                uint32_t b1 = __float_as_uint(Bs[kb + t4 + 4][col]);
                mma_tf32(acc[nt], a0, a1, a2, a3, b0, b1);
            }
        }
        __syncthreads();
    }
#pragma unroll
    for (int half = 0; half < 2; half++) {
        int r = rg * 16 + g + half * 8;
        int gr = m0 + r;
        if (gr < M) {
#pragma unroll
            for (int nt = 0; nt < NT; nt++) {
                int col = cg * (O / 2) + nt * 8 + 2 * t4;
                float v0 = acc[nt][half * 2 + 0];
                float v1 = acc[nt][half * 2 + 1];
                if (bias) { v0 += bias[col]; v1 += bias[col + 1]; }
                if (act == 1) {
                    v0 = v0 > 0.f ? v0 : (expf(v0) - 1.f);
                    v1 = v1 > 0.f ? v1 : (expf(v1) - 1.f);
                }
                *(float2*)&C[(size_t)gr * ldc + col] = make_float2(v0, v1);
            }
        }
    }
}

// ---------------- attention weight (raw fp32; rounded at pack) ----------------
__device__ __forceinline__ float attw_f(unsigned word, int mb, float f1n, float ean,
                                        float ebn, const float4 q) {
    float wv = 0.f;
    if ((word >> mb) & 1u) {
        float s = f1n + q.x;
        wv = (s > 0.f) ? ean * q.y : ebn * q.z;
    }
    return wv;
}

// ---------------- fused masked-softmax attention aggregate (bf16 MMA) ----------------
// 64-row tiles; 8 warps = 4 rowgroups x 2 k-groups. Each warp: 16 rows x full O cols,
// 16-k slice per tile. attw computed once per (row,k). One-time acc/Z merge across
// k-group warp pairs at the end.
// out[n,:] = elu( (sum_m w(n,m)*Wh[m,:]) / (sum_m w(n,m)) )
template <int O>
__global__ void att_mma_kernel(const float* __restrict__ Wh,
                               const float* __restrict__ f1v, const float* __restrict__ eav,
                               const float* __restrict__ ebv,
                               const float4* __restrict__ mfac,
                               const unsigned* __restrict__ bits,
                               float* __restrict__ outp) {
    constexpr int LDW = AA * HHD * O;
    constexpr int NT = O / 8;                    // n8 tiles per warp (full O)
    constexpr int BSTRIDE = (O == 64) ? 72 : 40; // uint32 row stride; %32 == 8
    int z = blockIdx.y;
    int a = z >> 2, h = z & 3;
    int n0 = blockIdx.x * 64;
    const float* whb = Wh + (a * HHD + h) * O;   // + m*LDW
    const float4* mfb = mfac + (size_t)z * NN;
    const unsigned* bb = bits + (size_t)a * WPR * NN;

    __shared__ uint32_t Whs[2][16 * BSTRIDE];    // bf16x2 pairs: entry (mp,o) = (m=2mp,2mp+1)
    __shared__ float4 mfs[2][32];
    __shared__ unsigned wds[2][64];
    __shared__ float mrg[4 * NT * 128];          // kg-merge buffer
    __shared__ float Zbuf[64];

    int tid = threadIdx.x, w = tid >> 5, lane = tid & 31;
    int rg = w >> 1, kg = w & 1;
    int g = lane >> 2, t4 = lane & 3;
    int r0 = rg * 16 + g, r1 = r0 + 8;
    int gr0 = n0 + r0, gr1 = n0 + r1;

    float f10 = 0.f, ea0 = 0.f, eb0 = 0.f, f11 = 0.f, ea1 = 0.f, eb1 = 0.f;
    if (gr0 < NN) { f10 = f1v[(size_t)z*NN+gr0]; ea0 = eav[(size_t)z*NN+gr0]; eb0 = ebv[(size_t)z*NN+gr0]; }
    if (gr1 < NN) { f11 = f1v[(size_t)z*NN+gr1]; ea1 = eav[(size_t)z*NN+gr1]; eb1 = ebv[(size_t)z*NN+gr1]; }

    float acc[NT][4];
#pragma unroll
    for (int i = 0; i < NT; i++)
#pragma unroll
        for (int j = 0; j < 4; j++) acc[i][j] = 0.f;
    float zp0 = 0.f, zp1 = 0.f;

    auto build = [&](int mt, int buf) {
        // pack Wh m-pairs to bf16x2: entry (mp, o), mp in 0..15, o in 0..O-1
#pragma unroll
        for (int i = 0; i < (16 * O) / 256; i++) {
            int e = tid + i * 256;
            int mp, o;
            if (O == 64) { mp = e >> 6; o = e & 63; } else { mp = e >> 5; o = e & 31; }
            int m0i = mt * 32 + 2 * mp;
            float v0 = (m0i < NN) ? whb[(size_t)m0i * LDW + o] : 0.f;
            float v1 = (m0i + 1 < NN) ? whb[(size_t)(m0i + 1) * LDW + o] : 0.f;
            Whs[buf][mp * BSTRIDE + o] = pack_bf16x2(v1, v0);
        }
        if (tid < 32) {
            int m = mt * 32 + tid;
            mfs[buf][tid] = (m < NN) ? mfb[m] : make_float4(0.f, 0.f, 0.f, 0.f);
        } else if (tid >= 64 && tid < 128) {
            int rr = n0 + tid - 64;
            wds[buf][tid - 64] = (rr < NN) ? bb[(size_t)mt * NN + rr] : 0u;
        }
    };

    build(0, 0);
    __syncthreads();

    int kb = kg * 16;
    for (int mt = 0; mt < NTILES; mt++) {
        int cur = mt & 1;
        if (mt + 1 < NTILES) build(mt + 1, cur ^ 1);
        unsigned w0 = wds[cur][r0], w1 = wds[cur][r1];
        // per-thread k indices within this warp's 16-k slice
        float4 qa = mfs[cur][kb + 2 * t4];
        float4 qb = mfs[cur][kb + 2 * t4 + 1];
        float4 qc = mfs[cur][kb + 2 * t4 + 8];
        float4 qd = mfs[cur][kb + 2 * t4 + 9];
        float w0a = attw_f(w0, kb + 2 * t4,     f10, ea0, eb0, qa);
        float w0b = attw_f(w0, kb + 2 * t4 + 1, f10, ea0, eb0, qb);
        float w0c = attw_f(w0, kb + 2 * t4 + 8, f10, ea0, eb0, qc);
        float w0d = attw_f(w0, kb + 2 * t4 + 9, f10, ea0, eb0, qd);
        float w1a = attw_f(w1, kb + 2 * t4,     f11, ea1, eb1, qa);
        float w1b = attw_f(w1, kb + 2 * t4 + 1, f11, ea1, eb1, qb);
        float w1c = attw_f(w1, kb + 2 * t4 + 8, f11, ea1, eb1, qc);
        float w1d = attw_f(w1, kb + 2 * t4 + 9, f11, ea1, eb1, qd);
        zp0 += (w0a + w0b) + (w0c + w0d);
        zp1 += (w1a + w1b) + (w1c + w1d);
        uint32_t a0 = pack_bf16x2(w0b, w0a);
        uint32_t a1 = pack_bf16x2(w1b, w1a);
        uint32_t a2 = pack_bf16x2(w0d, w0c);
        uint32_t a3 = pack_bf16x2(w1d, w1c);
        int row0 = kg * 8 + t4, row1 = row0 + 4;
#pragma unroll
        for (int nt = 0; nt < NT; nt++) {
            int col = nt * 8 + g;
            uint32_t b0 = Whs[cur][row0 * BSTRIDE + col];
            uint32_t b1 = Whs[cur][row1 * BSTRIDE + col];
            mma_bf16(acc[nt], a0, a1, a2, a3, b0, b1);
        }
        __syncthreads();
    }

    // Z reduce over quad (t4 bits) via butterfly
#pragma unroll
    for (int d = 1; d < 4; d <<= 1) {
        zp0 += __shfl_xor_sync(0xffffffffu, zp0, d);
        zp1 += __shfl_xor_sync(0xffffffffu, zp1, d);
    }

    // merge k-group pairs: kg=1 writes, kg=0 adds
    int flat = rg * 32 + lane;
    if (kg == 1) {
#pragma unroll
        for (int nt = 0; nt < NT; nt++)
#pragma unroll
            for (int j = 0; j < 4; j++)
                mrg[(nt * 4 + j) * 128 + flat] = acc[nt][j];
        if (t4 == 0) { Zbuf[r0] = zp0; Zbuf[r1] = zp1; }
    }
    __syncthreads();
    if (kg == 0) {
#pragma unroll
        for (int nt = 0; nt < NT; nt++)
#pragma unroll
            for (int j = 0; j < 4; j++)
                acc[nt][j] += mrg[(nt * 4 + j) * 128 + flat];
        zp0 += Zbuf[r0];
        zp1 += Zbuf[r1];
        float inv0 = (zp0 > 0.f) ? 1.f / zp0 : 0.f;
        float inv1 = (zp1 > 0.f) ? 1.f / zp1 : 0.f;
        // epilogue: normalize + elu + store
#pragma unroll
        for (int nt = 0; nt < NT; nt++) {
            int col = nt * 8 + 2 * t4;
            if (gr0 < NN) {
                float v0 = acc[nt][0] * inv0;
                float v1 = acc[nt][1] * inv0;
                v0 = v0 > 0.f ? v0 : (expf(v0) - 1.f);
                v1 = v1 > 0.f ? v1 : (expf(v1) - 1.f);
                *(float2*)&outp[(size_t)gr0 * LDW + (a * HHD + h) * O + col] = make_float2(v0, v1);
            }
            if (gr1 < NN) {
                float v2 = acc[nt][2] * inv1;
                float v3 = acc[nt][3] * inv1;
                v2 = v2 > 0.f ? v2 : (expf(v2) - 1.f);
                v3 = v3 > 0.f ? v3 : (expf(v3) - 1.f);
                *(float2*)&outp[(size_t)gr1 * LDW + (a * HHD + h) * O + col] = make_float2(v2, v3);
            }
        }
    }
}

// ---------------- SIMT SGEMM for tiny tail layers ----------------
__global__ void sgemm_kernel(const float* __restrict__ A, const float* __restrict__ B,
                             float* __restrict__ C, const float* __restrict__ bias,
                             int M, int K, int Nc, int lda, int ldb, int ldc,
                             int Hz, long long sAa, long long sAh,
                             long long sBa, long long sBh,
                             long long sCa, long long sCh, int act) {
    int z = blockIdx.z;
    int za = z / Hz, zh = z % Hz;
    A += za * sAa + zh * sAh;
    B += za * sBa + zh * sBh;
    C += za * sCa + zh * sCh;
    __shared__ float As[16][65];
    __shared__ __align__(16) float Bs[16][64];
    int tid = threadIdx.x;
    int tx = tid & 15, ty = tid >> 4;
    int m0 = blockIdx.x * 64, n0 = blockIdx.y * 64;
    float acc[4][4] = {};
    for (int k0 = 0; k0 < K; k0 += 16) {
        __syncthreads();
#pragma unroll
        for (int i = 0; i < 4; i++) {
            int e = tid + i * 256;
            int k = e & 15, m = e >> 4;
            As[k][m] = (m0 + m < M) ? A[(size_t)(m0 + m) * lda + k0 + k] : 0.f;
        }
#pragma unroll
        for (int i = 0; i < 4; i++) {
            int e = tid + i * 256;
            int n = e & 63, k = e >> 6;
            Bs[k][n] = (n0 + n < Nc) ? B[(size_t)(k0 + k) * ldb + n0 + n] : 0.f;
        }
        __syncthreads();
#pragma unroll
        for (int k = 0; k < 16; k++) {
            float4 bv = *reinterpret_cast<const float4*>(&Bs[k][tx * 4]);
            float b4[4] = {bv.x, bv.y, bv.z, bv.w};
#pragma unroll
            for (int i = 0; i < 4; i++) {
                float av = As[k][ty * 4 + i];
#pragma unroll
                for (int j = 0; j < 4; j++) acc[i][j] += av * b4[j];
            }
        }
    }
#pragma unroll
    for (int i = 0; i < 4; i++) {
        int r = m0 + ty * 4 + i;
        if (r >= M) continue;
#pragma unroll
        for (int j = 0; j < 4; j++) {
            int c = n0 + tx * 4 + j;
            if (c >= Nc) continue;
            float v = acc[i][j];
            if (bias) v += bias[c];
            if (act == 1) v = v > 0.f ? v : (expf(v) - 1.f);
            C[(size_t)r * ldc + c] = v;
        }
    }
}

// ---------------- log_softmax + L1 scalar ----------------
__global__ void lsm_kernel(float* __restrict__ out, int out_size) {
    int n = blockIdx.x * blockDim.x + threadIdx.x;
    if (n >= NN) return;
    float v[NCLSD];
    float mx = -1e30f;
#pragma unroll
    for (int c = 0; c < NCLSD; c++) { v[c] = g_logits[n * NCLSD + c]; mx = fmaxf(mx, v[c]); }
    float s = 0.f;
#pragma unroll
    for (int c = 0; c < NCLSD; c++) s += expf(v[c] - mx);
    float l = logf(s) + mx;
#pragma unroll
    for (int c = 0; c < NCLSD; c++) {
        int idx = n * NCLSD + c;
        if (idx < out_size) out[idx] = v[c] - l;
    }
}

__global__ void l1_kernel(const float* __restrict__ wfus1, const float* __restrict__ wfus2,
                          float* __restrict__ out, int out_size) {
    __shared__ float red[256];
    int tid = threadIdx.x;
    float s1 = 0.f, s2 = 0.f;
    for (int i = tid; i < FUSD * AA * FUSD; i += 256) s1 += fabsf(wfus1[i]);
    for (int i = tid; i < NCLSD * AA * NCLSD; i += 256) s2 += fabsf(wfus2[i]);
    red[tid] = s1 / (float)(FUSD * AA * FUSD) + s2 / (float)(NCLSD * AA * NCLSD);
    __syncthreads();
    for (int o = 128; o > 0; o >>= 1) {
        if (tid < o) red[tid] += red[tid + o];
        __syncthreads();
    }
    if (tid == 0 && out_size > NN * NCLSD) out[NN * NCLSD] = red[0];
}

// ---------------- host launcher ----------------
extern "C" void kernel_launch(void* const* d_in, const int* in_sizes, int n_in,
                              void* d_out, int out_size) {
    const float* x     = (const float*)d_in[0];
    const int*   adj   = (const int*)d_in[1];
    const float* W1    = (const float*)d_in[2];
    const float* a1    = (const float*)d_in[3];
    const float* W2    = (const float*)d_in[4];
    const float* a2    = (const float*)d_in[5];
    const float* wint1 = (const float*)d_in[6];
    const float* bint1 = (const float*)d_in[7];
    const float* wfus1 = (const float*)d_in[8];
    const float* bfus1 = (const float*)d_in[9];
    const float* wint2 = (const float*)d_in[10];
    const float* bint2 = (const float*)d_in[11];
    const float* wfus2 = (const float*)d_in[12];
    const float* bfus2 = (const float*)d_in[13];
    float* out = (float*)d_out;

    float *pWh1, *pgat1, *pWh2, *pgat2;
    float *pf1, *pea, *peb;
    float4* pmfac;
    float *ph1p, *pout1, *ph2p, *plogits;
    float *pwint1T, *pwfus1T, *pwint2T, *pwfus2T;
    unsigned* pbits;
    cudaGetSymbolAddress((void**)&pWh1, g_Wh1);
    cudaGetSymbolAddress((void**)&pgat1, g_gat1);
    cudaGetSymbolAddress((void**)&pWh2, g_Wh2);
    cudaGetSymbolAddress((void**)&pgat2, g_gat2);
    cudaGetSymbolAddress((void**)&pf1, g_f1);
    cudaGetSymbolAddress((void**)&pea, g_ea);
    cudaGetSymbolAddress((void**)&peb, g_eb);
    cudaGetSymbolAddress((void**)&pmfac, g_mfac4);
    cudaGetSymbolAddress((void**)&pbits, g_bits);
    cudaGetSymbolAddress((void**)&ph1p, g_h1p);
    cudaGetSymbolAddress((void**)&pout1, g_out1);
    cudaGetSymbolAddress((void**)&ph2p, g_h2p);
    cudaGetSymbolAddress((void**)&plogits, g_logits);
    cudaGetSymbolAddress((void**)&pwint1T, g_wint1T);
    cudaGetSymbolAddress((void**)&pwfus1T, g_wfus1T);
    cudaGetSymbolAddress((void**)&pwint2T, g_wint2T);
    cudaGetSymbolAddress((void**)&pwfus2T, g_wfus2T);

    int nblk64 = (NN + 63) / 64;     // 47

    // launch 0: stage 1 Wh1 = x @ W1 -> flattened [n][a*256+h*64+o]
    gemm_mma_kernel<O1D><<<dim3(nblk64, AA * HHD), 256>>>(
        x, W1, pWh1, nullptr, NN, NFEATD, NFEATD, O1D, LDW1,
        HHD, 0, 0, (long long)HHD * NFEATD * O1D, (long long)NFEATD * O1D,
        HO1D, O1D, 0);

    // launch 1: attention factors for stage 1
    fprep_kernel<<<(AA * HHD * NN + 255) / 256, 256>>>(pWh1, a1, O1D, LDW1);

    // launch 2: adjacency bitmask
    {
        long long warps = (long long)AA * NN * WPR;
        int blocks = (int)((warps * 32 + 255) / 256);
        bitmask_kernel<<<blocks, 256>>>(adj);
    }

    // launch 3: att1 (keep at this index for ncu capture)
    att_mma_kernel<O1D><<<dim3(nblk64, AA * HHD), 256>>>(
        pWh1, pf1, pea, peb, pmfac, pbits, pgat1);

    // launch 4: all weight transposes
    {
        int total = FUSD * HO1D + FUSD * AA * FUSD + NCLSD * HO2D + NCLSD * AA * NCLSD;
        transpose_all_kernel<<<(total + 255) / 256, 256>>>(wint1, wfus1, wint2, wfus2);
    }

    // interproj1: elu(gat1[:, a*256:(a+1)*256] @ wint1T + bint1) -> h1p[n][a*64+g]
    gemm_mma_kernel<FUSD><<<dim3(nblk64, AA), 256>>>(
        pgat1, pwint1T, ph1p, bint1, NN, HO1D, LDW1, FUSD, AA * FUSD,
        1, HO1D, 0, 0, 0, FUSD, 0, 1);

    // fusion1: out1 = h1p @ wfus1T + bfus1
    gemm_mma_kernel<FUSD><<<dim3(nblk64, 1), 256>>>(
        ph1p, pwfus1T, pout1, bfus1, NN, AA * FUSD, AA * FUSD, FUSD, FUSD,
        1, 0, 0, 0, 0, 0, 0, 0);

    // stage 2: Wh2 = out1 @ W2 -> flattened [n][a*128+h*32+o]
    gemm_mma_kernel<O2D><<<dim3(nblk64, AA * HHD), 256>>>(
        pout1, W2, pWh2, nullptr, NN, FUSD, FUSD, O2D, LDW2,
        HHD, 0, 0, (long long)HHD * FUSD * O2D, (long long)FUSD * O2D,
        HO2D, O2D, 0);

    fprep_kernel<<<(AA * HHD * NN + 255) / 256, 256>>>(pWh2, a2, O2D, LDW2);

    att_mma_kernel<O2D><<<dim3(nblk64, AA * HHD), 256>>>(
        pWh2, pf1, pea, peb, pmfac, pbits, pgat2);

    // interproj2: elu(gat2[:, a*128:(a+1)*128] @ wint2T + bint2) -> h2p[n][a*8+c]
    sgemm_kernel<<<dim3(nblk64, 1, AA), 256>>>(
        pgat2, pwint2T, ph2p, bint2, NN, HO2D, NCLSD, LDW2, NCLSD, AA * NCLSD,
        1, HO2D, 0, 0, 0, NCLSD, 0, 1);

    // fusion2: logits = h2p @ wfus2T + bfus2
    sgemm_kernel<<<dim3(nblk64, 1, 1), 256>>>(
        ph2p, pwfus2T, plogits, bfus2, NN, AA * NCLSD, NCLSD,
        AA * NCLSD, NCLSD, NCLSD,
        1, 0, 0, 0, 0, 0, 0, 0);

    lsm_kernel<<<(NN + 255) / 256, 256>>>(out, out_size);
    l1_kernel<<<1, 256>>>(wfus1, wfus2, out, out_size);
}

// round 9
// speedup vs baseline: 2.8047x; 1.0813x over previous
#include <cuda_runtime.h>
#include <math.h>
#include <stdint.h>

#define NN 3000
#define NFEATD 512
#define AA 2
#define HHD 4
#define O1D 64
#define O2D 32
#define HO1D 256
#define HO2D 128
#define LDW1 512          // flattened Wh1/gat1 row width = AA*HHD*O1D
#define LDW2 256          // flattened Wh2/gat2 row width
#define FUSD 64
#define NCLSD 8
#define WPR 94
#define NT64 47           // ceil(3000/64) 64-m tiles
#define ALPHAF 0.2f

// ---------------- scratch ----------------
__device__ float g_Wh1[NN*LDW1];        // [n][a*256+h*64+o]
__device__ float g_gat1[NN*LDW1];
__device__ float g_Wh2[NN*LDW2];        // [n][a*128+h*32+o]
__device__ float g_gat2[NN*LDW2];
__device__ float g_f1[AA*HHD*NN], g_ea[AA*HHD*NN], g_eb[AA*HHD*NN];
__device__ float4 g_mfac4[AA*HHD*NN];   // (f2, exp(f2), exp(a*f2), 0)
__device__ unsigned g_bits[AA*WPR*NN];  // [a][mt32][n]
__device__ float g_h1p[NN*AA*FUSD];
__device__ float g_out1[NN*FUSD];
__device__ float g_h2p[NN*AA*NCLSD];
__device__ float g_logits[NN*NCLSD];
__device__ float g_wint1T[HO1D*FUSD];
__device__ float g_wfus1T[AA*FUSD*FUSD];
__device__ float g_wint2T[HO2D*NCLSD];
__device__ float g_wfus2T[AA*NCLSD*NCLSD];

// ---------------- mma helpers ----------------
__device__ __forceinline__ void mma_tf32(float* c, uint32_t a0, uint32_t a1,
                                         uint32_t a2, uint32_t a3,
                                         uint32_t b0, uint32_t b1) {
    asm volatile(
        "mma.sync.aligned.m16n8k8.row.col.f32.tf32.tf32.f32 "
        "{%0,%1,%2,%3}, {%4,%5,%6,%7}, {%8,%9}, {%0,%1,%2,%3};\n"
        : "+f"(c[0]), "+f"(c[1]), "+f"(c[2]), "+f"(c[3])
        : "r"(a0), "r"(a1), "r"(a2), "r"(a3), "r"(b0), "r"(b1));
}
__device__ __forceinline__ void mma_bf16(float* c, uint32_t a0, uint32_t a1,
                                         uint32_t a2, uint32_t a3,
                                         uint32_t b0, uint32_t b1) {
    asm volatile(
        "mma.sync.aligned.m16n8k16.row.col.f32.bf16.bf16.f32 "
        "{%0,%1,%2,%3}, {%4,%5,%6,%7}, {%8,%9}, {%0,%1,%2,%3};\n"
        : "+f"(c[0]), "+f"(c[1]), "+f"(c[2]), "+f"(c[3])
        : "r"(a0), "r"(a1), "r"(a2), "r"(a3), "r"(b0), "r"(b1));
}
__device__ __forceinline__ float cvt_tf32(float v) {
    uint32_t r;
    asm("cvt.rna.tf32.f32 %0, %1;" : "=r"(r) : "f"(v));
    return __uint_as_float(r);
}
__device__ __forceinline__ uint32_t pack_bf16x2(float hi, float lo) {
    uint32_t r;
    asm("cvt.rn.bf16x2.f32 %0, %1, %2;" : "=r"(r) : "f"(hi), "f"(lo));
    return r;
}

// ---------------- merged weight transposes ----------------
__global__ void transpose_all_kernel(const float* __restrict__ wint1,
                                     const float* __restrict__ wfus1,
                                     const float* __restrict__ wint2,
                                     const float* __restrict__ wfus2) {
    const int S1 = FUSD * HO1D;
    const int S2 = FUSD * AA * FUSD;
    const int S3 = NCLSD * HO2D;
    const int S4 = NCLSD * AA * NCLSD;
    int t = blockIdx.x * blockDim.x + threadIdx.x;
    if (t < S1) {
        int r = t / HO1D, c = t % HO1D;
        g_wint1T[c * FUSD + r] = wint1[t];
    } else if (t < S1 + S2) {
        int e = t - S1;
        int r = e / (AA * FUSD), c = e % (AA * FUSD);
        g_wfus1T[c * FUSD + r] = wfus1[e];
    } else if (t < S1 + S2 + S3) {
        int e = t - S1 - S2;
        int r = e / HO2D, c = e % HO2D;
        g_wint2T[c * NCLSD + r] = wint2[e];
    } else if (t < S1 + S2 + S3 + S4) {
        int e = t - S1 - S2 - S3;
        int r = e / (AA * NCLSD), c = e % (AA * NCLSD);
        g_wfus2T[c * NCLSD + r] = wfus2[e];
    }
}

// ---------------- adjacency -> bitmask via ballot ----------------
__global__ void bitmask_kernel(const int* __restrict__ adj) {
    int gw = (blockIdx.x * blockDim.x + threadIdx.x) >> 5;
    int lane = threadIdx.x & 31;
    if (gw >= AA * NN * WPR) return;
    int a = gw / (NN * WPR);
    int rem = gw % (NN * WPR);
    int n = rem / WPR;
    int mt = rem % WPR;
    int m = mt * 32 + lane;
    int v = 0;
    if (m < NN) v = adj[(size_t)(a * NN + n) * NN + m] > 0;
    unsigned word = __ballot_sync(0xffffffffu, v);
    if (lane == 0) g_bits[(size_t)(a * WPR + mt) * NN + n] = word;
}

// ---------------- attention factor precompute (flattened Wh) ----------------
__global__ void fprep_kernel(const float* __restrict__ Wh, const float* __restrict__ avec,
                             int O, int ldw) {
    int t = blockIdx.x * blockDim.x + threadIdx.x;
    if (t >= AA * HHD * NN) return;
    int ah = t / NN, n = t % NN;
    int a = ah / HHD, h = ah % HHD;
    const float* wr = Wh + (size_t)n * ldw + (a * HHD + h) * O;
    const float* av = avec + ah * 2 * O;
    float f1 = 0.f, f2 = 0.f;
    for (int o = 0; o < O; o++) {
        float w = wr[o];
        f1 += w * av[o];
        f2 += w * av[O + o];
    }
    g_f1[t] = f1;
    g_ea[t] = expf(f1);
    g_eb[t] = expf(ALPHAF * f1);
    g_mfac4[t] = make_float4(f2, expf(f2), expf(ALPHAF * f2), 0.f);
}

// ---------------- generic tf32 MMA GEMM (batched, bias, elu) ----------------
template <int O>
__global__ void gemm_mma_kernel(const float* __restrict__ A, const float* __restrict__ B,
                                float* __restrict__ C, const float* __restrict__ bias,
                                int M, int K, int lda, int ldb, int ldc,
                                int Hz, long long sAa, long long sAh,
                                long long sBa, long long sBh,
                                long long sCa, int cOffH, int act) {
    constexpr int BS = O + 8;
    constexpr int NT = O / 16;
    int z = blockIdx.y;
    int za = z / Hz, zh = z - za * Hz;
    A += za * sAa + zh * sAh;
    B += za * sBa + zh * sBh;
    C += za * sCa + (long long)zh * cOffH;

    __shared__ float As[64][36];
    __shared__ float Bs[32][BS];

    int tid = threadIdx.x, w = tid >> 5, lane = tid & 31;
    int rg = w >> 1, cg = w & 1;
    int g = lane >> 2, t4 = lane & 3;
    int m0 = blockIdx.x * 64;

    float acc[NT][4];
#pragma unroll
    for (int i = 0; i < NT; i++)
#pragma unroll
        for (int j = 0; j < 4; j++) acc[i][j] = 0.f;

    for (int k0 = 0; k0 < K; k0 += 32) {
#pragma unroll
        for (int i = 0; i < 8; i++) {
            int e = tid + i * 256;
            int r = e >> 5, k = e & 31;
            int m = m0 + r;
            float v = (m < M) ? A[(size_t)m * lda + k0 + k] : 0.f;
            As[r][k] = cvt_tf32(v);
        }
#pragma unroll
        for (int i = 0; i < (32 * O) / 256; i++) {
            int e = tid + i * 256;
            int k, c;
            if (O == 64) { k = e >> 6; c = e & 63; } else { k = e >> 5; c = e & 31; }
            Bs[k][c] = cvt_tf32(B[(size_t)(k0 + k) * ldb + c]);
        }
        __syncthreads();
#pragma unroll
        for (int kk = 0; kk < 4; kk++) {
            int kb = kk * 8;
            int ar = rg * 16 + g;
            uint32_t a0 = __float_as_uint(As[ar][kb + t4]);
            uint32_t a1 = __float_as_uint(As[ar + 8][kb + t4]);
            uint32_t a2 = __float_as_uint(As[ar][kb + t4 + 4]);
            uint32_t a3 = __float_as_uint(As[ar + 8][kb + t4 + 4]);
#pragma unroll
            for (int nt = 0; nt < NT; nt++) {
                int col = cg * (O / 2) + nt * 8 + g;
                uint32_t b0 = __float_as_uint(Bs[kb + t4][col]);
                uint32_t b1 = __float_as_uint(Bs[kb + t4 + 4][col]);
                mma_tf32(acc[nt], a0, a1, a2, a3, b0, b1);
            }
        }
        __syncthreads();
    }
#pragma unroll
    for (int half = 0; half < 2; half++) {
        int r = rg * 16 + g + half * 8;
        int gr = m0 + r;
        if (gr < M) {
#pragma unroll
            for (int nt = 0; nt < NT; nt++) {
                int col = cg * (O / 2) + nt * 8 + 2 * t4;
                float v0 = acc[nt][half * 2 + 0];
                float v1 = acc[nt][half * 2 + 1];
                if (bias) { v0 += bias[col]; v1 += bias[col + 1]; }
                if (act == 1) {
                    v0 = v0 > 0.f ? v0 : (expf(v0) - 1.f);
                    v1 = v1 > 0.f ? v1 : (expf(v1) - 1.f);
                }
                *(float2*)&C[(size_t)gr * ldc + col] = make_float2(v0, v1);
            }
        }
    }
}

// ---------------- attention weight (raw fp32; rounded at pack) ----------------
__device__ __forceinline__ float attw_f(unsigned word, int mb, float f1n, float ean,
                                        float ebn, const float4 q) {
    float wv = 0.f;
    if ((word >> mb) & 1u) {
        float s = f1n + q.x;
        wv = (s > 0.f) ? ean * q.y : ebn * q.z;
    }
    return wv;
}

// ---------------- fused masked-softmax attention aggregate (bf16 MMA) ----------------
// 64-row tiles; 8 warps = 4 rowgroups x 2 k-groups. 64-m pipeline stages (two 32-m
// subtiles per iteration): half the barriers, 2x ILP between syncs.
// out[n,:] = elu( (sum_m w(n,m)*Wh[m,:]) / (sum_m w(n,m)) )
template <int O>
__global__ void att_mma_kernel(const float* __restrict__ Wh,
                               const float* __restrict__ f1v, const float* __restrict__ eav,
                               const float* __restrict__ ebv,
                               const float4* __restrict__ mfac,
                               const unsigned* __restrict__ bits,
                               float* __restrict__ outp) {
    constexpr int LDW = AA * HHD * O;
    constexpr int NT = O / 8;                    // n8 tiles per warp (full O)
    constexpr int BSTRIDE = (O == 64) ? 72 : 40; // uint32 row stride; %32 == 8
    int z = blockIdx.y;
    int a = z >> 2, h = z & 3;
    int n0 = blockIdx.x * 64;
    const float* whb = Wh + (a * HHD + h) * O;   // + m*LDW
    const float4* mfb = mfac + (size_t)z * NN;
    const unsigned* bb = bits + (size_t)a * WPR * NN;

    __shared__ uint32_t Whs[2][32 * BSTRIDE];    // bf16x2 pairs: 32 mp rows = 64 m
    __shared__ float4 mfs[2][64];
    __shared__ unsigned wds[2][2][64];           // [buf][sub32][n]
    __shared__ float mrg[4 * NT * 128];          // kg-merge buffer
    __shared__ float Zbuf[64];

    int tid = threadIdx.x, w = tid >> 5, lane = tid & 31;
    int rg = w >> 1, kg = w & 1;
    int g = lane >> 2, t4 = lane & 3;
    int r0 = rg * 16 + g, r1 = r0 + 8;
    int gr0 = n0 + r0, gr1 = n0 + r1;

    float f10 = 0.f, ea0 = 0.f, eb0 = 0.f, f11 = 0.f, ea1 = 0.f, eb1 = 0.f;
    if (gr0 < NN) { f10 = f1v[(size_t)z*NN+gr0]; ea0 = eav[(size_t)z*NN+gr0]; eb0 = ebv[(size_t)z*NN+gr0]; }
    if (gr1 < NN) { f11 = f1v[(size_t)z*NN+gr1]; ea1 = eav[(size_t)z*NN+gr1]; eb1 = ebv[(size_t)z*NN+gr1]; }

    float acc[NT][4];
#pragma unroll
    for (int i = 0; i < NT; i++)
#pragma unroll
        for (int j = 0; j < 4; j++) acc[i][j] = 0.f;
    float zp0 = 0.f, zp1 = 0.f;

    auto build = [&](int mt, int buf) {
        // pack 64 m rows as 32 bf16x2 pairs: entry (mp, o)
#pragma unroll
        for (int i = 0; i < (32 * O) / 256; i++) {
            int e = tid + i * 256;
            int mp, o;
            if (O == 64) { mp = e >> 6; o = e & 63; } else { mp = e >> 5; o = e & 31; }
            int m0i = mt * 64 + 2 * mp;
            float v0 = (m0i < NN) ? whb[(size_t)m0i * LDW + o] : 0.f;
            float v1 = (m0i + 1 < NN) ? whb[(size_t)(m0i + 1) * LDW + o] : 0.f;
            Whs[buf][mp * BSTRIDE + o] = pack_bf16x2(v1, v0);
        }
        if (tid < 64) {
            int m = mt * 64 + tid;
            mfs[buf][tid] = (m < NN) ? mfb[m] : make_float4(0.f, 0.f, 0.f, 0.f);
        } else if (tid < 192) {
            int j = (tid - 64) >> 6, n = (tid - 64) & 63;
            int rr = n0 + n;
            int wi = mt * 2 + j;
            wds[buf][j][n] = (rr < NN && wi < WPR) ? bb[(size_t)wi * NN + rr] : 0u;
        }
    };

    build(0, 0);
    __syncthreads();

    int kb = kg * 16;
    for (int mt = 0; mt < NT64; mt++) {
        int cur = mt & 1;
        if (mt + 1 < NT64) build(mt + 1, cur ^ 1);
#pragma unroll
        for (int sub = 0; sub < 2; sub++) {
            unsigned w0 = wds[cur][sub][r0], w1 = wds[cur][sub][r1];
            int base = sub * 32 + kb;
            float4 qa = mfs[cur][base + 2 * t4];
            float4 qb = mfs[cur][base + 2 * t4 + 1];
            float4 qc = mfs[cur][base + 2 * t4 + 8];
            float4 qd = mfs[cur][base + 2 * t4 + 9];
            float w0a = attw_f(w0, kb + 2 * t4,     f10, ea0, eb0, qa);
            float w0b = attw_f(w0, kb + 2 * t4 + 1, f10, ea0, eb0, qb);
            float w0c = attw_f(w0, kb + 2 * t4 + 8, f10, ea0, eb0, qc);
            float w0d = attw_f(w0, kb + 2 * t4 + 9, f10, ea0, eb0, qd);
            float w1a = attw_f(w1, kb + 2 * t4,     f11, ea1, eb1, qa);
            float w1b = attw_f(w1, kb + 2 * t4 + 1, f11, ea1, eb1, qb);
            float w1c = attw_f(w1, kb + 2 * t4 + 8, f11, ea1, eb1, qc);
            float w1d = attw_f(w1, kb + 2 * t4 + 9, f11, ea1, eb1, qd);
            zp0 += (w0a + w0b) + (w0c + w0d);
            zp1 += (w1a + w1b) + (w1c + w1d);
            uint32_t a0 = pack_bf16x2(w0b, w0a);
            uint32_t a1 = pack_bf16x2(w1b, w1a);
            uint32_t a2 = pack_bf16x2(w0d, w0c);
            uint32_t a3 = pack_bf16x2(w1d, w1c);
            int row0 = sub * 16 + kg * 8 + t4, row1 = row0 + 4;
#pragma unroll
            for (int nt = 0; nt < NT; nt++) {
                int col = nt * 8 + g;
                uint32_t b0 = Whs[cur][row0 * BSTRIDE + col];
                uint32_t b1 = Whs[cur][row1 * BSTRIDE + col];
                mma_bf16(acc[nt], a0, a1, a2, a3, b0, b1);
            }
        }
        __syncthreads();
    }

    // Z reduce over quad (t4 bits) via butterfly
#pragma unroll
    for (int d = 1; d < 4; d <<= 1) {
        zp0 += __shfl_xor_sync(0xffffffffu, zp0, d);
        zp1 += __shfl_xor_sync(0xffffffffu, zp1, d);
    }

    // merge k-group pairs: kg=1 writes, kg=0 adds
    int flat = rg * 32 + lane;
    if (kg == 1) {
#pragma unroll
        for (int nt = 0; nt < NT; nt++)
#pragma unroll
            for (int j = 0; j < 4; j++)
                mrg[(nt * 4 + j) * 128 + flat] = acc[nt][j];
        if (t4 == 0) { Zbuf[r0] = zp0; Zbuf[r1] = zp1; }
    }
    __syncthreads();
    if (kg == 0) {
#pragma unroll
        for (int nt = 0; nt < NT; nt++)
#pragma unroll
            for (int j = 0; j < 4; j++)
                acc[nt][j] += mrg[(nt * 4 + j) * 128 + flat];
        zp0 += Zbuf[r0];
        zp1 += Zbuf[r1];
        float inv0 = (zp0 > 0.f) ? 1.f / zp0 : 0.f;
        float inv1 = (zp1 > 0.f) ? 1.f / zp1 : 0.f;
        // epilogue: normalize + elu + store
#pragma unroll
        for (int nt = 0; nt < NT; nt++) {
            int col = nt * 8 + 2 * t4;
            if (gr0 < NN) {
                float v0 = acc[nt][0] * inv0;
                float v1 = acc[nt][1] * inv0;
                v0 = v0 > 0.f ? v0 : (expf(v0) - 1.f);
                v1 = v1 > 0.f ? v1 : (expf(v1) - 1.f);
                *(float2*)&outp[(size_t)gr0 * LDW + (a * HHD + h) * O + col] = make_float2(v0, v1);
            }
            if (gr1 < NN) {
                float v2 = acc[nt][2] * inv1;
                float v3 = acc[nt][3] * inv1;
                v2 = v2 > 0.f ? v2 : (expf(v2) - 1.f);
                v3 = v3 > 0.f ? v3 : (expf(v3) - 1.f);
                *(float2*)&outp[(size_t)gr1 * LDW + (a * HHD + h) * O + col] = make_float2(v2, v3);
            }
        }
    }
}

// ---------------- SIMT SGEMM for tiny tail layers ----------------
__global__ void sgemm_kernel(const float* __restrict__ A, const float* __restrict__ B,
                             float* __restrict__ C, const float* __restrict__ bias,
                             int M, int K, int Nc, int lda, int ldb, int ldc,
                             int Hz, long long sAa, long long sAh,
                             long long sBa, long long sBh,
                             long long sCa, long long sCh, int act) {
    int z = blockIdx.z;
    int za = z / Hz, zh = z % Hz;
    A += za * sAa + zh * sAh;
    B += za * sBa + zh * sBh;
    C += za * sCa + zh * sCh;
    __shared__ float As[16][65];
    __shared__ __align__(16) float Bs[16][64];
    int tid = threadIdx.x;
    int tx = tid & 15, ty = tid >> 4;
    int m0 = blockIdx.x * 64, n0 = blockIdx.y * 64;
    float acc[4][4] = {};
    for (int k0 = 0; k0 < K; k0 += 16) {
        __syncthreads();
#pragma unroll
        for (int i = 0; i < 4; i++) {
            int e = tid + i * 256;
            int k = e & 15, m = e >> 4;
            As[k][m] = (m0 + m < M) ? A[(size_t)(m0 + m) * lda + k0 + k] : 0.f;
        }
#pragma unroll
        for (int i = 0; i < 4; i++) {
            int e = tid + i * 256;
            int n = e & 63, k = e >> 6;
            Bs[k][n] = (n0 + n < Nc) ? B[(size_t)(k0 + k) * ldb + n0 + n] : 0.f;
        }
        __syncthreads();
#pragma unroll
        for (int k = 0; k < 16; k++) {
            float4 bv = *reinterpret_cast<const float4*>(&Bs[k][tx * 4]);
            float b4[4] = {bv.x, bv.y, bv.z, bv.w};
#pragma unroll
            for (int i = 0; i < 4; i++) {
                float av = As[k][ty * 4 + i];
#pragma unroll
                for (int j = 0; j < 4; j++) acc[i][j] += av * b4[j];
            }
        }
    }
#pragma unroll
    for (int i = 0; i < 4; i++) {
        int r = m0 + ty * 4 + i;
        if (r >= M) continue;
#pragma unroll
        for (int j = 0; j < 4; j++) {
            int c = n0 + tx * 4 + j;
            if (c >= Nc) continue;
            float v = acc[i][j];
            if (bias) v += bias[c];
            if (act == 1) v = v > 0.f ? v : (expf(v) - 1.f);
            C[(size_t)r * ldc + c] = v;
        }
    }
}

// ---------------- log_softmax + L1 scalar ----------------
__global__ void lsm_kernel(float* __restrict__ out, int out_size) {
    int n = blockIdx.x * blockDim.x + threadIdx.x;
    if (n >= NN) return;
    float v[NCLSD];
    float mx = -1e30f;
#pragma unroll
    for (int c = 0; c < NCLSD; c++) { v[c] = g_logits[n * NCLSD + c]; mx = fmaxf(mx, v[c]); }
    float s = 0.f;
#pragma unroll
    for (int c = 0; c < NCLSD; c++) s += expf(v[c] - mx);
    float l = logf(s) + mx;
#pragma unroll
    for (int c = 0; c < NCLSD; c++) {
        int idx = n * NCLSD + c;
        if (idx < out_size) out[idx] = v[c] - l;
    }
}

__global__ void l1_kernel(const float* __restrict__ wfus1, const float* __restrict__ wfus2,
                          float* __restrict__ out, int out_size) {
    __shared__ float red[256];
    int tid = threadIdx.x;
    float s1 = 0.f, s2 = 0.f;
    for (int i = tid; i < FUSD * AA * FUSD; i += 256) s1 += fabsf(wfus1[i]);
    for (int i = tid; i < NCLSD * AA * NCLSD; i += 256) s2 += fabsf(wfus2[i]);
    red[tid] = s1 / (float)(FUSD * AA * FUSD) + s2 / (float)(NCLSD * AA * NCLSD);
    __syncthreads();
    for (int o = 128; o > 0; o >>= 1) {
        if (tid < o) red[tid] += red[tid + o];
        __syncthreads();
    }
    if (tid == 0 && out_size > NN * NCLSD) out[NN * NCLSD] = red[0];
}

// ---------------- host launcher ----------------
extern "C" void kernel_launch(void* const* d_in, const int* in_sizes, int n_in,
                              void* d_out, int out_size) {
    const float* x     = (const float*)d_in[0];
    const int*   adj   = (const int*)d_in[1];
    const float* W1    = (const float*)d_in[2];
    const float* a1    = (const float*)d_in[3];
    const float* W2    = (const float*)d_in[4];
    const float* a2    = (const float*)d_in[5];
    const float* wint1 = (const float*)d_in[6];
    const float* bint1 = (const float*)d_in[7];
    const float* wfus1 = (const float*)d_in[8];
    const float* bfus1 = (const float*)d_in[9];
    const float* wint2 = (const float*)d_in[10];
    const float* bint2 = (const float*)d_in[11];
    const float* wfus2 = (const float*)d_in[12];
    const float* bfus2 = (const float*)d_in[13];
    float* out = (float*)d_out;

    float *pWh1, *pgat1, *pWh2, *pgat2;
    float *pf1, *pea, *peb;
    float4* pmfac;
    float *ph1p, *pout1, *ph2p, *plogits;
    float *pwint1T, *pwfus1T, *pwint2T, *pwfus2T;
    unsigned* pbits;
    cudaGetSymbolAddress((void**)&pWh1, g_Wh1);
    cudaGetSymbolAddress((void**)&pgat1, g_gat1);
    cudaGetSymbolAddress((void**)&pWh2, g_Wh2);
    cudaGetSymbolAddress((void**)&pgat2, g_gat2);
    cudaGetSymbolAddress((void**)&pf1, g_f1);
    cudaGetSymbolAddress((void**)&pea, g_ea);
    cudaGetSymbolAddress((void**)&peb, g_eb);
    cudaGetSymbolAddress((void**)&pmfac, g_mfac4);
    cudaGetSymbolAddress((void**)&pbits, g_bits);
    cudaGetSymbolAddress((void**)&ph1p, g_h1p);
    cudaGetSymbolAddress((void**)&pout1, g_out1);
    cudaGetSymbolAddress((void**)&ph2p, g_h2p);
    cudaGetSymbolAddress((void**)&plogits, g_logits);
    cudaGetSymbolAddress((void**)&pwint1T, g_wint1T);
    cudaGetSymbolAddress((void**)&pwfus1T, g_wfus1T);
    cudaGetSymbolAddress((void**)&pwint2T, g_wint2T);
    cudaGetSymbolAddress((void**)&pwfus2T, g_wfus2T);

    int nblk64 = (NN + 63) / 64;     // 47

    // launch 0: stage 1 Wh1 = x @ W1 -> flattened [n][a*256+h*64+o]
    gemm_mma_kernel<O1D><<<dim3(nblk64, AA * HHD), 256>>>(
        x, W1, pWh1, nullptr, NN, NFEATD, NFEATD, O1D, LDW1,
        HHD, 0, 0, (long long)HHD * NFEATD * O1D, (long long)NFEATD * O1D,
        HO1D, O1D, 0);

    // launch 1: attention factors for stage 1
    fprep_kernel<<<(AA * HHD * NN + 255) / 256, 256>>>(pWh1, a1, O1D, LDW1);

    // launch 2: adjacency bitmask
    {
        long long warps = (long long)AA * NN * WPR;
        int blocks = (int)((warps * 32 + 255) / 256);
        bitmask_kernel<<<blocks, 256>>>(adj);
    }

    // launch 3: att1 (keep at this index for ncu capture)
    att_mma_kernel<O1D><<<dim3(nblk64, AA * HHD), 256>>>(
        pWh1, pf1, pea, peb, pmfac, pbits, pgat1);

    // launch 4: all weight transposes
    {
        int total = FUSD * HO1D + FUSD * AA * FUSD + NCLSD * HO2D + NCLSD * AA * NCLSD;
        transpose_all_kernel<<<(total + 255) / 256, 256>>>(wint1, wfus1, wint2, wfus2);
    }

    // interproj1: elu(gat1[:, a*256:(a+1)*256] @ wint1T + bint1) -> h1p[n][a*64+g]
    gemm_mma_kernel<FUSD><<<dim3(nblk64, AA), 256>>>(
        pgat1, pwint1T, ph1p, bint1, NN, HO1D, LDW1, FUSD, AA * FUSD,
        1, HO1D, 0, 0, 0, FUSD, 0, 1);

    // fusion1: out1 = h1p @ wfus1T + bfus1
    gemm_mma_kernel<FUSD><<<dim3(nblk64, 1), 256>>>(
        ph1p, pwfus1T, pout1, bfus1, NN, AA * FUSD, AA * FUSD, FUSD, FUSD,
        1, 0, 0, 0, 0, 0, 0, 0);

    // stage 2: Wh2 = out1 @ W2 -> flattened [n][a*128+h*32+o]
    gemm_mma_kernel<O2D><<<dim3(nblk64, AA * HHD), 256>>>(
        pout1, W2, pWh2, nullptr, NN, FUSD, FUSD, O2D, LDW2,
        HHD, 0, 0, (long long)HHD * FUSD * O2D, (long long)FUSD * O2D,
        HO2D, O2D, 0);

    fprep_kernel<<<(AA * HHD * NN + 255) / 256, 256>>>(pWh2, a2, O2D, LDW2);

    att_mma_kernel<O2D><<<dim3(nblk64, AA * HHD), 256>>>(
        pWh2, pf1, pea, peb, pmfac, pbits, pgat2);

    // interproj2: elu(gat2[:, a*128:(a+1)*128] @ wint2T + bint2) -> h2p[n][a*8+c]
    sgemm_kernel<<<dim3(nblk64, 1, AA), 256>>>(
        pgat2, pwint2T, ph2p, bint2, NN, HO2D, NCLSD, LDW2, NCLSD, AA * NCLSD,
        1, HO2D, 0, 0, 0, NCLSD, 0, 1);

    // fusion2: logits = h2p @ wfus2T + bfus2
    sgemm_kernel<<<dim3(nblk64, 1, 1), 256>>>(
        ph2p, pwfus2T, plogits, bfus2, NN, AA * NCLSD, NCLSD,
        AA * NCLSD, NCLSD, NCLSD,
        1, 0, 0, 0, 0, 0, 0, 0);

    lsm_kernel<<<(NN + 255) / 256, 256>>>(out, out_size);
    l1_kernel<<<1, 256>>>(wfus1, wfus2, out, out_size);
}

// round 10
// speedup vs baseline: 3.2721x; 1.1666x over previous
#include <cuda_runtime.h>
#include <math.h>
#include <stdint.h>

#define NN 3000
#define NFEATD 512
#define AA 2
#define HHD 4
#define O1D 64
#define O2D 32
#define HO1D 256
#define HO2D 128
#define LDW1 512          // flattened Wh1/gat1 row width = AA*HHD*O1D
#define LDW2 256          // flattened Wh2/gat2 row width
#define FUSD 64
#define NCLSD 8
#define WPR 94
#define NT64 47           // ceil(3000/64) 64-m tiles
#define MPPAD 1504        // NT64*32 padded mp rows
#define ALPHAF 0.2f

// ---------------- scratch ----------------
__device__ float g_Wh1[NN*LDW1];        // [n][a*256+h*64+o]
__device__ float g_gat1[NN*LDW1];
__device__ float g_Wh2[NN*LDW2];        // [n][a*128+h*32+o]
__device__ float g_gat2[NN*LDW2];
__device__ uint32_t g_WhB[8*MPPAD*O1D]; // bf16x2-packed Wh pairs [z][mp][o]
__device__ float g_f1[AA*HHD*NN], g_ea[AA*HHD*NN], g_eb[AA*HHD*NN];
__device__ float4 g_mfac4[AA*HHD*NN];   // (f2, exp(f2), exp(a*f2), 0)
__device__ unsigned g_bits[AA*WPR*NN];  // [a][mt32][n]
__device__ float g_h1p[NN*AA*FUSD];
__device__ float g_out1[NN*FUSD];
__device__ float g_h2p[NN*AA*NCLSD];
__device__ float g_logits[NN*NCLSD];
__device__ float g_wint1T[HO1D*FUSD];
__device__ float g_wfus1T[AA*FUSD*FUSD];
__device__ float g_wint2T[HO2D*NCLSD];
__device__ float g_wfus2T[AA*NCLSD*NCLSD];

// ---------------- mma / async helpers ----------------
__device__ __forceinline__ void mma_tf32(float* c, uint32_t a0, uint32_t a1,
                                         uint32_t a2, uint32_t a3,
                                         uint32_t b0, uint32_t b1) {
    asm volatile(
        "mma.sync.aligned.m16n8k8.row.col.f32.tf32.tf32.f32 "
        "{%0,%1,%2,%3}, {%4,%5,%6,%7}, {%8,%9}, {%0,%1,%2,%3};\n"
        : "+f"(c[0]), "+f"(c[1]), "+f"(c[2]), "+f"(c[3])
        : "r"(a0), "r"(a1), "r"(a2), "r"(a3), "r"(b0), "r"(b1));
}
__device__ __forceinline__ void mma_bf16(float* c, uint32_t a0, uint32_t a1,
                                         uint32_t a2, uint32_t a3,
                                         uint32_t b0, uint32_t b1) {
    asm volatile(
        "mma.sync.aligned.m16n8k16.row.col.f32.bf16.bf16.f32 "
        "{%0,%1,%2,%3}, {%4,%5,%6,%7}, {%8,%9}, {%0,%1,%2,%3};\n"
        : "+f"(c[0]), "+f"(c[1]), "+f"(c[2]), "+f"(c[3])
        : "r"(a0), "r"(a1), "r"(a2), "r"(a3), "r"(b0), "r"(b1));
}
__device__ __forceinline__ float cvt_tf32(float v) {
    uint32_t r;
    asm("cvt.rna.tf32.f32 %0, %1;" : "=r"(r) : "f"(v));
    return __uint_as_float(r);
}
__device__ __forceinline__ uint32_t pack_bf16x2(float hi, float lo) {
    uint32_t r;
    asm("cvt.rn.bf16x2.f32 %0, %1, %2;" : "=r"(r) : "f"(hi), "f"(lo));
    return r;
}
__device__ __forceinline__ void cp_async16(uint32_t dst_smem, const void* src) {
    asm volatile("cp.async.cg.shared.global [%0], [%1], 16;" :: "r"(dst_smem), "l"(src));
}
__device__ __forceinline__ void cp_async_commit() {
    asm volatile("cp.async.commit_group;");
}
__device__ __forceinline__ void cp_async_wait0() {
    asm volatile("cp.async.wait_group 0;");
}

// ---------------- merged weight transposes ----------------
__global__ void transpose_all_kernel(const float* __restrict__ wint1,
                                     const float* __restrict__ wfus1,
                                     const float* __restrict__ wint2,
                                     const float* __restrict__ wfus2) {
    const int S1 = FUSD * HO1D;
    const int S2 = FUSD * AA * FUSD;
    const int S3 = NCLSD * HO2D;
    const int S4 = NCLSD * AA * NCLSD;
    int t = blockIdx.x * blockDim.x + threadIdx.x;
    if (t < S1) {
        int r = t / HO1D, c = t % HO1D;
        g_wint1T[c * FUSD + r] = wint1[t];
    } else if (t < S1 + S2) {
        int e = t - S1;
        int r = e / (AA * FUSD), c = e % (AA * FUSD);
        g_wfus1T[c * FUSD + r] = wfus1[e];
    } else if (t < S1 + S2 + S3) {
        int e = t - S1 - S2;
        int r = e / HO2D, c = e % HO2D;
        g_wint2T[c * NCLSD + r] = wint2[e];
    } else if (t < S1 + S2 + S3 + S4) {
        int e = t - S1 - S2 - S3;
        int r = e / (AA * NCLSD), c = e % (AA * NCLSD);
        g_wfus2T[c * NCLSD + r] = wfus2[e];
    }
}

// ---------------- adjacency -> bitmask via ballot ----------------
__global__ void bitmask_kernel(const int* __restrict__ adj) {
    int gw = (blockIdx.x * blockDim.x + threadIdx.x) >> 5;
    int lane = threadIdx.x & 31;
    if (gw >= AA * NN * WPR) return;
    int a = gw / (NN * WPR);
    int rem = gw % (NN * WPR);
    int n = rem / WPR;
    int mt = rem % WPR;
    int m = mt * 32 + lane;
    int v = 0;
    if (m < NN) v = adj[(size_t)(a * NN + n) * NN + m] > 0;
    unsigned word = __ballot_sync(0xffffffffu, v);
    if (lane == 0) g_bits[(size_t)(a * WPR + mt) * NN + n] = word;
}

// ---------------- attention factor precompute (flattened Wh) ----------------
__global__ void fprep_kernel(const float* __restrict__ Wh, const float* __restrict__ avec,
                             int O, int ldw) {
    int t = blockIdx.x * blockDim.x + threadIdx.x;
    if (t >= AA * HHD * NN) return;
    int ah = t / NN, n = t % NN;
    int a = ah / HHD, h = ah % HHD;
    const float* wr = Wh + (size_t)n * ldw + (a * HHD + h) * O;
    const float* av = avec + ah * 2 * O;
    float f1 = 0.f, f2 = 0.f;
    for (int o = 0; o < O; o++) {
        float w = wr[o];
        f1 += w * av[o];
        f2 += w * av[O + o];
    }
    g_f1[t] = f1;
    g_ea[t] = expf(f1);
    g_eb[t] = expf(ALPHAF * f1);
    g_mfac4[t] = make_float4(f2, expf(f2), expf(ALPHAF * f2), 0.f);
}

// ---------------- repack Wh -> bf16x2 consecutive-m pairs [z][mp][o] ----------------
template <int O>
__global__ void repack_kernel(const float* __restrict__ Wh) {
    constexpr int LDW = AA * HHD * O;
    int z = blockIdx.y;
    int a = z >> 2, h = z & 3;
    int q = blockIdx.x * blockDim.x + threadIdx.x;
    if (q >= MPPAD * O / 4) return;
    int mp = q / (O / 4);
    int o4 = (q % (O / 4)) * 4;
    int m0 = 2 * mp, m1 = 2 * mp + 1;
    const float* base = Wh + (a * HHD + h) * O + o4;
    float4 v0 = (m0 < NN) ? *(const float4*)(base + (size_t)m0 * LDW) : make_float4(0.f, 0.f, 0.f, 0.f);
    float4 v1 = (m1 < NN) ? *(const float4*)(base + (size_t)m1 * LDW) : make_float4(0.f, 0.f, 0.f, 0.f);
    uint4 p;
    p.x = pack_bf16x2(v1.x, v0.x);
    p.y = pack_bf16x2(v1.y, v0.y);
    p.z = pack_bf16x2(v1.z, v0.z);
    p.w = pack_bf16x2(v1.w, v0.w);
    *(uint4*)&g_WhB[(size_t)z * MPPAD * O + mp * O + o4] = p;
}

// ---------------- generic tf32 MMA GEMM (batched, bias, elu) ----------------
template <int O>
__global__ void gemm_mma_kernel(const float* __restrict__ A, const float* __restrict__ B,
                                float* __restrict__ C, const float* __restrict__ bias,
                                int M, int K, int lda, int ldb, int ldc,
                                int Hz, long long sAa, long long sAh,
                                long long sBa, long long sBh,
                                long long sCa, int cOffH, int act) {
    constexpr int BS = O + 8;
    constexpr int NT = O / 16;
    int z = blockIdx.y;
    int za = z / Hz, zh = z - za * Hz;
    A += za * sAa + zh * sAh;
    B += za * sBa + zh * sBh;
    C += za * sCa + (long long)zh * cOffH;

    __shared__ float As[64][36];
    __shared__ float Bs[32][BS];

    int tid = threadIdx.x, w = tid >> 5, lane = tid & 31;
    int rg = w >> 1, cg = w & 1;
    int g = lane >> 2, t4 = lane & 3;
    int m0 = blockIdx.x * 64;

    float acc[NT][4];
#pragma unroll
    for (int i = 0; i < NT; i++)
#pragma unroll
        for (int j = 0; j < 4; j++) acc[i][j] = 0.f;

    for (int k0 = 0; k0 < K; k0 += 32) {
#pragma unroll
        for (int i = 0; i < 8; i++) {
            int e = tid + i * 256;
            int r = e >> 5, k = e & 31;
            int m = m0 + r;
            float v = (m < M) ? A[(size_t)m * lda + k0 + k] : 0.f;
            As[r][k] = cvt_tf32(v);
        }
#pragma unroll
        for (int i = 0; i < (32 * O) / 256; i++) {
            int e = tid + i * 256;
            int k, c;
            if (O == 64) { k = e >> 6; c = e & 63; } else { k = e >> 5; c = e & 31; }
            Bs[k][c] = cvt_tf32(B[(size_t)(k0 + k) * ldb + c]);
        }
        __syncthreads();
#pragma unroll
        for (int kk = 0; kk < 4; kk++) {
            int kb = kk * 8;
            int ar = rg * 16 + g;
            uint32_t a0 = __float_as_uint(As[ar][kb + t4]);
            uint32_t a1 = __float_as_uint(As[ar + 8][kb + t4]);
            uint32_t a2 = __float_as_uint(As[ar][kb + t4 + 4]);
            uint32_t a3 = __float_as_uint(As[ar + 8][kb + t4 + 4]);
#pragma unroll
            for (int nt = 0; nt < NT; nt++) {
                int col = cg * (O / 2) + nt * 8 + g;
                uint32_t b0 = __float_as_uint(Bs[kb + t4][col]);
                uint32_t b1 = __float_as_uint(Bs[kb + t4 + 4][col]);
                mma_tf32(acc[nt], a0, a1, a2, a3, b0, b1);
            }
        }
        __syncthreads();
    }
#pragma unroll
    for (int half = 0; half < 2; half++) {
        int r = rg * 16 + g + half * 8;
        int gr = m0 + r;
        if (gr < M) {
#pragma unroll
            for (int nt = 0; nt < NT; nt++) {
                int col = cg * (O / 2) + nt * 8 + 2 * t4;
                float v0 = acc[nt][half * 2 + 0];
                float v1 = acc[nt][half * 2 + 1];
                if (bias) { v0 += bias[col]; v1 += bias[col + 1]; }
                if (act == 1) {
                    v0 = v0 > 0.f ? v0 : (expf(v0) - 1.f);
                    v1 = v1 > 0.f ? v1 : (expf(v1) - 1.f);
                }
                *(float2*)&C[(size_t)gr * ldc + col] = make_float2(v0, v1);
            }
        }
    }
}

// ---------------- attention weight (raw fp32; rounded at pack) ----------------
__device__ __forceinline__ float attw_f(unsigned word, int mb, float f1n, float ean,
                                        float ebn, const float4 q) {
    float wv = 0.f;
    if ((word >> mb) & 1u) {
        float s = f1n + q.x;
        wv = (s > 0.f) ? ean * q.y : ebn * q.z;
    }
    return wv;
}

// ---------------- fused masked-softmax attention aggregate (bf16 MMA + cp.async) --------
// 64-row tiles; 8 warps = 4 rowgroups x 2 k-groups. 64-m stages; Wh tiles arrive
// pre-packed bf16x2 via cp.async (overlapped with compute of previous tile).
// out[n,:] = elu( (sum_m w(n,m)*Wh[m,:]) / (sum_m w(n,m)) )
template <int O>
__global__ void att_mma_kernel(const uint32_t* __restrict__ WhB,
                               const float* __restrict__ f1v, const float* __restrict__ eav,
                               const float* __restrict__ ebv,
                               const float4* __restrict__ mfac,
                               const unsigned* __restrict__ bits,
                               float* __restrict__ outp) {
    constexpr int LDW = AA * HHD * O;
    constexpr int NT = O / 8;                    // n8 tiles per warp (full O)
    constexpr int BSTRIDE = (O == 64) ? 72 : 40; // uint32 row stride; %32 == 8
    constexpr int CPR = O / 4;                   // 16B chunks per mp-row
    int z = blockIdx.y;
    int a = z >> 2, h = z & 3;
    int n0 = blockIdx.x * 64;
    const uint32_t* wbb = WhB + (size_t)z * MPPAD * O;
    const float4* mfb = mfac + (size_t)z * NN;
    const unsigned* bb = bits + (size_t)a * WPR * NN;

    __shared__ uint32_t Whs[2][32 * BSTRIDE];    // bf16x2 pairs: 32 mp rows = 64 m
    __shared__ float4 mfs[2][64];
    __shared__ unsigned wds[2][2][64];           // [buf][sub32][n]
    __shared__ float mrg[4 * NT * 128];          // kg-merge buffer
    __shared__ float Zbuf[64];

    int tid = threadIdx.x, w = tid >> 5, lane = tid & 31;
    int rg = w >> 1, kg = w & 1;
    int g = lane >> 2, t4 = lane & 3;
    int r0 = rg * 16 + g, r1 = r0 + 8;
    int gr0 = n0 + r0, gr1 = n0 + r1;

    uint32_t whs0 = (uint32_t)__cvta_generic_to_shared(&Whs[0][0]);

    float f10 = 0.f, ea0 = 0.f, eb0 = 0.f, f11 = 0.f, ea1 = 0.f, eb1 = 0.f;
    if (gr0 < NN) { f10 = f1v[(size_t)z*NN+gr0]; ea0 = eav[(size_t)z*NN+gr0]; eb0 = ebv[(size_t)z*NN+gr0]; }
    if (gr1 < NN) { f11 = f1v[(size_t)z*NN+gr1]; ea1 = eav[(size_t)z*NN+gr1]; eb1 = ebv[(size_t)z*NN+gr1]; }

    float acc[NT][4];
#pragma unroll
    for (int i = 0; i < NT; i++)
#pragma unroll
        for (int j = 0; j < 4; j++) acc[i][j] = 0.f;
    float zp0 = 0.f, zp1 = 0.f;

    auto build = [&](int mt, int buf) {
        // Wh tile: 32 mp rows x O uint32, via cp.async 16B chunks
#pragma unroll
        for (int i = 0; i < (32 * CPR) / 256; i++) {
            int c = tid + i * 256;
            int row = c / CPR;
            int col = (c % CPR) * 4;
            uint32_t dst = whs0 + (uint32_t)(buf * 32 * BSTRIDE + row * BSTRIDE + col) * 4u;
            cp_async16(dst, wbb + (size_t)(mt * 32 + row) * O + col);
        }
        if (tid < 64) {
            int m = mt * 64 + tid;
            mfs[buf][tid] = (m < NN) ? mfb[m] : make_float4(0.f, 0.f, 0.f, 0.f);
        } else if (tid < 192) {
            int j = (tid - 64) >> 6, n = (tid - 64) & 63;
            int rr = n0 + n;
            int wi = mt * 2 + j;
            wds[buf][j][n] = (rr < NN && wi < WPR) ? bb[(size_t)wi * NN + rr] : 0u;
        }
    };

    build(0, 0);
    cp_async_commit();
    cp_async_wait0();
    __syncthreads();

    int kb = kg * 16;
    for (int mt = 0; mt < NT64; mt++) {
        int cur = mt & 1;
        if (mt + 1 < NT64) { build(mt + 1, cur ^ 1); cp_async_commit(); }
#pragma unroll
        for (int sub = 0; sub < 2; sub++) {
            unsigned w0 = wds[cur][sub][r0], w1 = wds[cur][sub][r1];
            int base = sub * 32 + kb;
            float4 qa = mfs[cur][base + 2 * t4];
            float4 qb = mfs[cur][base + 2 * t4 + 1];
            float4 qc = mfs[cur][base + 2 * t4 + 8];
            float4 qd = mfs[cur][base + 2 * t4 + 9];
            float w0a = attw_f(w0, kb + 2 * t4,     f10, ea0, eb0, qa);
            float w0b = attw_f(w0, kb + 2 * t4 + 1, f10, ea0, eb0, qb);
            float w0c = attw_f(w0, kb + 2 * t4 + 8, f10, ea0, eb0, qc);
            float w0d = attw_f(w0, kb + 2 * t4 + 9, f10, ea0, eb0, qd);
            float w1a = attw_f(w1, kb + 2 * t4,     f11, ea1, eb1, qa);
            float w1b = attw_f(w1, kb + 2 * t4 + 1, f11, ea1, eb1, qb);
            float w1c = attw_f(w1, kb + 2 * t4 + 8, f11, ea1, eb1, qc);
            float w1d = attw_f(w1, kb + 2 * t4 + 9, f11, ea1, eb1, qd);
            zp0 += (w0a + w0b) + (w0c + w0d);
            zp1 += (w1a + w1b) + (w1c + w1d);
            uint32_t a0 = pack_bf16x2(w0b, w0a);
            uint32_t a1 = pack_bf16x2(w1b, w1a);
            uint32_t a2 = pack_bf16x2(w0d, w0c);
            uint32_t a3 = pack_bf16x2(w1d, w1c);
            int row0 = sub * 16 + kg * 8 + t4, row1 = row0 + 4;
#pragma unroll
            for (int nt = 0; nt < NT; nt++) {
                int col = nt * 8 + g;
                uint32_t b0 = Whs[cur][row0 * BSTRIDE + col];
                uint32_t b1 = Whs[cur][row1 * BSTRIDE + col];
                mma_bf16(acc[nt], a0, a1, a2, a3, b0, b1);
            }
        }
        cp_async_wait0();
        __syncthreads();
    }

    // Z reduce over quad (t4 bits) via butterfly
#pragma unroll
    for (int d = 1; d < 4; d <<= 1) {
        zp0 += __shfl_xor_sync(0xffffffffu, zp0, d);
        zp1 += __shfl_xor_sync(0xffffffffu, zp1, d);
    }

    // merge k-group pairs: kg=1 writes, kg=0 adds
    int flat = rg * 32 + lane;
    if (kg == 1) {
#pragma unroll
        for (int nt = 0; nt < NT; nt++)
#pragma unroll
            for (int j = 0; j < 4; j++)
                mrg[(nt * 4 + j) * 128 + flat] = acc[nt][j];
        if (t4 == 0) { Zbuf[r0] = zp0; Zbuf[r1] = zp1; }
    }
    __syncthreads();
    if (kg == 0) {
#pragma unroll
        for (int nt = 0; nt < NT; nt++)
#pragma unroll
            for (int j = 0; j < 4; j++)
                acc[nt][j] += mrg[(nt * 4 + j) * 128 + flat];
        zp0 += Zbuf[r0];
        zp1 += Zbuf[r1];
        float inv0 = (zp0 > 0.f) ? 1.f / zp0 : 0.f;
        float inv1 = (zp1 > 0.f) ? 1.f / zp1 : 0.f;
        // epilogue: normalize + elu + store
#pragma unroll
        for (int nt = 0; nt < NT; nt++) {
            int col = nt * 8 + 2 * t4;
            if (gr0 < NN) {
                float v0 = acc[nt][0] * inv0;
                float v1 = acc[nt][1] * inv0;
                v0 = v0 > 0.f ? v0 : (expf(v0) - 1.f);
                v1 = v1 > 0.f ? v1 : (expf(v1) - 1.f);
                *(float2*)&outp[(size_t)gr0 * LDW + (a * HHD + h) * O + col] = make_float2(v0, v1);
            }
            if (gr1 < NN) {
                float v2 = acc[nt][2] * inv1;
                float v3 = acc[nt][3] * inv1;
                v2 = v2 > 0.f ? v2 : (expf(v2) - 1.f);
                v3 = v3 > 0.f ? v3 : (expf(v3) - 1.f);
                *(float2*)&outp[(size_t)gr1 * LDW + (a * HHD + h) * O + col] = make_float2(v2, v3);
            }
        }
    }
}

// ---------------- SIMT SGEMM for tiny tail layers ----------------
__global__ void sgemm_kernel(const float* __restrict__ A, const float* __restrict__ B,
                             float* __restrict__ C, const float* __restrict__ bias,
                             int M, int K, int Nc, int lda, int ldb, int ldc,
                             int Hz, long long sAa, long long sAh,
                             long long sBa, long long sBh,
                             long long sCa, long long sCh, int act) {
    int z = blockIdx.z;
    int za = z / Hz, zh = z % Hz;
    A += za * sAa + zh * sAh;
    B += za * sBa + zh * sBh;
    C += za * sCa + zh * sCh;
    __shared__ float As[16][65];
    __shared__ __align__(16) float Bs[16][64];
    int tid = threadIdx.x;
    int tx = tid & 15, ty = tid >> 4;
    int m0 = blockIdx.x * 64, n0 = blockIdx.y * 64;
    float acc[4][4] = {};
    for (int k0 = 0; k0 < K; k0 += 16) {
        __syncthreads();
#pragma unroll
        for (int i = 0; i < 4; i++) {
            int e = tid + i * 256;
            int k = e & 15, m = e >> 4;
            As[k][m] = (m0 + m < M) ? A[(size_t)(m0 + m) * lda + k0 + k] : 0.f;
        }
#pragma unroll
        for (int i = 0; i < 4; i++) {
            int e = tid + i * 256;
            int n = e & 63, k = e >> 6;
            Bs[k][n] = (n0 + n < Nc) ? B[(size_t)(k0 + k) * ldb + n0 + n] : 0.f;
        }
        __syncthreads();
#pragma unroll
        for (int k = 0; k < 16; k++) {
            float4 bv = *reinterpret_cast<const float4*>(&Bs[k][tx * 4]);
            float b4[4] = {bv.x, bv.y, bv.z, bv.w};
#pragma unroll
            for (int i = 0; i < 4; i++) {
                float av = As[k][ty * 4 + i];
#pragma unroll
                for (int j = 0; j < 4; j++) acc[i][j] += av * b4[j];
            }
        }
    }
#pragma unroll
    for (int i = 0; i < 4; i++) {
        int r = m0 + ty * 4 + i;
        if (r >= M) continue;
#pragma unroll
        for (int j = 0; j < 4; j++) {
            int c = n0 + tx * 4 + j;
            if (c >= Nc) continue;
            float v = acc[i][j];
            if (bias) v += bias[c];
            if (act == 1) v = v > 0.f ? v : (expf(v) - 1.f);
            C[(size_t)r * ldc + c] = v;
        }
    }
}

// ---------------- log_softmax + L1 scalar ----------------
__global__ void lsm_kernel(float* __restrict__ out, int out_size) {
    int n = blockIdx.x * blockDim.x + threadIdx.x;
    if (n >= NN) return;
    float v[NCLSD];
    float mx = -1e30f;
#pragma unroll
    for (int c = 0; c < NCLSD; c++) { v[c] = g_logits[n * NCLSD + c]; mx = fmaxf(mx, v[c]); }
    float s = 0.f;
#pragma unroll
    for (int c = 0; c < NCLSD; c++) s += expf(v[c] - mx);
    float l = logf(s) + mx;
#pragma unroll
    for (int c = 0; c < NCLSD; c++) {
        int idx = n * NCLSD + c;
        if (idx < out_size) out[idx] = v[c] - l;
    }
}

__global__ void l1_kernel(const float* __restrict__ wfus1, const float* __restrict__ wfus2,
                          float* __restrict__ out, int out_size) {
    __shared__ float red[256];
    int tid = threadIdx.x;
    float s1 = 0.f, s2 = 0.f;
    for (int i = tid; i < FUSD * AA * FUSD; i += 256) s1 += fabsf(wfus1[i]);
    for (int i = tid; i < NCLSD * AA * NCLSD; i += 256) s2 += fabsf(wfus2[i]);
    red[tid] = s1 / (float)(FUSD * AA * FUSD) + s2 / (float)(NCLSD * AA * NCLSD);
    __syncthreads();
    for (int o = 128; o > 0; o >>= 1) {
        if (tid < o) red[tid] += red[tid + o];
        __syncthreads();
    }
    if (tid == 0 && out_size > NN * NCLSD) out[NN * NCLSD] = red[0];
}

// ---------------- host launcher ----------------
extern "C" void kernel_launch(void* const* d_in, const int* in_sizes, int n_in,
                              void* d_out, int out_size) {
    const float* x     = (const float*)d_in[0];
    const int*   adj   = (const int*)d_in[1];
    const float* W1    = (const float*)d_in[2];
    const float* a1    = (const float*)d_in[3];
    const float* W2    = (const float*)d_in[4];
    const float* a2    = (const float*)d_in[5];
    const float* wint1 = (const float*)d_in[6];
    const float* bint1 = (const float*)d_in[7];
    const float* wfus1 = (const float*)d_in[8];
    const float* bfus1 = (const float*)d_in[9];
    const float* wint2 = (const float*)d_in[10];
    const float* bint2 = (const float*)d_in[11];
    const float* wfus2 = (const float*)d_in[12];
    const float* bfus2 = (const float*)d_in[13];
    float* out = (float*)d_out;

    float *pWh1, *pgat1, *pWh2, *pgat2;
    float *pf1, *pea, *peb;
    float4* pmfac;
    uint32_t* pWhB;
    float *ph1p, *pout1, *ph2p, *plogits;
    float *pwint1T, *pwfus1T, *pwint2T, *pwfus2T;
    unsigned* pbits;
    cudaGetSymbolAddress((void**)&pWh1, g_Wh1);
    cudaGetSymbolAddress((void**)&pgat1, g_gat1);
    cudaGetSymbolAddress((void**)&pWh2, g_Wh2);
    cudaGetSymbolAddress((void**)&pgat2, g_gat2);
    cudaGetSymbolAddress((void**)&pf1, g_f1);
    cudaGetSymbolAddress((void**)&pea, g_ea);
    cudaGetSymbolAddress((void**)&peb, g_eb);
    cudaGetSymbolAddress((void**)&pmfac, g_mfac4);
    cudaGetSymbolAddress((void**)&pWhB, g_WhB);
    cudaGetSymbolAddress((void**)&pbits, g_bits);
    cudaGetSymbolAddress((void**)&ph1p, g_h1p);
    cudaGetSymbolAddress((void**)&pout1, g_out1);
    cudaGetSymbolAddress((void**)&ph2p, g_h2p);
    cudaGetSymbolAddress((void**)&plogits, g_logits);
    cudaGetSymbolAddress((void**)&pwint1T, g_wint1T);
    cudaGetSymbolAddress((void**)&pwfus1T, g_wfus1T);
    cudaGetSymbolAddress((void**)&pwint2T, g_wint2T);
    cudaGetSymbolAddress((void**)&pwfus2T, g_wfus2T);

    int nblk64 = (NN + 63) / 64;     // 47

    // adjacency bitmask (independent of everything else)
    {
        long long warps = (long long)AA * NN * WPR;
        int blocks = (int)((warps * 32 + 255) / 256);
        bitmask_kernel<<<blocks, 256>>>(adj);
    }

    // stage 1 Wh1 = x @ W1 -> flattened [n][a*256+h*64+o]
    gemm_mma_kernel<O1D><<<dim3(nblk64, AA * HHD), 256>>>(
        x, W1, pWh1, nullptr, NN, NFEATD, NFEATD, O1D, LDW1,
        HHD, 0, 0, (long long)HHD * NFEATD * O1D, (long long)NFEATD * O1D,
        HO1D, O1D, 0);

    // attention factors + bf16 repack for stage 1
    fprep_kernel<<<(AA * HHD * NN + 255) / 256, 256>>>(pWh1, a1, O1D, LDW1);
    repack_kernel<O1D><<<dim3((MPPAD * O1D / 4 + 255) / 256, AA * HHD), 256>>>(pWh1);

    // att1
    att_mma_kernel<O1D><<<dim3(nblk64, AA * HHD), 256>>>(
        pWhB, pf1, pea, peb, pmfac, pbits, pgat1);

    // all weight transposes
    {
        int total = FUSD * HO1D + FUSD * AA * FUSD + NCLSD * HO2D + NCLSD * AA * NCLSD;
        transpose_all_kernel<<<(total + 255) / 256, 256>>>(wint1, wfus1, wint2, wfus2);
    }

    // interproj1: elu(gat1[:, a*256:(a+1)*256] @ wint1T + bint1) -> h1p[n][a*64+g]
    gemm_mma_kernel<FUSD><<<dim3(nblk64, AA), 256>>>(
        pgat1, pwint1T, ph1p, bint1, NN, HO1D, LDW1, FUSD, AA * FUSD,
        1, HO1D, 0, 0, 0, FUSD, 0, 1);

    // fusion1: out1 = h1p @ wfus1T + bfus1
    gemm_mma_kernel<FUSD><<<dim3(nblk64, 1), 256>>>(
        ph1p, pwfus1T, pout1, bfus1, NN, AA * FUSD, AA * FUSD, FUSD, FUSD,
        1, 0, 0, 0, 0, 0, 0, 0);

    // stage 2: Wh2 = out1 @ W2 -> flattened [n][a*128+h*32+o]
    gemm_mma_kernel<O2D><<<dim3(nblk64, AA * HHD), 256>>>(
        pout1, W2, pWh2, nullptr, NN, FUSD, FUSD, O2D, LDW2,
        HHD, 0, 0, (long long)HHD * FUSD * O2D, (long long)FUSD * O2D,
        HO2D, O2D, 0);

    fprep_kernel<<<(AA * HHD * NN + 255) / 256, 256>>>(pWh2, a2, O2D, LDW2);
    repack_kernel<O2D><<<dim3((MPPAD * O2D / 4 + 255) / 256, AA * HHD), 256>>>(pWh2);

    att_mma_kernel<O2D><<<dim3(nblk64, AA * HHD), 256>>>(
        pWhB, pf1, pea, peb, pmfac, pbits, pgat2);

    // interproj2: elu(gat2[:, a*128:(a+1)*128] @ wint2T + bint2) -> h2p[n][a*8+c]
    sgemm_kernel<<<dim3(nblk64, 1, AA), 256>>>(
        pgat2, pwint2T, ph2p, bint2, NN, HO2D, NCLSD, LDW2, NCLSD, AA * NCLSD,
        1, HO2D, 0, 0, 0, NCLSD, 0, 1);

    // fusion2: logits = h2p @ wfus2T + bfus2
    sgemm_kernel<<<dim3(nblk64, 1, 1), 256>>>(
        ph2p, pwfus2T, plogits, bfus2, NN, AA * NCLSD, NCLSD,
        AA * NCLSD, NCLSD, NCLSD,
        1, 0, 0, 0, 0, 0, 0, 0);

    lsm_kernel<<<(NN + 255) / 256, 256>>>(out, out_size);
    l1_kernel<<<1, 256>>>(wfus1, wfus2, out, out_size);
}

// round 11
// speedup vs baseline: 3.2917x; 1.0060x over previous
#include <cuda_runtime.h>
#include <math.h>
#include <stdint.h>

#define NN 3000
#define NFEATD 512
#define AA 2
#define HHD 4
#define O1D 64
#define O2D 32
#define HO1D 256
#define HO2D 128
#define LDW1 512          // flattened gat1 row width = AA*HHD*O1D
#define LDW2 256          // flattened gat2 row width
#define FUSD 64
#define NCLSD 8
#define WPR 94
#define NT64 47           // ceil(3000/64) 64-m tiles
#define MPPAD 1504        // NT64*32 padded mp rows
#define ALPHAF 0.2f

// ---------------- scratch ----------------
__device__ float g_gat1[NN*LDW1];
__device__ float g_gat2[NN*LDW2];
__device__ uint32_t g_WhB[8*MPPAD*O1D]; // bf16x2-packed Wh pairs [z][mp][o]
__device__ float g_f1[AA*HHD*NN], g_ea[AA*HHD*NN], g_eb[AA*HHD*NN];
__device__ float4 g_mfac4[AA*HHD*NN];   // (f2, exp(f2), exp(a*f2), 0)
__device__ unsigned g_bits[AA*WPR*NN];  // [a][mt32][n]
__device__ float g_h1p[NN*AA*FUSD];
__device__ float g_out1[NN*FUSD];
__device__ float g_h2p[NN*AA*NCLSD];
__device__ float g_logits[NN*NCLSD];
__device__ float g_wint1T[HO1D*FUSD];
__device__ float g_wfus1T[AA*FUSD*FUSD];
__device__ float g_wint2T[HO2D*NCLSD];
__device__ float g_wfus2T[AA*NCLSD*NCLSD];

// ---------------- mma / async helpers ----------------
__device__ __forceinline__ void mma_tf32(float* c, uint32_t a0, uint32_t a1,
                                         uint32_t a2, uint32_t a3,
                                         uint32_t b0, uint32_t b1) {
    asm volatile(
        "mma.sync.aligned.m16n8k8.row.col.f32.tf32.tf32.f32 "
        "{%0,%1,%2,%3}, {%4,%5,%6,%7}, {%8,%9}, {%0,%1,%2,%3};\n"
        : "+f"(c[0]), "+f"(c[1]), "+f"(c[2]), "+f"(c[3])
        : "r"(a0), "r"(a1), "r"(a2), "r"(a3), "r"(b0), "r"(b1));
}
__device__ __forceinline__ void mma_bf16(float* c, uint32_t a0, uint32_t a1,
                                         uint32_t a2, uint32_t a3,
                                         uint32_t b0, uint32_t b1) {
    asm volatile(
        "mma.sync.aligned.m16n8k16.row.col.f32.bf16.bf16.f32 "
        "{%0,%1,%2,%3}, {%4,%5,%6,%7}, {%8,%9}, {%0,%1,%2,%3};\n"
        : "+f"(c[0]), "+f"(c[1]), "+f"(c[2]), "+f"(c[3])
        : "r"(a0), "r"(a1), "r"(a2), "r"(a3), "r"(b0), "r"(b1));
}
__device__ __forceinline__ float cvt_tf32(float v) {
    uint32_t r;
    asm("cvt.rna.tf32.f32 %0, %1;" : "=r"(r) : "f"(v));
    return __uint_as_float(r);
}
__device__ __forceinline__ uint32_t pack_bf16x2(float hi, float lo) {
    uint32_t r;
    asm("cvt.rn.bf16x2.f32 %0, %1, %2;" : "=r"(r) : "f"(hi), "f"(lo));
    return r;
}
__device__ __forceinline__ void cp_async16(uint32_t dst_smem, const void* src) {
    asm volatile("cp.async.cg.shared.global [%0], [%1], 16;" :: "r"(dst_smem), "l"(src));
}
__device__ __forceinline__ void cp_async_commit() {
    asm volatile("cp.async.commit_group;");
}
__device__ __forceinline__ void cp_async_wait0() {
    asm volatile("cp.async.wait_group 0;");
}

// ---------------- merged weight transposes ----------------
__global__ void transpose_all_kernel(const float* __restrict__ wint1,
                                     const float* __restrict__ wfus1,
                                     const float* __restrict__ wint2,
                                     const float* __restrict__ wfus2) {
    const int S1 = FUSD * HO1D;
    const int S2 = FUSD * AA * FUSD;
    const int S3 = NCLSD * HO2D;
    const int S4 = NCLSD * AA * NCLSD;
    int t = blockIdx.x * blockDim.x + threadIdx.x;
    if (t < S1) {
        int r = t / HO1D, c = t % HO1D;
        g_wint1T[c * FUSD + r] = wint1[t];
    } else if (t < S1 + S2) {
        int e = t - S1;
        int r = e / (AA * FUSD), c = e % (AA * FUSD);
        g_wfus1T[c * FUSD + r] = wfus1[e];
    } else if (t < S1 + S2 + S3) {
        int e = t - S1 - S2;
        int r = e / HO2D, c = e % HO2D;
        g_wint2T[c * NCLSD + r] = wint2[e];
    } else if (t < S1 + S2 + S3 + S4) {
        int e = t - S1 - S2 - S3;
        int r = e / (AA * NCLSD), c = e % (AA * NCLSD);
        g_wfus2T[c * NCLSD + r] = wfus2[e];
    }
}

// ---------------- adjacency -> bitmask via ballot ----------------
__global__ void bitmask_kernel(const int* __restrict__ adj) {
    int gw = (blockIdx.x * blockDim.x + threadIdx.x) >> 5;
    int lane = threadIdx.x & 31;
    if (gw >= AA * NN * WPR) return;
    int a = gw / (NN * WPR);
    int rem = gw % (NN * WPR);
    int n = rem / WPR;
    int mt = rem % WPR;
    int m = mt * 32 + lane;
    int v = 0;
    if (m < NN) v = adj[(size_t)(a * NN + n) * NN + m] > 0;
    unsigned word = __ballot_sync(0xffffffffu, v);
    if (lane == 0) g_bits[(size_t)(a * WPR + mt) * NN + n] = word;
}

// ---------------- Wh-stage GEMM with fused fprep + bf16 repack epilogue ----------------
// Computes Wh-tile (64 rows x O cols) for one (a,h)=z, then:
//   - f1/f2 = dot(Wh_row, avec) via quad-shfl + smem atomics -> g_f1/g_ea/g_eb/g_mfac
//   - bf16x2 row-pair pack -> g_WhB (no fp32 Wh ever hits GMEM)
template <int O>
__global__ void gemm_whprep_kernel(const float* __restrict__ A, const float* __restrict__ B,
                                   const float* __restrict__ avec,
                                   uint32_t* __restrict__ WhB,
                                   float* __restrict__ f1o, float* __restrict__ eao,
                                   float* __restrict__ ebo, float4* __restrict__ mfac,
                                   int M, int K, int lda, int ldb,
                                   long long sBh) {
    constexpr int BS = O + 8;
    constexpr int NT = O / 16;
    int z = blockIdx.y;                 // = a*HHD + h
    B += (long long)z * sBh;
    const float* av = avec + (size_t)z * 2 * O;

    __shared__ float As[64][36];
    __shared__ float Bs[32][BS];
    __shared__ float f1s[64], f2s[64];

    int tid = threadIdx.x, w = tid >> 5, lane = tid & 31;
    int rg = w >> 1, cg = w & 1;
    int g = lane >> 2, t4 = lane & 3;
    int m0 = blockIdx.x * 64;

    if (tid < 64) { f1s[tid] = 0.f; f2s[tid] = 0.f; }

    float acc[NT][4];
#pragma unroll
    for (int i = 0; i < NT; i++)
#pragma unroll
        for (int j = 0; j < 4; j++) acc[i][j] = 0.f;

    for (int k0 = 0; k0 < K; k0 += 32) {
        __syncthreads();
#pragma unroll
        for (int i = 0; i < 8; i++) {
            int e = tid + i * 256;
            int r = e >> 5, k = e & 31;
            int m = m0 + r;
            float v = (m < M) ? A[(size_t)m * lda + k0 + k] : 0.f;
            As[r][k] = cvt_tf32(v);
        }
#pragma unroll
        for (int i = 0; i < (32 * O) / 256; i++) {
            int e = tid + i * 256;
            int k, c;
            if (O == 64) { k = e >> 6; c = e & 63; } else { k = e >> 5; c = e & 31; }
            Bs[k][c] = cvt_tf32(B[(size_t)(k0 + k) * ldb + c]);
        }
        __syncthreads();
#pragma unroll
        for (int kk = 0; kk < 4; kk++) {
            int kb = kk * 8;
            int ar = rg * 16 + g;
            uint32_t a0 = __float_as_uint(As[ar][kb + t4]);
            uint32_t a1 = __float_as_uint(As[ar + 8][kb + t4]);
            uint32_t a2 = __float_as_uint(As[ar][kb + t4 + 4]);
            uint32_t a3 = __float_as_uint(As[ar + 8][kb + t4 + 4]);
#pragma unroll
            for (int nt = 0; nt < NT; nt++) {
                int col = cg * (O / 2) + nt * 8 + g;
                uint32_t b0 = __float_as_uint(Bs[kb + t4][col]);
                uint32_t b1 = __float_as_uint(Bs[kb + t4 + 4][col]);
                mma_tf32(acc[nt], a0, a1, a2, a3, b0, b1);
            }
        }
        __syncthreads();
    }

    // ---- fused epilogue ----
#pragma unroll
    for (int half = 0; half < 2; half++) {
        int r = rg * 16 + g + half * 8;
        int gr = m0 + r;
        float p1 = 0.f, p2 = 0.f;
#pragma unroll
        for (int nt = 0; nt < NT; nt++) {
            int col = cg * (O / 2) + nt * 8 + 2 * t4;
            float v0 = acc[nt][half * 2 + 0];
            float v1 = acc[nt][half * 2 + 1];
            p1 += v0 * av[col] + v1 * av[col + 1];
            p2 += v0 * av[O + col] + v1 * av[O + col + 1];
            // bf16 pack: pair rows (even g, odd g) via shfl_xor(4)
            float u0 = __shfl_xor_sync(0xffffffffu, v0, 4);
            float u1 = __shfl_xor_sync(0xffffffffu, v1, 4);
            if ((g & 1) == 0) {
                uint2 p;
                p.x = pack_bf16x2(u0, v0);
                p.y = pack_bf16x2(u1, v1);
                *(uint2*)&WhB[(size_t)z * MPPAD * O + (size_t)(gr >> 1) * O + col] = p;
            }
        }
        // quad reduce over t4
        p1 += __shfl_xor_sync(0xffffffffu, p1, 1);
        p1 += __shfl_xor_sync(0xffffffffu, p1, 2);
        p2 += __shfl_xor_sync(0xffffffffu, p2, 1);
        p2 += __shfl_xor_sync(0xffffffffu, p2, 2);
        if (t4 == 0) {
            atomicAdd(&f1s[r], p1);
            atomicAdd(&f2s[r], p2);
        }
    }
    __syncthreads();
    if (tid < 64) {
        int gr = m0 + tid;
        if (gr < NN) {
            float f1 = f1s[tid], f2 = f2s[tid];
            size_t idx = (size_t)z * NN + gr;
            f1o[idx] = f1;
            eao[idx] = expf(f1);
            ebo[idx] = expf(ALPHAF * f1);
            mfac[idx] = make_float4(f2, expf(f2), expf(ALPHAF * f2), 0.f);
        }
    }
}

// ---------------- generic tf32 MMA GEMM (batched, bias, elu) ----------------
template <int O>
__global__ void gemm_mma_kernel(const float* __restrict__ A, const float* __restrict__ B,
                                float* __restrict__ C, const float* __restrict__ bias,
                                int M, int K, int lda, int ldb, int ldc,
                                int Hz, long long sAa, long long sAh,
                                long long sBa, long long sBh,
                                long long sCa, int cOffH, int act) {
    constexpr int BS = O + 8;
    constexpr int NT = O / 16;
    int z = blockIdx.y;
    int za = z / Hz, zh = z - za * Hz;
    A += za * sAa + zh * sAh;
    B += za * sBa + zh * sBh;
    C += za * sCa + (long long)zh * cOffH;

    __shared__ float As[64][36];
    __shared__ float Bs[32][BS];

    int tid = threadIdx.x, w = tid >> 5, lane = tid & 31;
    int rg = w >> 1, cg = w & 1;
    int g = lane >> 2, t4 = lane & 3;
    int m0 = blockIdx.x * 64;

    float acc[NT][4];
#pragma unroll
    for (int i = 0; i < NT; i++)
#pragma unroll
        for (int j = 0; j < 4; j++) acc[i][j] = 0.f;

    for (int k0 = 0; k0 < K; k0 += 32) {
#pragma unroll
        for (int i = 0; i < 8; i++) {
            int e = tid + i * 256;
            int r = e >> 5, k = e & 31;
            int m = m0 + r;
            float v = (m < M) ? A[(size_t)m * lda + k0 + k] : 0.f;
            As[r][k] = cvt_tf32(v);
        }
#pragma unroll
        for (int i = 0; i < (32 * O) / 256; i++) {
            int e = tid + i * 256;
            int k, c;
            if (O == 64) { k = e >> 6; c = e & 63; } else { k = e >> 5; c = e & 31; }
            Bs[k][c] = cvt_tf32(B[(size_t)(k0 + k) * ldb + c]);
        }
        __syncthreads();
#pragma unroll
        for (int kk = 0; kk < 4; kk++) {
            int kb = kk * 8;
            int ar = rg * 16 + g;
            uint32_t a0 = __float_as_uint(As[ar][kb + t4]);
            uint32_t a1 = __float_as_uint(As[ar + 8][kb + t4]);
            uint32_t a2 = __float_as_uint(As[ar][kb + t4 + 4]);
            uint32_t a3 = __float_as_uint(As[ar + 8][kb + t4 + 4]);
#pragma unroll
            for (int nt = 0; nt < NT; nt++) {
                int col = cg * (O / 2) + nt * 8 + g;
                uint32_t b0 = __float_as_uint(Bs[kb + t4][col]);
                uint32_t b1 = __float_as_uint(Bs[kb + t4 + 4][col]);
                mma_tf32(acc[nt], a0, a1, a2, a3, b0, b1);
            }
        }
        __syncthreads();
    }
#pragma unroll
    for (int half = 0; half < 2; half++) {
        int r = rg * 16 + g + half * 8;
        int gr = m0 + r;
        if (gr < M) {
#pragma unroll
            for (int nt = 0; nt < NT; nt++) {
                int col = cg * (O / 2) + nt * 8 + 2 * t4;
                float v0 = acc[nt][half * 2 + 0];
                float v1 = acc[nt][half * 2 + 1];
                if (bias) { v0 += bias[col]; v1 += bias[col + 1]; }
                if (act == 1) {
                    v0 = v0 > 0.f ? v0 : (expf(v0) - 1.f);
                    v1 = v1 > 0.f ? v1 : (expf(v1) - 1.f);
                }
                *(float2*)&C[(size_t)gr * ldc + col] = make_float2(v0, v1);
            }
        }
    }
}

// ---------------- attention weight (raw fp32; rounded at pack) ----------------
__device__ __forceinline__ float attw_f(unsigned word, int mb, float f1n, float ean,
                                        float ebn, const float4 q) {
    float wv = 0.f;
    if ((word >> mb) & 1u) {
        float s = f1n + q.x;
        wv = (s > 0.f) ? ean * q.y : ebn * q.z;
    }
    return wv;
}

// ---------------- fused masked-softmax attention aggregate (bf16 MMA + cp.async) --------
template <int O>
__global__ void att_mma_kernel(const uint32_t* __restrict__ WhB,
                               const float* __restrict__ f1v, const float* __restrict__ eav,
                               const float* __restrict__ ebv,
                               const float4* __restrict__ mfac,
                               const unsigned* __restrict__ bits,
                               float* __restrict__ outp) {
    constexpr int LDW = AA * HHD * O;
    constexpr int NT = O / 8;                    // n8 tiles per warp (full O)
    constexpr int BSTRIDE = (O == 64) ? 72 : 40; // uint32 row stride; %32 == 8
    constexpr int CPR = O / 4;                   // 16B chunks per mp-row
    int z = blockIdx.y;
    int a = z >> 2, h = z & 3;
    int n0 = blockIdx.x * 64;
    const uint32_t* wbb = WhB + (size_t)z * MPPAD * O;
    const float4* mfb = mfac + (size_t)z * NN;
    const unsigned* bb = bits + (size_t)a * WPR * NN;

    __shared__ uint32_t Whs[2][32 * BSTRIDE];    // bf16x2 pairs: 32 mp rows = 64 m
    __shared__ float4 mfs[2][64];
    __shared__ unsigned wds[2][2][64];           // [buf][sub32][n]
    __shared__ float mrg[4 * NT * 128];          // kg-merge buffer
    __shared__ float Zbuf[64];

    int tid = threadIdx.x, w = tid >> 5, lane = tid & 31;
    int rg = w >> 1, kg = w & 1;
    int g = lane >> 2, t4 = lane & 3;
    int r0 = rg * 16 + g, r1 = r0 + 8;
    int gr0 = n0 + r0, gr1 = n0 + r1;

    uint32_t whs0 = (uint32_t)__cvta_generic_to_shared(&Whs[0][0]);

    float f10 = 0.f, ea0 = 0.f, eb0 = 0.f, f11 = 0.f, ea1 = 0.f, eb1 = 0.f;
    if (gr0 < NN) { f10 = f1v[(size_t)z*NN+gr0]; ea0 = eav[(size_t)z*NN+gr0]; eb0 = ebv[(size_t)z*NN+gr0]; }
    if (gr1 < NN) { f11 = f1v[(size_t)z*NN+gr1]; ea1 = eav[(size_t)z*NN+gr1]; eb1 = ebv[(size_t)z*NN+gr1]; }

    float acc[NT][4];
#pragma unroll
    for (int i = 0; i < NT; i++)
#pragma unroll
        for (int j = 0; j < 4; j++) acc[i][j] = 0.f;
    float zp0 = 0.f, zp1 = 0.f;

    auto build = [&](int mt, int buf) {
#pragma unroll
        for (int i = 0; i < (32 * CPR) / 256; i++) {
            int c = tid + i * 256;
            int row = c / CPR;
            int col = (c % CPR) * 4;
            uint32_t dst = whs0 + (uint32_t)(buf * 32 * BSTRIDE + row * BSTRIDE + col) * 4u;
            cp_async16(dst, wbb + (size_t)(mt * 32 + row) * O + col);
        }
        if (tid < 64) {
            int m = mt * 64 + tid;
            mfs[buf][tid] = (m < NN) ? mfb[m] : make_float4(0.f, 0.f, 0.f, 0.f);
        } else if (tid < 192) {
            int j = (tid - 64) >> 6, n = (tid - 64) & 63;
            int rr = n0 + n;
            int wi = mt * 2 + j;
            wds[buf][j][n] = (rr < NN && wi < WPR) ? bb[(size_t)wi * NN + rr] : 0u;
        }
    };

    build(0, 0);
    cp_async_commit();
    cp_async_wait0();
    __syncthreads();

    int kb = kg * 16;
    for (int mt = 0; mt < NT64; mt++) {
        int cur = mt & 1;
        if (mt + 1 < NT64) { build(mt + 1, cur ^ 1); cp_async_commit(); }
#pragma unroll
        for (int sub = 0; sub < 2; sub++) {
            unsigned w0 = wds[cur][sub][r0], w1 = wds[cur][sub][r1];
            int base = sub * 32 + kb;
            float4 qa = mfs[cur][base + 2 * t4];
            float4 qb = mfs[cur][base + 2 * t4 + 1];
            float4 qc = mfs[cur][base + 2 * t4 + 8];
            float4 qd = mfs[cur][base + 2 * t4 + 9];
            float w0a = attw_f(w0, kb + 2 * t4,     f10, ea0, eb0, qa);
            float w0b = attw_f(w0, kb + 2 * t4 + 1, f10, ea0, eb0, qb);
            float w0c = attw_f(w0, kb + 2 * t4 + 8, f10, ea0, eb0, qc);
            float w0d = attw_f(w0, kb + 2 * t4 + 9, f10, ea0, eb0, qd);
            float w1a = attw_f(w1, kb + 2 * t4,     f11, ea1, eb1, qa);
            float w1b = attw_f(w1, kb + 2 * t4 + 1, f11, ea1, eb1, qb);
            float w1c = attw_f(w1, kb + 2 * t4 + 8, f11, ea1, eb1, qc);
            float w1d = attw_f(w1, kb + 2 * t4 + 9, f11, ea1, eb1, qd);
            zp0 += (w0a + w0b) + (w0c + w0d);
            zp1 += (w1a + w1b) + (w1c + w1d);
            uint32_t a0 = pack_bf16x2(w0b, w0a);
            uint32_t a1 = pack_bf16x2(w1b, w1a);
            uint32_t a2 = pack_bf16x2(w0d, w0c);
            uint32_t a3 = pack_bf16x2(w1d, w1c);
            int row0 = sub * 16 + kg * 8 + t4, row1 = row0 + 4;
#pragma unroll
            for (int nt = 0; nt < NT; nt++) {
                int col = nt * 8 + g;
                uint32_t b0 = Whs[cur][row0 * BSTRIDE + col];
                uint32_t b1 = Whs[cur][row1 * BSTRIDE + col];
                mma_bf16(acc[nt], a0, a1, a2, a3, b0, b1);
            }
        }
        cp_async_wait0();
        __syncthreads();
    }

#pragma unroll
    for (int d = 1; d < 4; d <<= 1) {
        zp0 += __shfl_xor_sync(0xffffffffu, zp0, d);
        zp1 += __shfl_xor_sync(0xffffffffu, zp1, d);
    }

    int flat = rg * 32 + lane;
    if (kg == 1) {
#pragma unroll
        for (int nt = 0; nt < NT; nt++)
#pragma unroll
            for (int j = 0; j < 4; j++)
                mrg[(nt * 4 + j) * 128 + flat] = acc[nt][j];
        if (t4 == 0) { Zbuf[r0] = zp0; Zbuf[r1] = zp1; }
    }
    __syncthreads();
    if (kg == 0) {
#pragma unroll
        for (int nt = 0; nt < NT; nt++)
#pragma unroll
            for (int j = 0; j < 4; j++)
                acc[nt][j] += mrg[(nt * 4 + j) * 128 + flat];
        zp0 += Zbuf[r0];
        zp1 += Zbuf[r1];
        float inv0 = (zp0 > 0.f) ? 1.f / zp0 : 0.f;
        float inv1 = (zp1 > 0.f) ? 1.f / zp1 : 0.f;
#pragma unroll
        for (int nt = 0; nt < NT; nt++) {
            int col = nt * 8 + 2 * t4;
            if (gr0 < NN) {
                float v0 = acc[nt][0] * inv0;
                float v1 = acc[nt][1] * inv0;
                v0 = v0 > 0.f ? v0 : (expf(v0) - 1.f);
                v1 = v1 > 0.f ? v1 : (expf(v1) - 1.f);
                *(float2*)&outp[(size_t)gr0 * LDW + (a * HHD + h) * O + col] = make_float2(v0, v1);
            }
            if (gr1 < NN) {
                float v2 = acc[nt][2] * inv1;
                float v3 = acc[nt][3] * inv1;
                v2 = v2 > 0.f ? v2 : (expf(v2) - 1.f);
                v3 = v3 > 0.f ? v3 : (expf(v3) - 1.f);
                *(float2*)&outp[(size_t)gr1 * LDW + (a * HHD + h) * O + col] = make_float2(v2, v3);
            }
        }
    }
}

// ---------------- SIMT SGEMM for tiny tail layers ----------------
__global__ void sgemm_kernel(const float* __restrict__ A, const float* __restrict__ B,
                             float* __restrict__ C, const float* __restrict__ bias,
                             int M, int K, int Nc, int lda, int ldb, int ldc,
                             int Hz, long long sAa, long long sAh,
                             long long sBa, long long sBh,
                             long long sCa, long long sCh, int act) {
    int z = blockIdx.z;
    int za = z / Hz, zh = z % Hz;
    A += za * sAa + zh * sAh;
    B += za * sBa + zh * sBh;
    C += za * sCa + zh * sCh;
    __shared__ float As[16][65];
    __shared__ __align__(16) float Bs[16][64];
    int tid = threadIdx.x;
    int tx = tid & 15, ty = tid >> 4;
    int m0 = blockIdx.x * 64, n0 = blockIdx.y * 64;
    float acc[4][4] = {};
    for (int k0 = 0; k0 < K; k0 += 16) {
        __syncthreads();
#pragma unroll
        for (int i = 0; i < 4; i++) {
            int e = tid + i * 256;
            int k = e & 15, m = e >> 4;
            As[k][m] = (m0 + m < M) ? A[(size_t)(m0 + m) * lda + k0 + k] : 0.f;
        }
#pragma unroll
        for (int i = 0; i < 4; i++) {
            int e = tid + i * 256;
            int n = e & 63, k = e >> 6;
            Bs[k][n] = (n0 + n < Nc) ? B[(size_t)(k0 + k) * ldb + n0 + n] : 0.f;
        }
        __syncthreads();
#pragma unroll
        for (int k = 0; k < 16; k++) {
            float4 bv = *reinterpret_cast<const float4*>(&Bs[k][tx * 4]);
            float b4[4] = {bv.x, bv.y, bv.z, bv.w};
#pragma unroll
            for (int i = 0; i < 4; i++) {
                float av = As[k][ty * 4 + i];
#pragma unroll
                for (int j = 0; j < 4; j++) acc[i][j] += av * b4[j];
            }
        }
    }
#pragma unroll
    for (int i = 0; i < 4; i++) {
        int r = m0 + ty * 4 + i;
        if (r >= M) continue;
#pragma unroll
        for (int j = 0; j < 4; j++) {
            int c = n0 + tx * 4 + j;
            if (c >= Nc) continue;
            float v = acc[i][j];
            if (bias) v += bias[c];
            if (act == 1) v = v > 0.f ? v : (expf(v) - 1.f);
            C[(size_t)r * ldc + c] = v;
        }
    }
}

// ---------------- log_softmax + L1 scalar ----------------
__global__ void lsm_kernel(float* __restrict__ out, int out_size) {
    int n = blockIdx.x * blockDim.x + threadIdx.x;
    if (n >= NN) return;
    float v[NCLSD];
    float mx = -1e30f;
#pragma unroll
    for (int c = 0; c < NCLSD; c++) { v[c] = g_logits[n * NCLSD + c]; mx = fmaxf(mx, v[c]); }
    float s = 0.f;
#pragma unroll
    for (int c = 0; c < NCLSD; c++) s += expf(v[c] - mx);
    float l = logf(s) + mx;
#pragma unroll
    for (int c = 0; c < NCLSD; c++) {
        int idx = n * NCLSD + c;
        if (idx < out_size) out[idx] = v[c] - l;
    }
}

__global__ void l1_kernel(const float* __restrict__ wfus1, const float* __restrict__ wfus2,
                          float* __restrict__ out, int out_size) {
    __shared__ float red[256];
    int tid = threadIdx.x;
    float s1 = 0.f, s2 = 0.f;
    for (int i = tid; i < FUSD * AA * FUSD; i += 256) s1 += fabsf(wfus1[i]);
    for (int i = tid; i < NCLSD * AA * NCLSD; i += 256) s2 += fabsf(wfus2[i]);
    red[tid] = s1 / (float)(FUSD * AA * FUSD) + s2 / (float)(NCLSD * AA * NCLSD);
    __syncthreads();
    for (int o = 128; o > 0; o >>= 1) {
        if (tid < o) red[tid] += red[tid + o];
        __syncthreads();
    }
    if (tid == 0 && out_size > NN * NCLSD) out[NN * NCLSD] = red[0];
}

// ---------------- host launcher ----------------
extern "C" void kernel_launch(void* const* d_in, const int* in_sizes, int n_in,
                              void* d_out, int out_size) {
    const float* x     = (const float*)d_in[0];
    const int*   adj   = (const int*)d_in[1];
    const float* W1    = (const float*)d_in[2];
    const float* a1    = (const float*)d_in[3];
    const float* W2    = (const float*)d_in[4];
    const float* a2    = (const float*)d_in[5];
    const float* wint1 = (const float*)d_in[6];
    const float* bint1 = (const float*)d_in[7];
    const float* wfus1 = (const float*)d_in[8];
    const float* bfus1 = (const float*)d_in[9];
    const float* wint2 = (const float*)d_in[10];
    const float* bint2 = (const float*)d_in[11];
    const float* wfus2 = (const float*)d_in[12];
    const float* bfus2 = (const float*)d_in[13];
    float* out = (float*)d_out;

    float *pgat1, *pgat2;
    float *pf1, *pea, *peb;
    float4* pmfac;
    uint32_t* pWhB;
    float *ph1p, *pout1, *ph2p, *plogits;
    float *pwint1T, *pwfus1T, *pwint2T, *pwfus2T;
    unsigned* pbits;
    cudaGetSymbolAddress((void**)&pgat1, g_gat1);
    cudaGetSymbolAddress((void**)&pgat2, g_gat2);
    cudaGetSymbolAddress((void**)&pf1, g_f1);
    cudaGetSymbolAddress((void**)&pea, g_ea);
    cudaGetSymbolAddress((void**)&peb, g_eb);
    cudaGetSymbolAddress((void**)&pmfac, g_mfac4);
    cudaGetSymbolAddress((void**)&pWhB, g_WhB);
    cudaGetSymbolAddress((void**)&pbits, g_bits);
    cudaGetSymbolAddress((void**)&ph1p, g_h1p);
    cudaGetSymbolAddress((void**)&pout1, g_out1);
    cudaGetSymbolAddress((void**)&ph2p, g_h2p);
    cudaGetSymbolAddress((void**)&plogits, g_logits);
    cudaGetSymbolAddress((void**)&pwint1T, g_wint1T);
    cudaGetSymbolAddress((void**)&pwfus1T, g_wfus1T);
    cudaGetSymbolAddress((void**)&pwint2T, g_wint2T);
    cudaGetSymbolAddress((void**)&pwfus2T, g_wfus2T);

    int nblk64 = (NN + 63) / 64;     // 47

    // adjacency bitmask (independent of everything else)
    {
        long long warps = (long long)AA * NN * WPR;
        int blocks = (int)((warps * 32 + 255) / 256);
        bitmask_kernel<<<blocks, 256>>>(adj);
    }

    // stage 1: Wh1 GEMM with fused fprep + bf16 repack (no fp32 Wh written)
    gemm_whprep_kernel<O1D><<<dim3(nblk64, AA * HHD), 256>>>(
        x, W1, a1, pWhB, pf1, pea, peb, pmfac,
        NN, NFEATD, NFEATD, O1D, (long long)NFEATD * O1D);

    // att1
    att_mma_kernel<O1D><<<dim3(nblk64, AA * HHD), 256>>>(
        pWhB, pf1, pea, peb, pmfac, pbits, pgat1);

    // all weight transposes
    {
        int total = FUSD * HO1D + FUSD * AA * FUSD + NCLSD * HO2D + NCLSD * AA * NCLSD;
        transpose_all_kernel<<<(total + 255) / 256, 256>>>(wint1, wfus1, wint2, wfus2);
    }

    // interproj1: elu(gat1[:, a*256:(a+1)*256] @ wint1T + bint1) -> h1p[n][a*64+g]
    gemm_mma_kernel<FUSD><<<dim3(nblk64, AA), 256>>>(
        pgat1, pwint1T, ph1p, bint1, NN, HO1D, LDW1, FUSD, AA * FUSD,
        1, HO1D, 0, 0, 0, FUSD, 0, 1);

    // fusion1: out1 = h1p @ wfus1T + bfus1
    gemm_mma_kernel<FUSD><<<dim3(nblk64, 1), 256>>>(
        ph1p, pwfus1T, pout1, bfus1, NN, AA * FUSD, AA * FUSD, FUSD, FUSD,
        1, 0, 0, 0, 0, 0, 0, 0);

    // stage 2: Wh2 GEMM with fused fprep + repack
    gemm_whprep_kernel<O2D><<<dim3(nblk64, AA * HHD), 256>>>(
        pout1, W2, a2, pWhB, pf1, pea, peb, pmfac,
        NN, FUSD, FUSD, O2D, (long long)FUSD * O2D);

    att_mma_kernel<O2D><<<dim3(nblk64, AA * HHD), 256>>>(
        pWhB, pf1, pea, peb, pmfac, pbits, pgat2);

    // interproj2: elu(gat2[:, a*128:(a+1)*128] @ wint2T + bint2) -> h2p[n][a*8+c]
    sgemm_kernel<<<dim3(nblk64, 1, AA), 256>>>(
        pgat2, pwint2T, ph2p, bint2, NN, HO2D, NCLSD, LDW2, NCLSD, AA * NCLSD,
        1, HO2D, 0, 0, 0, NCLSD, 0, 1);

    // fusion2: logits = h2p @ wfus2T + bfus2
    sgemm_kernel<<<dim3(nblk64, 1, 1), 256>>>(
        ph2p, pwfus2T, plogits, bfus2, NN, AA * NCLSD, NCLSD,
        AA * NCLSD, NCLSD, NCLSD,
        1, 0, 0, 0, 0, 0, 0, 0);

    lsm_kernel<<<(NN + 255) / 256, 256>>>(out, out_size);
    l1_kernel<<<1, 256>>>(wfus1, wfus2, out, out_size);
}